// round 11
// baseline (speedup 1.0000x reference)
#include <cuda_runtime.h>
#include <cuda_fp16.h>
#include <math.h>
#include <stdint.h>

// Problem dims
#define V_ 32000
#define E_ 1024
#define H_ 16
#define F_ 4096
#define L_ 4
#define T_ 2048
#define B_ 2
#define D_ 64
#define M_ (B_*T_)   // 4096

// ---------------------------------------------------------------------------
// Scratch (device globals; allocation APIs are forbidden)
// ---------------------------------------------------------------------------
__device__ float g_h  [M_*E_];
__device__ __half g_qkv[M_*3*E_];
__device__ float g_bqkv[L_*3*E_];
__device__ __half g_xn [M_*E_];
__device__ __half g_o  [M_*E_];
__device__ __half g_mlp[M_*F_];
__device__ __half g_qkvT[L_*3*E_*E_];
__device__ __half g_woT [L_*E_*E_];
__device__ __half g_w1T [L_*F_*E_];
__device__ __half g_w2T [L_*E_*F_];
__device__ __half g_woutT[(size_t)V_*E_];

// ---------------------------------------------------------------------------
// PTX helpers
// ---------------------------------------------------------------------------
__device__ __forceinline__ uint32_t smem_u32(const void* p) {
    uint32_t a;
    asm("{ .reg .u64 t; cvta.to.shared.u64 t, %1; cvt.u32.u64 %0, t; }" : "=r"(a) : "l"(p));
    return a;
}
static __device__ __forceinline__ void cpa16(uint32_t s, const void* g) {
    asm volatile("cp.async.cg.shared.global [%0], [%1], 16;" :: "r"(s), "l"(g) : "memory");
}
#define CP_COMMIT() asm volatile("cp.async.commit_group;" ::: "memory")
#define CP_WAIT0()  asm volatile("cp.async.wait_group 0;" ::: "memory")
#define CP_WAIT1()  asm volatile("cp.async.wait_group 1;" ::: "memory")

struct Frag4 { uint32_t x, y, z, w; };

static __device__ __forceinline__ Frag4 ldsm_x4(uint32_t addr) {
    Frag4 r;
    asm volatile("ldmatrix.sync.aligned.m8n8.x4.shared.b16 {%0,%1,%2,%3}, [%4];"
                 : "=r"(r.x), "=r"(r.y), "=r"(r.z), "=r"(r.w) : "r"(addr));
    return r;
}
static __device__ __forceinline__ Frag4 ldsm_x4_t(uint32_t addr) {
    Frag4 r;
    asm volatile("ldmatrix.sync.aligned.m8n8.x4.trans.shared.b16 {%0,%1,%2,%3}, [%4];"
                 : "=r"(r.x), "=r"(r.y), "=r"(r.z), "=r"(r.w) : "r"(addr));
    return r;
}

static __device__ __forceinline__ void mma_f16(float* c, const Frag4& a,
                                               uint32_t b0, uint32_t b1) {
    asm volatile(
        "mma.sync.aligned.m16n8k16.row.col.f32.f16.f16.f32 "
        "{%0,%1,%2,%3}, {%4,%5,%6,%7}, {%8,%9}, {%0,%1,%2,%3};"
        : "+f"(c[0]), "+f"(c[1]), "+f"(c[2]), "+f"(c[3])
        : "r"(a.x), "r"(a.y), "r"(a.z), "r"(a.w), "r"(b0), "r"(b1));
}
static __device__ __forceinline__ void mma4(float* c, uint32_t a0, uint32_t a1,
                                            uint32_t a2, uint32_t a3,
                                            uint32_t b0, uint32_t b1) {
    asm volatile(
        "mma.sync.aligned.m16n8k16.row.col.f32.f16.f16.f32 "
        "{%0,%1,%2,%3}, {%4,%5,%6,%7}, {%8,%9}, {%0,%1,%2,%3};"
        : "+f"(c[0]), "+f"(c[1]), "+f"(c[2]), "+f"(c[3])
        : "r"(a0), "r"(a1), "r"(a2), "r"(a3), "r"(b0), "r"(b1));
}

static __device__ __forceinline__ float ex2f(float x) {
    float y;
    asm("ex2.approx.ftz.f32 %0, %1;" : "=f"(y) : "f"(x));
    return y;
}

__device__ __forceinline__ float gelu_exact(float x) {
    return 0.5f * x * (1.0f + erff(x * 0.70710678118654752f));
}

// ===========================================================================
// XL GEMM (Wout, MLP1): CTA 256x256, 512 threads (16 warps, 4x4),
// warptile 64x64, BK=32, 3-stage cp.async.
// SMEM intensity 8 MAC/B + 4 warps/SMSP -> both BW and latency covered.
// EPI: 0 = fp32 +bias ; 1 = gelu->fp16
// ===========================================================================
#define XROWB    80
#define XT_A     (256 * XROWB)              // 20480
#define XT_STG   (2 * XT_A)                 // 40960
#define XT_SMEM  (3 * XT_STG)               // 122880

static __device__ __forceinline__ void xt_load(
    uint32_t st, const __half* __restrict__ A, const __half* __restrict__ Bm,
    int bm, int bn, int k0, int K, int tid)
{
#pragma unroll
    for (int i = 0; i < 2; i++) {            // A: 256 rows x 4 chunks = 1024
        int c = tid + (i << 9);
        int r = c >> 2, q = c & 3;
        cpa16(st + (uint32_t)(r * XROWB + q * 16),
              A + (size_t)(bm + r) * K + k0 + (q << 3));
    }
#pragma unroll
    for (int i = 0; i < 2; i++) {            // B: 256 rows x 4 chunks = 1024
        int c = tid + (i << 9);
        int r = c >> 2, q = c & 3;
        cpa16(st + XT_A + (uint32_t)(r * XROWB + q * 16),
              Bm + (size_t)(bn + r) * K + k0 + (q << 3));
    }
}

template<int EPI>
__global__ __launch_bounds__(512, 1) void xtgemm_kernel(
    const __half* __restrict__ A, const __half* __restrict__ Bm,
    const float* __restrict__ bias,
    float* __restrict__ Cf, __half* __restrict__ Ch,
    int N, int K)
{
    extern __shared__ __align__(1024) unsigned char smem[];
    uint32_t sb = smem_u32(smem);
    int tid = threadIdx.x, wid = tid >> 5, lane = tid & 31;
    int bm = blockIdx.x * 256, bn = blockIdx.y * 256;
    int wm = wid & 3, wn = wid >> 2;         // 4 x 4 warps, warptile 64x64

    uint32_t a_lane = (uint32_t)((wm * 64 + (lane & 15)) * XROWB + ((lane >> 4) << 4));
    uint32_t b_lane = (uint32_t)(XT_A + (wn * 64 + (lane & 7) + ((lane >> 4) << 3)) * XROWB
                                 + (((lane >> 3) & 1) << 4));

    float acc[4][8][4];
#pragma unroll
    for (int i = 0; i < 4; i++)
#pragma unroll
        for (int j = 0; j < 8; j++)
#pragma unroll
            for (int e = 0; e < 4; e++) acc[i][j][e] = 0.f;

    int nk = K >> 5;
    xt_load(sb,          A, Bm, bm, bn, 0,  K, tid); CP_COMMIT();
    xt_load(sb + XT_STG, A, Bm, bm, bn, 32, K, tid); CP_COMMIT();

    uint32_t stg[3] = {sb, sb + XT_STG, sb + 2 * XT_STG};
    int cur = 0, nxt = 2;
    for (int kt = 0; kt < nk; kt++) {
        CP_WAIT1();
        __syncthreads();

        int kf = kt + 2;
        if (kf < nk)
            xt_load(stg[nxt], A, Bm, bm, bn, kf << 5, K, tid);
        CP_COMMIT();

        uint32_t st = stg[cur];
        cur = (cur + 1) % 3; nxt = (nxt + 1) % 3;
#pragma unroll
        for (int ks = 0; ks < 2; ks++) {
            uint32_t kb = ks << 5;
            Frag4 ah[4];
#pragma unroll
            for (int mt = 0; mt < 4; mt++)
                ah[mt] = ldsm_x4(st + a_lane + mt * (16 * XROWB) + kb);
#pragma unroll
            for (int np = 0; np < 4; np++) {
                Frag4 bf = ldsm_x4(st + b_lane + np * (16 * XROWB) + kb);
#pragma unroll
                for (int mt = 0; mt < 4; mt++) {
                    mma_f16(acc[mt][np * 2],     ah[mt], bf.x, bf.y);
                    mma_f16(acc[mt][np * 2 + 1], ah[mt], bf.z, bf.w);
                }
            }
        }
    }
    __syncthreads();

    int row_in = lane >> 2;
    int col2   = (lane & 3) << 1;
#pragma unroll
    for (int mt = 0; mt < 4; mt++) {
#pragma unroll
        for (int nt = 0; nt < 8; nt++) {
            int col = bn + wn * 64 + nt * 8 + col2;
            float bx = bias[col], by = bias[col + 1];
#pragma unroll
            for (int half = 0; half < 2; half++) {
                int row = bm + wm * 64 + mt * 16 + row_in + half * 8;
                size_t off = (size_t)row * N + col;
                float v0 = acc[mt][nt][half * 2 + 0] + bx;
                float v1 = acc[mt][nt][half * 2 + 1] + by;
                if (EPI == 0) {
                    *(float2*)&Cf[off] = make_float2(v0, v1);
                } else {
                    __half2 hh;
                    hh.x = __float2half(gelu_exact(v0));
                    hh.y = __float2half(gelu_exact(v1));
                    *(__half2*)&Ch[off] = hh;
                }
            }
        }
    }
}

// ===========================================================================
// BIG-TILE GEMM (QKV): CTA 128x256, 512 threads (16 warps, 2x8),
// warptile 64x32, BK=64, 3-stage. EPI 2 = fp16 out.
// ===========================================================================
#define ROWB     144
#define BT_TA    (128 * ROWB)               // 18432
#define BT_TB    (256 * ROWB)               // 36864
#define BT_STG   (BT_TA + BT_TB)            // 55296
#define BT_SMEM  (3 * BT_STG)               // 165888

static __device__ __forceinline__ void bt_load(
    uint32_t st, const __half* __restrict__ A, const __half* __restrict__ Bm,
    int bm, int bn, int k0, int K, int tid)
{
#pragma unroll
    for (int i = 0; i < 2; i++) {
        int c = tid + (i << 9);
        int r = c >> 3, q = c & 7;
        cpa16(st + (uint32_t)(r * ROWB + q * 16),
              A + (size_t)(bm + r) * K + k0 + (q << 3));
    }
#pragma unroll
    for (int i = 0; i < 4; i++) {
        int c = tid + (i << 9);
        int r = c >> 3, q = c & 7;
        cpa16(st + BT_TA + (uint32_t)(r * ROWB + q * 16),
              Bm + (size_t)(bn + r) * K + k0 + (q << 3));
    }
}

__global__ __launch_bounds__(512, 1) void btgemm_kernel(
    const __half* __restrict__ A, const __half* __restrict__ Bm,
    const float* __restrict__ bias,
    __half* __restrict__ Ch,
    int N, int K)
{
    extern __shared__ __align__(1024) unsigned char smem[];
    uint32_t sb = smem_u32(smem);
    int tid = threadIdx.x, wid = tid >> 5, lane = tid & 31;
    int bm = blockIdx.x * 128, bn = blockIdx.y * 256;
    int wm = wid & 1, wn = wid >> 1;

    uint32_t a_lane = (uint32_t)((wm * 64 + (lane & 15)) * ROWB + ((lane >> 4) << 4));
    uint32_t b_lane = (uint32_t)(BT_TA + ((lane & 7) + ((lane >> 4) << 3)) * ROWB
                                 + (((lane >> 3) & 1) << 4));

    float acc[4][4][4];
#pragma unroll
    for (int i = 0; i < 4; i++)
#pragma unroll
        for (int j = 0; j < 4; j++)
#pragma unroll
            for (int e = 0; e < 4; e++) acc[i][j][e] = 0.f;

    int nk = K >> 6;
    bt_load(sb,          A, Bm, bm, bn, 0,  K, tid); CP_COMMIT();
    bt_load(sb + BT_STG, A, Bm, bm, bn, 64, K, tid); CP_COMMIT();

    uint32_t stg[3] = {sb, sb + BT_STG, sb + 2 * BT_STG};
    int cur = 0, nxt = 2;
    for (int kt = 0; kt < nk; kt++) {
        CP_WAIT1();
        __syncthreads();

        int kf = kt + 2;
        if (kf < nk)
            bt_load(stg[nxt], A, Bm, bm, bn, kf << 6, K, tid);
        CP_COMMIT();

        uint32_t st = stg[cur];
        cur = (cur + 1) % 3; nxt = (nxt + 1) % 3;
#pragma unroll
        for (int ks = 0; ks < 4; ks++) {
            uint32_t kb = ks << 5;
            Frag4 ah[4];
#pragma unroll
            for (int mt = 0; mt < 4; mt++)
                ah[mt] = ldsm_x4(st + a_lane + mt * (16 * ROWB) + kb);
#pragma unroll
            for (int np = 0; np < 2; np++) {
                Frag4 bf = ldsm_x4(st + b_lane + (wn * 32 + np * 16) * ROWB + kb);
#pragma unroll
                for (int mt = 0; mt < 4; mt++) {
                    mma_f16(acc[mt][np * 2],     ah[mt], bf.x, bf.y);
                    mma_f16(acc[mt][np * 2 + 1], ah[mt], bf.z, bf.w);
                }
            }
        }
    }
    __syncthreads();

    int row_in = lane >> 2;
    int col2   = (lane & 3) << 1;
#pragma unroll
    for (int mt = 0; mt < 4; mt++) {
#pragma unroll
        for (int nt = 0; nt < 4; nt++) {
            int col = bn + wn * 32 + nt * 8 + col2;
            float bx = bias[col], by = bias[col + 1];
#pragma unroll
            for (int half = 0; half < 2; half++) {
                int row = bm + wm * 64 + mt * 16 + row_in + half * 8;
                size_t off = (size_t)row * N + col;
                __half2 hh;
                hh.x = __float2half(acc[mt][nt][half * 2 + 0] + bx);
                hh.y = __float2half(acc[mt][nt][half * 2 + 1] + by);
                *(__half2*)&Ch[off] = hh;
            }
        }
    }
}

// ===========================================================================
// SMALL-TILE GEMM (N=1024): CTA 128x128, BK=64, 3-stage, 2 CTAs/SM.
// fp32 out: +bias +residual
// ===========================================================================
#define TILE_A  (128 * ROWB)
#define STAGE_B (2 * TILE_A)
#define SMEM_G  (3 * STAGE_B)         // 110592

static __device__ __forceinline__ void load_stage(
    uint32_t st, const __half* __restrict__ A, const __half* __restrict__ Bm,
    int bm, int bn, int k0, int K, int tid)
{
#pragma unroll
    for (int i = 0; i < 4; i++) {
        int c = tid + (i << 8);
        int r = c >> 3, q = c & 7;
        uint32_t so = (uint32_t)(r * ROWB + q * 16);
        cpa16(st + so, A + (size_t)(bm + r) * K + k0 + (q << 3));
    }
#pragma unroll
    for (int i = 0; i < 4; i++) {
        int c = tid + (i << 8);
        int r = c >> 3, q = c & 7;
        uint32_t so = (uint32_t)(r * ROWB + q * 16);
        cpa16(st + TILE_A + so, Bm + (size_t)(bn + r) * K + k0 + (q << 3));
    }
}

__global__ __launch_bounds__(256, 2) void tgemm_res_kernel(
    const __half* __restrict__ A, const __half* __restrict__ Bm,
    const float* __restrict__ bias, const float* __restrict__ res,
    float* __restrict__ Cf, int N, int K)
{
    extern __shared__ __align__(1024) unsigned char smem[];
    uint32_t sb = smem_u32(smem);
    int tid = threadIdx.x, wid = tid >> 5, lane = tid & 31;
    int bm = blockIdx.x * 128, bn = blockIdx.y * 128;
    int wm = wid & 1, wn = wid >> 1;

    uint32_t a_lane = (uint32_t)((wm * 64 + (lane & 15)) * ROWB + ((lane >> 4) << 4));
    uint32_t b_lane = (uint32_t)(TILE_A + ((lane & 7) + ((lane >> 4) << 3)) * ROWB
                                 + (((lane >> 3) & 1) << 4));

    float acc[4][4][4];
#pragma unroll
    for (int i = 0; i < 4; i++)
#pragma unroll
        for (int j = 0; j < 4; j++)
#pragma unroll
            for (int e = 0; e < 4; e++) acc[i][j][e] = 0.f;

    int nk = K >> 6;
    load_stage(sb,           A, Bm, bm, bn, 0,  K, tid); CP_COMMIT();
    load_stage(sb + STAGE_B, A, Bm, bm, bn, 64, K, tid); CP_COMMIT();

    uint32_t stg[3] = {sb, sb + STAGE_B, sb + 2 * STAGE_B};
    int cur = 0, nxt = 2;
    for (int kt = 0; kt < nk; kt++) {
        CP_WAIT1();
        __syncthreads();

        int kf = kt + 2;
        if (kf < nk)
            load_stage(stg[nxt], A, Bm, bm, bn, kf << 6, K, tid);
        CP_COMMIT();

        uint32_t st = stg[cur];
        cur = (cur + 1) % 3; nxt = (nxt + 1) % 3;
#pragma unroll
        for (int ks = 0; ks < 4; ks++) {
            uint32_t kb = ks << 5;
            Frag4 ah[4];
#pragma unroll
            for (int mt = 0; mt < 4; mt++)
                ah[mt] = ldsm_x4(st + a_lane + mt * (16 * ROWB) + kb);
#pragma unroll
            for (int np = 0; np < 2; np++) {
                Frag4 bf = ldsm_x4(st + b_lane + (wn * 32 + np * 16) * ROWB + kb);
#pragma unroll
                for (int mt = 0; mt < 4; mt++) {
                    mma_f16(acc[mt][np * 2],     ah[mt], bf.x, bf.y);
                    mma_f16(acc[mt][np * 2 + 1], ah[mt], bf.z, bf.w);
                }
            }
        }
    }
    __syncthreads();

    int row_in = lane >> 2;
    int col2   = (lane & 3) << 1;
#pragma unroll
    for (int mt = 0; mt < 4; mt++) {
#pragma unroll
        for (int nt = 0; nt < 4; nt++) {
            int col = bn + wn * 32 + nt * 8 + col2;
            float bx = bias[col], by = bias[col + 1];
#pragma unroll
            for (int half = 0; half < 2; half++) {
                int row = bm + wm * 64 + mt * 16 + row_in + half * 8;
                size_t off = (size_t)row * N + col;
                float2 rv = *(const float2*)&res[off];
                *(float2*)&Cf[off] = make_float2(acc[mt][nt][half * 2 + 0] + bx + rv.x,
                                                 acc[mt][nt][half * 2 + 1] + by + rv.y);
            }
        }
    }
}

// ===========================================================================
// Flash attention (HMMA fp16, fp32 softmax). qkv fp16 [M,3E] -> oh fp16 [M,E]
// ===========================================================================
__global__ __launch_bounds__(128) void fattn_kernel(const __half* __restrict__ qkv,
                                                    __half* __restrict__ oh) {
    __shared__ __half Qs[64 * 72];
    __shared__ __half Ks[2][64 * 72];
    __shared__ __half Vs[2][64 * 72];

    int tid = threadIdx.x, wid = tid >> 5, lane = tid & 31;
    int qt = 31 - (blockIdx.x & 31);         // long blocks first
    int bh = blockIdx.x >> 5;
    int b  = bh >> 4, hh = bh & 15;
    int q0 = qt * 64;

    for (int i = tid; i < 512; i += 128) {
        int r = i >> 3, c8 = (i & 7) << 3;
        *(uint4*)&Qs[r * 72 + c8] =
            *(const uint4*)(qkv + (size_t)(b * T_ + q0 + r) * 3072 + hh * 64 + c8);
    }
    __syncthreads();

    uint32_t qbase = smem_u32(Qs);
    Frag4 qf[4];
    {
        int rr = wid * 16 + (lane & 15);
#pragma unroll
        for (int kd = 0; kd < 4; kd++)
            qf[kd] = ldsm_x4(qbase + (uint32_t)(rr * 144 + kd * 32 + ((lane >> 4) << 4)));
    }

    uint32_t ksb[2] = {smem_u32(Ks[0]), smem_u32(Ks[1])};
    uint32_t vsb[2] = {smem_u32(Vs[0]), smem_u32(Vs[1])};

    float o[8][4];
#pragma unroll
    for (int t = 0; t < 8; t++)
#pragma unroll
        for (int e = 0; e < 4; e++) o[t][e] = 0.f;
    float m0 = -1e30f, m1 = -1e30f, l0 = 0.f, l1 = 0.f;

    const float SC = 0.18033688011f;   // 0.125 * log2(e)
    int ntiles = qt + 1;

    for (int i = tid; i < 512; i += 128) {
        int r = i >> 3, c8 = (i & 7) << 3;
        size_t base = (size_t)(b * T_ + r) * 3072 + hh * 64 + c8;
        cpa16(ksb[0] + (uint32_t)(r * 144 + c8 * 2), qkv + base + 1024);
        cpa16(vsb[0] + (uint32_t)(r * 144 + c8 * 2), qkv + base + 2048);
    }
    CP_COMMIT();

    for (int t = 0; t < ntiles; t++) {
        if (t + 1 < ntiles) {
            int kb = (t + 1) * 64;
            int buf = (t + 1) & 1;
            for (int i = tid; i < 512; i += 128) {
                int r = i >> 3, c8 = (i & 7) << 3;
                size_t base = (size_t)(b * T_ + kb + r) * 3072 + hh * 64 + c8;
                cpa16(ksb[buf] + (uint32_t)(r * 144 + c8 * 2), qkv + base + 1024);
                cpa16(vsb[buf] + (uint32_t)(r * 144 + c8 * 2), qkv + base + 2048);
            }
            CP_COMMIT();
            CP_WAIT1();
        } else {
            CP_WAIT0();
        }
        __syncthreads();

        int buf = t & 1;
        uint32_t kb_s = ksb[buf], vb_s = vsb[buf];

        float s[8][4];
#pragma unroll
        for (int j = 0; j < 8; j++)
#pragma unroll
            for (int e = 0; e < 4; e++) s[j][e] = 0.f;
#pragma unroll
        for (int kd = 0; kd < 4; kd++) {
#pragma unroll
            for (int np = 0; np < 4; np++) {
                Frag4 bf = ldsm_x4(kb_s + (uint32_t)((np * 16 + (lane & 7) + ((lane >> 4) << 3)) * 144
                                                     + kd * 32 + (((lane >> 3) & 1) << 4)));
                mma_f16(s[np * 2],     qf[kd], bf.x, bf.y);
                mma_f16(s[np * 2 + 1], qf[kd], bf.z, bf.w);
            }
        }

#pragma unroll
        for (int j = 0; j < 8; j++)
#pragma unroll
            for (int e = 0; e < 4; e++) s[j][e] *= SC;

        if (t == qt) {
            int lr0 = wid * 16 + (lane >> 2);
#pragma unroll
            for (int j = 0; j < 8; j++) {
                int c = 8 * j + 2 * (lane & 3);
                if (c     > lr0)     s[j][0] = -1e30f;
                if (c + 1 > lr0)     s[j][1] = -1e30f;
                if (c     > lr0 + 8) s[j][2] = -1e30f;
                if (c + 1 > lr0 + 8) s[j][3] = -1e30f;
            }
        }

        float mr0 = -1e30f, mr1 = -1e30f;
#pragma unroll
        for (int j = 0; j < 8; j++) {
            mr0 = fmaxf(mr0, fmaxf(s[j][0], s[j][1]));
            mr1 = fmaxf(mr1, fmaxf(s[j][2], s[j][3]));
        }
        mr0 = fmaxf(mr0, __shfl_xor_sync(0xffffffffu, mr0, 1));
        mr0 = fmaxf(mr0, __shfl_xor_sync(0xffffffffu, mr0, 2));
        mr1 = fmaxf(mr1, __shfl_xor_sync(0xffffffffu, mr1, 1));
        mr1 = fmaxf(mr1, __shfl_xor_sync(0xffffffffu, mr1, 2));

        float nm0 = fmaxf(m0, mr0), nm1 = fmaxf(m1, mr1);
        float c0 = ex2f(m0 - nm0), c1 = ex2f(m1 - nm1);
        m0 = nm0; m1 = nm1;
        l0 *= c0; l1 *= c1;

        uint32_t pf[8][2];
        float ps0 = 0.f, ps1 = 0.f;
#pragma unroll
        for (int j = 0; j < 8; j++) {
            float p0 = ex2f(s[j][0] - m0), p1 = ex2f(s[j][1] - m0);
            float p2 = ex2f(s[j][2] - m1), p3 = ex2f(s[j][3] - m1);
            ps0 += p0 + p1; ps1 += p2 + p3;
            __half2 h01 = __floats2half2_rn(p0, p1);
            __half2 h23 = __floats2half2_rn(p2, p3);
            pf[j][0] = *(uint32_t*)&h01;
            pf[j][1] = *(uint32_t*)&h23;
        }
        l0 += ps0; l1 += ps1;

#pragma unroll
        for (int tt = 0; tt < 8; tt++) {
            o[tt][0] *= c0; o[tt][1] *= c0;
            o[tt][2] *= c1; o[tt][3] *= c1;
        }

#pragma unroll
        for (int j = 0; j < 4; j++) {
            uint32_t a0 = pf[2 * j][0],     a1 = pf[2 * j][1];
            uint32_t a2 = pf[2 * j + 1][0], a3 = pf[2 * j + 1][1];
#pragma unroll
            for (int t2 = 0; t2 < 4; t2++) {
                Frag4 vf = ldsm_x4_t(vb_s + (uint32_t)((j * 16 + (lane & 7) + (((lane >> 3) & 1) << 3)) * 144
                                                       + t2 * 32 + ((lane >> 4) << 4)));
                mma4(o[2 * t2],     a0, a1, a2, a3, vf.x, vf.y);
                mma4(o[2 * t2 + 1], a0, a1, a2, a3, vf.z, vf.w);
            }
        }
        __syncthreads();
    }

    l0 += __shfl_xor_sync(0xffffffffu, l0, 1);
    l0 += __shfl_xor_sync(0xffffffffu, l0, 2);
    l1 += __shfl_xor_sync(0xffffffffu, l1, 1);
    l1 += __shfl_xor_sync(0xffffffffu, l1, 2);
    float li0 = 1.0f / l0, li1 = 1.0f / l1;

    int r0g = q0 + wid * 16 + (lane >> 2);
    int dbase = hh * 64 + 2 * (lane & 3);
#pragma unroll
    for (int tt = 0; tt < 8; tt++) {
        __half2 h01 = __floats2half2_rn(o[tt][0] * li0, o[tt][1] * li0);
        __half2 h23 = __floats2half2_rn(o[tt][2] * li1, o[tt][3] * li1);
        *(__half2*)&oh[(size_t)(b * T_ + r0g) * E_ + dbase + tt * 8]       = h01;
        *(__half2*)&oh[(size_t)(b * T_ + r0g + 8) * E_ + dbase + tt * 8]   = h23;
    }
}

// ---------------------------------------------------------------------------
// Weight transpose + fp16
// ---------------------------------------------------------------------------
__global__ void wconv_kernel(const float* __restrict__ W,
                             __half* __restrict__ Th,
                             int K, int N, size_t inLs, size_t outLs)
{
    __shared__ float t[32][33];
    const float* Wl = W + blockIdx.z * inLs;
    Th += blockIdx.z * outLs;
    int n0 = blockIdx.x * 32, k0 = blockIdx.y * 32;
    int tx = threadIdx.x, ty = threadIdx.y;
#pragma unroll
    for (int i = 0; i < 4; i++)
        t[ty + 8 * i][tx] = Wl[(size_t)(k0 + ty + 8 * i) * N + n0 + tx];
    __syncthreads();
#pragma unroll
    for (int i = 0; i < 4; i++) {
        int n = ty + 8 * i;
        Th[(size_t)(n0 + n) * K + k0 + tx] = __float2half(t[tx][n]);
    }
}

__global__ void wconv_qkv_kernel(const float* __restrict__ Wq,
                                 const float* __restrict__ Wk,
                                 const float* __restrict__ Wv,
                                 const float* __restrict__ bq,
                                 const float* __restrict__ bk,
                                 const float* __restrict__ bv,
                                 __half* __restrict__ Th,
                                 float* __restrict__ bqkv)
{
    __shared__ float t[32][33];
    int l = blockIdx.z / 3, which = blockIdx.z % 3;
    const size_t EE = (size_t)E_ * E_;
    const float* Wl = (which == 0 ? Wq : which == 1 ? Wk : Wv) + l * EE;
    const float* bl = (which == 0 ? bq : which == 1 ? bk : bv) + l * E_;
    Th += (size_t)l * 3 * EE + (size_t)which * EE;
    int n0 = blockIdx.x * 32, k0 = blockIdx.y * 32;
    int tx = threadIdx.x, ty = threadIdx.y;
    int tid = ty * 32 + tx;

    if (blockIdx.x == 0 && blockIdx.y == 0) {
#pragma unroll
        for (int i = 0; i < 4; i++) {
            int j = tid + 256 * i;
            bqkv[l * 3072 + which * 1024 + j] = bl[j];
        }
    }

#pragma unroll
    for (int i = 0; i < 4; i++)
        t[ty + 8 * i][tx] = Wl[(size_t)(k0 + ty + 8 * i) * E_ + n0 + tx];
    __syncthreads();
#pragma unroll
    for (int i = 0; i < 4; i++) {
        int n = ty + 8 * i;
        Th[(size_t)(n0 + n) * E_ + k0 + tx] = __float2half(t[tx][n]);
    }
}

// ---------------------------------------------------------------------------
// Embedding / LayerNorm
// ---------------------------------------------------------------------------
__global__ void embed_kernel(const int* __restrict__ x, const float* __restrict__ tok,
                             const float* __restrict__ pos, float* __restrict__ h) {
    int i = blockIdx.x * 256 + threadIdx.x;
    int row = i >> 10, e = i & 1023;
    int tkn = x[row];
    int t = row & (T_ - 1);
    h[i] = tok[(size_t)tkn * E_ + e] + pos[(size_t)t * E_ + e];
}

__global__ __launch_bounds__(256) void ln_kernel(const float* __restrict__ in,
                                                 const float* __restrict__ gam,
                                                 const float* __restrict__ bet,
                                                 __half* __restrict__ outh) {
    int row = blockIdx.x;
    const float* xr = in + (size_t)row * E_;
    float v0[4];
    float s = 0.f;
#pragma unroll
    for (int i = 0; i < 4; i++) { v0[i] = xr[threadIdx.x + 256 * i]; s += v0[i]; }

    __shared__ float sh[8];
    float t = s;
#pragma unroll
    for (int o = 16; o > 0; o >>= 1) t += __shfl_xor_sync(0xffffffffu, t, o);
    if ((threadIdx.x & 31) == 0) sh[threadIdx.x >> 5] = t;
    __syncthreads();
    float tot = 0.f;
#pragma unroll
    for (int i = 0; i < 8; i++) tot += sh[i];
    float mean = tot * (1.0f / E_);

    float vs = 0.f;
#pragma unroll
    for (int i = 0; i < 4; i++) { float d = v0[i] - mean; vs += d * d; }
    __syncthreads();
    t = vs;
#pragma unroll
    for (int o = 16; o > 0; o >>= 1) t += __shfl_xor_sync(0xffffffffu, t, o);
    if ((threadIdx.x & 31) == 0) sh[threadIdx.x >> 5] = t;
    __syncthreads();
    tot = 0.f;
#pragma unroll
    for (int i = 0; i < 8; i++) tot += sh[i];
    float rstd = rsqrtf(tot * (1.0f / E_) + 1e-5f);

#pragma unroll
    for (int i = 0; i < 4; i++) {
        int e = threadIdx.x + 256 * i;
        float y = (v0[i] - mean) * rstd * gam[e] + bet[e];
        outh[(size_t)row * E_ + e] = __float2half(y);
    }
}

// ---------------------------------------------------------------------------
// Host orchestration
// ---------------------------------------------------------------------------
extern "C" void kernel_launch(void* const* d_in, const int* in_sizes, int n_in,
                              void* d_out, int out_size) {
    const int*   x    = (const int*)  d_in[0];
    const float* tok  = (const float*)d_in[1];
    const float* pos  = (const float*)d_in[2];
    const float* Wq   = (const float*)d_in[3];
    const float* bq   = (const float*)d_in[4];
    const float* Wk   = (const float*)d_in[5];
    const float* bk   = (const float*)d_in[6];
    const float* Wv   = (const float*)d_in[7];
    const float* bv   = (const float*)d_in[8];
    const float* Wo   = (const float*)d_in[9];
    const float* bo   = (const float*)d_in[10];
    const float* ln1g = (const float*)d_in[11];
    const float* ln1b = (const float*)d_in[12];
    const float* W1   = (const float*)d_in[13];
    const float* b1   = (const float*)d_in[14];
    const float* W2   = (const float*)d_in[15];
    const float* b2   = (const float*)d_in[16];
    const float* ln2g = (const float*)d_in[17];
    const float* ln2b = (const float*)d_in[18];
    const float* lnfg = (const float*)d_in[19];
    const float* lnfb = (const float*)d_in[20];
    const float* Wout = (const float*)d_in[21];
    const float* bout = (const float*)d_in[22];
    float* out = (float*)d_out;

    float *h, *bqkv;
    __half *qkvh, *xn, *o, *mlp;
    __half *qkvT, *woT, *w1T, *w2T, *wouT;
    cudaGetSymbolAddress((void**)&h,    g_h);
    cudaGetSymbolAddress((void**)&qkvh, g_qkv);
    cudaGetSymbolAddress((void**)&bqkv, g_bqkv);
    cudaGetSymbolAddress((void**)&xn,   g_xn);
    cudaGetSymbolAddress((void**)&o,    g_o);
    cudaGetSymbolAddress((void**)&mlp,  g_mlp);
    cudaGetSymbolAddress((void**)&qkvT, g_qkvT);
    cudaGetSymbolAddress((void**)&woT,  g_woT);
    cudaGetSymbolAddress((void**)&w1T,  g_w1T);
    cudaGetSymbolAddress((void**)&w2T,  g_w2T);
    cudaGetSymbolAddress((void**)&wouT, g_woutT);

    cudaFuncSetAttribute((const void*)btgemm_kernel,    cudaFuncAttributeMaxDynamicSharedMemorySize, BT_SMEM);
    cudaFuncSetAttribute((const void*)xtgemm_kernel<0>, cudaFuncAttributeMaxDynamicSharedMemorySize, XT_SMEM);
    cudaFuncSetAttribute((const void*)xtgemm_kernel<1>, cudaFuncAttributeMaxDynamicSharedMemorySize, XT_SMEM);
    cudaFuncSetAttribute((const void*)tgemm_res_kernel, cudaFuncAttributeMaxDynamicSharedMemorySize, SMEM_G);

    const size_t EE = (size_t)E_ * E_, EF = (size_t)E_ * F_;
    dim3 tb(32, 8);

    embed_kernel<<<(M_ * E_) / 256, 256>>>(x, tok, pos, h);                          // 0
    ln_kernel<<<M_, 256>>>(h, ln1g, ln1b, xn);                                       // 1
    wconv_qkv_kernel<<<dim3(32, 32, 3 * L_), tb>>>(Wq, Wk, Wv, bq, bk, bv,
                                                   qkvT, bqkv);                      // 2
    btgemm_kernel<<<dim3(M_ / 128, 12), 512, BT_SMEM>>>(                             // 3
        xn, qkvT, bqkv, qkvh, 3 * E_, E_);
    wconv_kernel<<<dim3(32, 32, L_), tb>>>(Wo, woT, E_, E_, EE, EE);                 // 4
    wconv_kernel<<<dim3(128, 32, L_), tb>>>(W1, w1T, E_, F_, EF, EF);                // 5
    wconv_kernel<<<dim3(32, 128, L_), tb>>>(W2, w2T, F_, E_, EF, EF);                // 6
    wconv_kernel<<<dim3(1000, 32, 1), tb>>>(Wout, wouT, E_, V_, 0, 0);               // 7

    for (int l = 0; l < L_; l++) {
        if (l > 0) {
            ln_kernel<<<M_, 256>>>(h, ln1g + l * E_, ln1b + l * E_, xn);
            btgemm_kernel<<<dim3(M_ / 128, 12), 512, BT_SMEM>>>(
                xn, qkvT + l * 3 * EE, bqkv + l * 3 * E_, qkvh, 3 * E_, E_);
        }
        fattn_kernel<<<B_ * H_ * (T_ / 64), 128>>>(qkvh, o);
        tgemm_res_kernel<<<dim3(M_ / 128, 8), 256, SMEM_G>>>(
            o, woT + l * EE, bo + l * E_, h, h, E_, E_);
        ln_kernel<<<M_, 256>>>(h, ln2g + l * E_, ln2b + l * E_, xn);
        xtgemm_kernel<1><<<dim3(M_ / 256, F_ / 256), 512, XT_SMEM>>>(
            xn, w1T + l * EF, b1 + l * F_, nullptr, mlp, F_, E_);
        tgemm_res_kernel<<<dim3(M_ / 128, 8), 256, SMEM_G>>>(
            mlp, w2T + l * EF, b2 + l * E_, h, h, E_, F_);
    }

    ln_kernel<<<M_, 256>>>(h, lnfg, lnfb, xn);
    xtgemm_kernel<0><<<dim3(M_ / 256, V_ / 256), 512, XT_SMEM>>>(
        xn, wouT, bout, out, nullptr, V_, E_);
}

// round 12
// speedup vs baseline: 1.4404x; 1.4404x over previous
#include <cuda_runtime.h>
#include <cuda_fp16.h>
#include <math.h>
#include <stdint.h>

// Problem dims
#define V_ 32000
#define E_ 1024
#define H_ 16
#define F_ 4096
#define L_ 4
#define T_ 2048
#define B_ 2
#define D_ 64
#define M_ (B_*T_)   // 4096

// ---------------------------------------------------------------------------
// Scratch (device globals; allocation APIs are forbidden)
// ---------------------------------------------------------------------------
__device__ float g_h  [M_*E_];
__device__ __half g_qkv[M_*3*E_];
__device__ float g_bqkv[L_*3*E_];
__device__ __half g_xn [M_*E_];
__device__ __half g_o  [M_*E_];
__device__ __half g_mlp[M_*F_];
__device__ __half g_qkvT[L_*3*E_*E_];
__device__ __half g_woT [L_*E_*E_];
__device__ __half g_w1T [L_*F_*E_];
__device__ __half g_w2T [L_*E_*F_];
__device__ __half g_woutC[(size_t)V_*E_];   // Wout as fp16, SAME [K,N] layout (no transpose)

// ---------------------------------------------------------------------------
// PTX helpers
// ---------------------------------------------------------------------------
__device__ __forceinline__ uint32_t smem_u32(const void* p) {
    uint32_t a;
    asm("{ .reg .u64 t; cvta.to.shared.u64 t, %1; cvt.u32.u64 %0, t; }" : "=r"(a) : "l"(p));
    return a;
}
static __device__ __forceinline__ void cpa16(uint32_t s, const void* g) {
    asm volatile("cp.async.cg.shared.global [%0], [%1], 16;" :: "r"(s), "l"(g) : "memory");
}
#define CP_COMMIT() asm volatile("cp.async.commit_group;" ::: "memory")
#define CP_WAIT0()  asm volatile("cp.async.wait_group 0;" ::: "memory")
#define CP_WAIT1()  asm volatile("cp.async.wait_group 1;" ::: "memory")

struct Frag4 { uint32_t x, y, z, w; };

static __device__ __forceinline__ Frag4 ldsm_x4(uint32_t addr) {
    Frag4 r;
    asm volatile("ldmatrix.sync.aligned.m8n8.x4.shared.b16 {%0,%1,%2,%3}, [%4];"
                 : "=r"(r.x), "=r"(r.y), "=r"(r.z), "=r"(r.w) : "r"(addr));
    return r;
}
static __device__ __forceinline__ Frag4 ldsm_x4_t(uint32_t addr) {
    Frag4 r;
    asm volatile("ldmatrix.sync.aligned.m8n8.x4.trans.shared.b16 {%0,%1,%2,%3}, [%4];"
                 : "=r"(r.x), "=r"(r.y), "=r"(r.z), "=r"(r.w) : "r"(addr));
    return r;
}

static __device__ __forceinline__ void mma_f16(float* c, const Frag4& a,
                                               uint32_t b0, uint32_t b1) {
    asm volatile(
        "mma.sync.aligned.m16n8k16.row.col.f32.f16.f16.f32 "
        "{%0,%1,%2,%3}, {%4,%5,%6,%7}, {%8,%9}, {%0,%1,%2,%3};"
        : "+f"(c[0]), "+f"(c[1]), "+f"(c[2]), "+f"(c[3])
        : "r"(a.x), "r"(a.y), "r"(a.z), "r"(a.w), "r"(b0), "r"(b1));
}
static __device__ __forceinline__ void mma4(float* c, uint32_t a0, uint32_t a1,
                                            uint32_t a2, uint32_t a3,
                                            uint32_t b0, uint32_t b1) {
    asm volatile(
        "mma.sync.aligned.m16n8k16.row.col.f32.f16.f16.f32 "
        "{%0,%1,%2,%3}, {%4,%5,%6,%7}, {%8,%9}, {%0,%1,%2,%3};"
        : "+f"(c[0]), "+f"(c[1]), "+f"(c[2]), "+f"(c[3])
        : "r"(a0), "r"(a1), "r"(a2), "r"(a3), "r"(b0), "r"(b1));
}

static __device__ __forceinline__ float ex2f(float x) {
    float y;
    asm("ex2.approx.ftz.f32 %0, %1;" : "=f"(y) : "f"(x));
    return y;
}

__device__ __forceinline__ float gelu_exact(float x) {
    return 0.5f * x * (1.0f + erff(x * 0.70710678118654752f));
}

// ===========================================================================
// BIG-TILE GEMM (QKV, MLP1): CTA 128x256, 512 threads (16 warps, 2x8),
// warptile 64x32, BK=64, 3-stage. EPI: 1 = gelu->fp16 ; 2 = fp16
// ===========================================================================
#define ROWB     144
#define BT_TA    (128 * ROWB)               // 18432
#define BT_TB    (256 * ROWB)               // 36864
#define BT_STG   (BT_TA + BT_TB)            // 55296
#define BT_SMEM  (3 * BT_STG)               // 165888

static __device__ __forceinline__ void bt_load(
    uint32_t st, const __half* __restrict__ A, const __half* __restrict__ Bm,
    int bm, int bn, int k0, int K, int tid)
{
#pragma unroll
    for (int i = 0; i < 2; i++) {
        int c = tid + (i << 9);
        int r = c >> 3, q = c & 7;
        cpa16(st + (uint32_t)(r * ROWB + q * 16),
              A + (size_t)(bm + r) * K + k0 + (q << 3));
    }
#pragma unroll
    for (int i = 0; i < 4; i++) {
        int c = tid + (i << 9);
        int r = c >> 3, q = c & 7;
        cpa16(st + BT_TA + (uint32_t)(r * ROWB + q * 16),
              Bm + (size_t)(bn + r) * K + k0 + (q << 3));
    }
}

template<int EPI>
__global__ __launch_bounds__(512, 1) void btgemm_kernel(
    const __half* __restrict__ A, const __half* __restrict__ Bm,
    const float* __restrict__ bias,
    float* __restrict__ Cf, __half* __restrict__ Ch,
    int N, int K)
{
    extern __shared__ __align__(1024) unsigned char smem[];
    uint32_t sb = smem_u32(smem);
    int tid = threadIdx.x, wid = tid >> 5, lane = tid & 31;
    int bm = blockIdx.x * 128, bn = blockIdx.y * 256;
    int wm = wid & 1, wn = wid >> 1;

    uint32_t a_lane = (uint32_t)((wm * 64 + (lane & 15)) * ROWB + ((lane >> 4) << 4));
    uint32_t b_lane = (uint32_t)(BT_TA + ((lane & 7) + ((lane >> 4) << 3)) * ROWB
                                 + (((lane >> 3) & 1) << 4));

    float acc[4][4][4];
#pragma unroll
    for (int i = 0; i < 4; i++)
#pragma unroll
        for (int j = 0; j < 4; j++)
#pragma unroll
            for (int e = 0; e < 4; e++) acc[i][j][e] = 0.f;

    int nk = K >> 6;
    bt_load(sb,          A, Bm, bm, bn, 0,  K, tid); CP_COMMIT();
    bt_load(sb + BT_STG, A, Bm, bm, bn, 64, K, tid); CP_COMMIT();

    uint32_t stg[3] = {sb, sb + BT_STG, sb + 2 * BT_STG};
    int cur = 0, nxt = 2;
    for (int kt = 0; kt < nk; kt++) {
        CP_WAIT1();
        __syncthreads();

        int kf = kt + 2;
        if (kf < nk)
            bt_load(stg[nxt], A, Bm, bm, bn, kf << 6, K, tid);
        CP_COMMIT();

        uint32_t st = stg[cur];
        cur = (cur + 1) % 3; nxt = (nxt + 1) % 3;
#pragma unroll
        for (int ks = 0; ks < 4; ks++) {
            uint32_t kb = ks << 5;
            Frag4 ah[4];
#pragma unroll
            for (int mt = 0; mt < 4; mt++)
                ah[mt] = ldsm_x4(st + a_lane + mt * (16 * ROWB) + kb);
#pragma unroll
            for (int np = 0; np < 2; np++) {
                Frag4 bf = ldsm_x4(st + b_lane + (wn * 32 + np * 16) * ROWB + kb);
#pragma unroll
                for (int mt = 0; mt < 4; mt++) {
                    mma_f16(acc[mt][np * 2],     ah[mt], bf.x, bf.y);
                    mma_f16(acc[mt][np * 2 + 1], ah[mt], bf.z, bf.w);
                }
            }
        }
    }
    __syncthreads();

    int row_in = lane >> 2;
    int col2   = (lane & 3) << 1;
#pragma unroll
    for (int mt = 0; mt < 4; mt++) {
#pragma unroll
        for (int nt = 0; nt < 4; nt++) {
            int col = bn + wn * 32 + nt * 8 + col2;
            float bx = bias[col], by = bias[col + 1];
#pragma unroll
            for (int half = 0; half < 2; half++) {
                int row = bm + wm * 64 + mt * 16 + row_in + half * 8;
                size_t off = (size_t)row * N + col;
                float v0 = acc[mt][nt][half * 2 + 0] + bx;
                float v1 = acc[mt][nt][half * 2 + 1] + by;
                if (EPI == 0) {
                    *(float2*)&Cf[off] = make_float2(v0, v1);
                } else if (EPI == 1) {
                    __half2 hh;
                    hh.x = __float2half(gelu_exact(v0));
                    hh.y = __float2half(gelu_exact(v1));
                    *(__half2*)&Ch[off] = hh;
                } else {
                    __half2 hh;
                    hh.x = __float2half(v0);
                    hh.y = __float2half(v1);
                    *(__half2*)&Ch[off] = hh;
                }
            }
        }
    }
}

// ===========================================================================
// TRANS-B GEMM (Wout): B read directly from [K,N] fp16 (N-contig), fragments
// via ldmatrix.trans (same pattern as fattn P@V). CTA 128x256, 512 threads,
// warptile 64x32, BK=32, 3-stage. fp32 +bias out.
// ===========================================================================
#define WT_AROW  80
#define WT_AT    (128 * WT_AROW)            // 10240
#define WT_BROW  528
#define WT_BT    (32 * WT_BROW)             // 16896
#define WT_STG   (WT_AT + WT_BT)            // 27136
#define WT_SMEM  (3 * WT_STG)               // 81408

static __device__ __forceinline__ void wt_load(
    uint32_t st, const __half* __restrict__ A, const __half* __restrict__ Bm,
    int bm, int bn, int k0, int K, int N, int tid)
{
    {   // A: 128 rows x 4 chunks (32 f16/row) = 512
        int r = tid >> 2, q = tid & 3;
        cpa16(st + (uint32_t)(r * WT_AROW + q * 16),
              A + (size_t)(bm + r) * K + k0 + (q << 3));
    }
#pragma unroll
    for (int i = 0; i < 2; i++) {   // B: 32 k-rows x 32 chunks (256 f16/row) = 1024
        int c = tid + (i << 9);
        int r = c >> 5, q = c & 31;
        cpa16(st + WT_AT + (uint32_t)(r * WT_BROW + q * 16),
              Bm + (size_t)(k0 + r) * N + bn + (q << 3));
    }
}

__global__ __launch_bounds__(512, 1) void wtgemm_kernel(
    const __half* __restrict__ A, const __half* __restrict__ Bm,
    const float* __restrict__ bias, float* __restrict__ Cf,
    int N, int K)
{
    extern __shared__ __align__(1024) unsigned char smem[];
    uint32_t sb = smem_u32(smem);
    int tid = threadIdx.x, wid = tid >> 5, lane = tid & 31;
    int bm = blockIdx.x * 128, bn = blockIdx.y * 256;
    int wm = wid & 1, wn = wid >> 1;

    uint32_t a_lane = (uint32_t)((wm * 64 + (lane & 15)) * WT_AROW + ((lane >> 4) << 4));
    uint32_t b_row  = (uint32_t)((lane & 7) + (((lane >> 3) & 1) << 3));
    uint32_t b_colb = (uint32_t)(wn * 64 + ((lane >> 4) << 4));

    float acc[4][4][4];
#pragma unroll
    for (int i = 0; i < 4; i++)
#pragma unroll
        for (int j = 0; j < 4; j++)
#pragma unroll
            for (int e = 0; e < 4; e++) acc[i][j][e] = 0.f;

    int nk = K >> 5;
    wt_load(sb,          A, Bm, bm, bn, 0,  K, N, tid); CP_COMMIT();
    wt_load(sb + WT_STG, A, Bm, bm, bn, 32, K, N, tid); CP_COMMIT();

    uint32_t stg[3] = {sb, sb + WT_STG, sb + 2 * WT_STG};
    int cur = 0, nxt = 2;
    for (int kt = 0; kt < nk; kt++) {
        CP_WAIT1();
        __syncthreads();

        int kf = kt + 2;
        if (kf < nk)
            wt_load(stg[nxt], A, Bm, bm, bn, kf << 5, K, N, tid);
        CP_COMMIT();

        uint32_t st = stg[cur];
        cur = (cur + 1) % 3; nxt = (nxt + 1) % 3;
#pragma unroll
        for (int kd = 0; kd < 2; kd++) {
            Frag4 ah[4];
#pragma unroll
            for (int mt = 0; mt < 4; mt++)
                ah[mt] = ldsm_x4(st + a_lane + mt * (16 * WT_AROW) + kd * 32);
#pragma unroll
            for (int np = 0; np < 2; np++) {
                Frag4 bf = ldsm_x4_t(st + WT_AT
                                     + (kd * 16 + b_row) * WT_BROW
                                     + b_colb + np * 32);
#pragma unroll
                for (int mt = 0; mt < 4; mt++) {
                    mma_f16(acc[mt][np * 2],     ah[mt], bf.x, bf.y);
                    mma_f16(acc[mt][np * 2 + 1], ah[mt], bf.z, bf.w);
                }
            }
        }
    }
    __syncthreads();

    int row_in = lane >> 2;
    int col2   = (lane & 3) << 1;
#pragma unroll
    for (int mt = 0; mt < 4; mt++) {
#pragma unroll
        for (int nt = 0; nt < 4; nt++) {
            int col = bn + wn * 32 + nt * 8 + col2;
            float bx = bias[col], by = bias[col + 1];
#pragma unroll
            for (int half = 0; half < 2; half++) {
                int row = bm + wm * 64 + mt * 16 + row_in + half * 8;
                size_t off = (size_t)row * N + col;
                *(float2*)&Cf[off] = make_float2(acc[mt][nt][half * 2 + 0] + bx,
                                                 acc[mt][nt][half * 2 + 1] + by);
            }
        }
    }
}

// ===========================================================================
// SMALL-TILE GEMM (N=1024): CTA 128x128, BK=64, 3-stage, 2 CTAs/SM.
// fp32 out: +bias +residual
// ===========================================================================
#define TILE_A  (128 * ROWB)
#define STAGE_B (2 * TILE_A)
#define SMEM_G  (3 * STAGE_B)         // 110592

static __device__ __forceinline__ void load_stage(
    uint32_t st, const __half* __restrict__ A, const __half* __restrict__ Bm,
    int bm, int bn, int k0, int K, int tid)
{
#pragma unroll
    for (int i = 0; i < 4; i++) {
        int c = tid + (i << 8);
        int r = c >> 3, q = c & 7;
        uint32_t so = (uint32_t)(r * ROWB + q * 16);
        cpa16(st + so, A + (size_t)(bm + r) * K + k0 + (q << 3));
    }
#pragma unroll
    for (int i = 0; i < 4; i++) {
        int c = tid + (i << 8);
        int r = c >> 3, q = c & 7;
        uint32_t so = (uint32_t)(r * ROWB + q * 16);
        cpa16(st + TILE_A + so, Bm + (size_t)(bn + r) * K + k0 + (q << 3));
    }
}

__global__ __launch_bounds__(256, 2) void tgemm_res_kernel(
    const __half* __restrict__ A, const __half* __restrict__ Bm,
    const float* __restrict__ bias, const float* __restrict__ res,
    float* __restrict__ Cf, int N, int K)
{
    extern __shared__ __align__(1024) unsigned char smem[];
    uint32_t sb = smem_u32(smem);
    int tid = threadIdx.x, wid = tid >> 5, lane = tid & 31;
    int bm = blockIdx.x * 128, bn = blockIdx.y * 128;
    int wm = wid & 1, wn = wid >> 1;

    uint32_t a_lane = (uint32_t)((wm * 64 + (lane & 15)) * ROWB + ((lane >> 4) << 4));
    uint32_t b_lane = (uint32_t)(TILE_A + ((lane & 7) + ((lane >> 4) << 3)) * ROWB
                                 + (((lane >> 3) & 1) << 4));

    float acc[4][4][4];
#pragma unroll
    for (int i = 0; i < 4; i++)
#pragma unroll
        for (int j = 0; j < 4; j++)
#pragma unroll
            for (int e = 0; e < 4; e++) acc[i][j][e] = 0.f;

    int nk = K >> 6;
    load_stage(sb,           A, Bm, bm, bn, 0,  K, tid); CP_COMMIT();
    load_stage(sb + STAGE_B, A, Bm, bm, bn, 64, K, tid); CP_COMMIT();

    uint32_t stg[3] = {sb, sb + STAGE_B, sb + 2 * STAGE_B};
    int cur = 0, nxt = 2;
    for (int kt = 0; kt < nk; kt++) {
        CP_WAIT1();
        __syncthreads();

        int kf = kt + 2;
        if (kf < nk)
            load_stage(stg[nxt], A, Bm, bm, bn, kf << 6, K, tid);
        CP_COMMIT();

        uint32_t st = stg[cur];
        cur = (cur + 1) % 3; nxt = (nxt + 1) % 3;
#pragma unroll
        for (int ks = 0; ks < 4; ks++) {
            uint32_t kb = ks << 5;
            Frag4 ah[4];
#pragma unroll
            for (int mt = 0; mt < 4; mt++)
                ah[mt] = ldsm_x4(st + a_lane + mt * (16 * ROWB) + kb);
#pragma unroll
            for (int np = 0; np < 2; np++) {
                Frag4 bf = ldsm_x4(st + b_lane + (wn * 32 + np * 16) * ROWB + kb);
#pragma unroll
                for (int mt = 0; mt < 4; mt++) {
                    mma_f16(acc[mt][np * 2],     ah[mt], bf.x, bf.y);
                    mma_f16(acc[mt][np * 2 + 1], ah[mt], bf.z, bf.w);
                }
            }
        }
    }
    __syncthreads();

    int row_in = lane >> 2;
    int col2   = (lane & 3) << 1;
#pragma unroll
    for (int mt = 0; mt < 4; mt++) {
#pragma unroll
        for (int nt = 0; nt < 4; nt++) {
            int col = bn + wn * 32 + nt * 8 + col2;
            float bx = bias[col], by = bias[col + 1];
#pragma unroll
            for (int half = 0; half < 2; half++) {
                int row = bm + wm * 64 + mt * 16 + row_in + half * 8;
                size_t off = (size_t)row * N + col;
                float2 rv = *(const float2*)&res[off];
                *(float2*)&Cf[off] = make_float2(acc[mt][nt][half * 2 + 0] + bx + rv.x,
                                                 acc[mt][nt][half * 2 + 1] + by + rv.y);
            }
        }
    }
}

// ===========================================================================
// Flash attention (HMMA fp16, fp32 softmax). qkv fp16 [M,3E] -> oh fp16 [M,E]
// ===========================================================================
__global__ __launch_bounds__(128) void fattn_kernel(const __half* __restrict__ qkv,
                                                    __half* __restrict__ oh) {
    __shared__ __half Qs[64 * 72];
    __shared__ __half Ks[2][64 * 72];
    __shared__ __half Vs[2][64 * 72];

    int tid = threadIdx.x, wid = tid >> 5, lane = tid & 31;
    int qt = 31 - (blockIdx.x & 31);         // long blocks first
    int bh = blockIdx.x >> 5;
    int b  = bh >> 4, hh = bh & 15;
    int q0 = qt * 64;

    for (int i = tid; i < 512; i += 128) {
        int r = i >> 3, c8 = (i & 7) << 3;
        *(uint4*)&Qs[r * 72 + c8] =
            *(const uint4*)(qkv + (size_t)(b * T_ + q0 + r) * 3072 + hh * 64 + c8);
    }
    __syncthreads();

    uint32_t qbase = smem_u32(Qs);
    Frag4 qf[4];
    {
        int rr = wid * 16 + (lane & 15);
#pragma unroll
        for (int kd = 0; kd < 4; kd++)
            qf[kd] = ldsm_x4(qbase + (uint32_t)(rr * 144 + kd * 32 + ((lane >> 4) << 4)));
    }

    uint32_t ksb[2] = {smem_u32(Ks[0]), smem_u32(Ks[1])};
    uint32_t vsb[2] = {smem_u32(Vs[0]), smem_u32(Vs[1])};

    float o[8][4];
#pragma unroll
    for (int t = 0; t < 8; t++)
#pragma unroll
        for (int e = 0; e < 4; e++) o[t][e] = 0.f;
    float m0 = -1e30f, m1 = -1e30f, l0 = 0.f, l1 = 0.f;

    const float SC = 0.18033688011f;   // 0.125 * log2(e)
    int ntiles = qt + 1;

    for (int i = tid; i < 512; i += 128) {
        int r = i >> 3, c8 = (i & 7) << 3;
        size_t base = (size_t)(b * T_ + r) * 3072 + hh * 64 + c8;
        cpa16(ksb[0] + (uint32_t)(r * 144 + c8 * 2), qkv + base + 1024);
        cpa16(vsb[0] + (uint32_t)(r * 144 + c8 * 2), qkv + base + 2048);
    }
    CP_COMMIT();

    for (int t = 0; t < ntiles; t++) {
        if (t + 1 < ntiles) {
            int kb = (t + 1) * 64;
            int buf = (t + 1) & 1;
            for (int i = tid; i < 512; i += 128) {
                int r = i >> 3, c8 = (i & 7) << 3;
                size_t base = (size_t)(b * T_ + kb + r) * 3072 + hh * 64 + c8;
                cpa16(ksb[buf] + (uint32_t)(r * 144 + c8 * 2), qkv + base + 1024);
                cpa16(vsb[buf] + (uint32_t)(r * 144 + c8 * 2), qkv + base + 2048);
            }
            CP_COMMIT();
            CP_WAIT1();
        } else {
            CP_WAIT0();
        }
        __syncthreads();

        int buf = t & 1;
        uint32_t kb_s = ksb[buf], vb_s = vsb[buf];

        float s[8][4];
#pragma unroll
        for (int j = 0; j < 8; j++)
#pragma unroll
            for (int e = 0; e < 4; e++) s[j][e] = 0.f;
#pragma unroll
        for (int kd = 0; kd < 4; kd++) {
#pragma unroll
            for (int np = 0; np < 4; np++) {
                Frag4 bf = ldsm_x4(kb_s + (uint32_t)((np * 16 + (lane & 7) + ((lane >> 4) << 3)) * 144
                                                     + kd * 32 + (((lane >> 3) & 1) << 4)));
                mma_f16(s[np * 2],     qf[kd], bf.x, bf.y);
                mma_f16(s[np * 2 + 1], qf[kd], bf.z, bf.w);
            }
        }

#pragma unroll
        for (int j = 0; j < 8; j++)
#pragma unroll
            for (int e = 0; e < 4; e++) s[j][e] *= SC;

        if (t == qt) {
            int lr0 = wid * 16 + (lane >> 2);
#pragma unroll
            for (int j = 0; j < 8; j++) {
                int c = 8 * j + 2 * (lane & 3);
                if (c     > lr0)     s[j][0] = -1e30f;
                if (c + 1 > lr0)     s[j][1] = -1e30f;
                if (c     > lr0 + 8) s[j][2] = -1e30f;
                if (c + 1 > lr0 + 8) s[j][3] = -1e30f;
            }
        }

        float mr0 = -1e30f, mr1 = -1e30f;
#pragma unroll
        for (int j = 0; j < 8; j++) {
            mr0 = fmaxf(mr0, fmaxf(s[j][0], s[j][1]));
            mr1 = fmaxf(mr1, fmaxf(s[j][2], s[j][3]));
        }
        mr0 = fmaxf(mr0, __shfl_xor_sync(0xffffffffu, mr0, 1));
        mr0 = fmaxf(mr0, __shfl_xor_sync(0xffffffffu, mr0, 2));
        mr1 = fmaxf(mr1, __shfl_xor_sync(0xffffffffu, mr1, 1));
        mr1 = fmaxf(mr1, __shfl_xor_sync(0xffffffffu, mr1, 2));

        float nm0 = fmaxf(m0, mr0), nm1 = fmaxf(m1, mr1);
        float c0 = ex2f(m0 - nm0), c1 = ex2f(m1 - nm1);
        m0 = nm0; m1 = nm1;
        l0 *= c0; l1 *= c1;

        uint32_t pf[8][2];
        float ps0 = 0.f, ps1 = 0.f;
#pragma unroll
        for (int j = 0; j < 8; j++) {
            float p0 = ex2f(s[j][0] - m0), p1 = ex2f(s[j][1] - m0);
            float p2 = ex2f(s[j][2] - m1), p3 = ex2f(s[j][3] - m1);
            ps0 += p0 + p1; ps1 += p2 + p3;
            __half2 h01 = __floats2half2_rn(p0, p1);
            __half2 h23 = __floats2half2_rn(p2, p3);
            pf[j][0] = *(uint32_t*)&h01;
            pf[j][1] = *(uint32_t*)&h23;
        }
        l0 += ps0; l1 += ps1;

#pragma unroll
        for (int tt = 0; tt < 8; tt++) {
            o[tt][0] *= c0; o[tt][1] *= c0;
            o[tt][2] *= c1; o[tt][3] *= c1;
        }

#pragma unroll
        for (int j = 0; j < 4; j++) {
            uint32_t a0 = pf[2 * j][0],     a1 = pf[2 * j][1];
            uint32_t a2 = pf[2 * j + 1][0], a3 = pf[2 * j + 1][1];
#pragma unroll
            for (int t2 = 0; t2 < 4; t2++) {
                Frag4 vf = ldsm_x4_t(vb_s + (uint32_t)((j * 16 + (lane & 7) + (((lane >> 3) & 1) << 3)) * 144
                                                       + t2 * 32 + ((lane >> 4) << 4)));
                mma4(o[2 * t2],     a0, a1, a2, a3, vf.x, vf.y);
                mma4(o[2 * t2 + 1], a0, a1, a2, a3, vf.z, vf.w);
            }
        }
        __syncthreads();
    }

    l0 += __shfl_xor_sync(0xffffffffu, l0, 1);
    l0 += __shfl_xor_sync(0xffffffffu, l0, 2);
    l1 += __shfl_xor_sync(0xffffffffu, l1, 1);
    l1 += __shfl_xor_sync(0xffffffffu, l1, 2);
    float li0 = 1.0f / l0, li1 = 1.0f / l1;

    int r0g = q0 + wid * 16 + (lane >> 2);
    int dbase = hh * 64 + 2 * (lane & 3);
#pragma unroll
    for (int tt = 0; tt < 8; tt++) {
        __half2 h01 = __floats2half2_rn(o[tt][0] * li0, o[tt][1] * li0);
        __half2 h23 = __floats2half2_rn(o[tt][2] * li1, o[tt][3] * li1);
        *(__half2*)&oh[(size_t)(b * T_ + r0g) * E_ + dbase + tt * 8]       = h01;
        *(__half2*)&oh[(size_t)(b * T_ + r0g + 8) * E_ + dbase + tt * 8]   = h23;
    }
}

// ---------------------------------------------------------------------------
// Weight transpose + fp16 (128B-coalesced writes): W[K,N] -> T[N,K]
// tile = 32 n x 64 k, block (32,8)
// ---------------------------------------------------------------------------
__global__ void wconvT_kernel(const float* __restrict__ W,
                              __half* __restrict__ Th,
                              int K, int N, size_t inLs, size_t outLs)
{
    __shared__ float s[32][65];
    const float* Wl = W + blockIdx.z * inLs;
    Th += blockIdx.z * outLs;
    int n0 = blockIdx.x * 32, k0 = blockIdx.y * 64;
    int tx = threadIdx.x, ty = threadIdx.y;
    int tid = ty * 32 + tx;
#pragma unroll
    for (int i = 0; i < 8; i++) {
        int e = tid + 256 * i;
        int n = e & 31, k = e >> 5;
        s[n][k] = Wl[(size_t)(k0 + k) * N + n0 + n];
    }
    __syncthreads();
#pragma unroll
    for (int i = 0; i < 4; i++) {
        int n = ty + 8 * i;
        __half2 h = __floats2half2_rn(s[n][2 * tx], s[n][2 * tx + 1]);
        *(__half2*)&Th[(size_t)(n0 + n) * K + k0 + 2 * tx] = h;
    }
}

// QKV variant: grid.z = l*3 + which
__global__ void wconvT_qkv_kernel(const float* __restrict__ Wq,
                                  const float* __restrict__ Wk,
                                  const float* __restrict__ Wv,
                                  __half* __restrict__ Th)
{
    __shared__ float s[32][65];
    int l = blockIdx.z / 3, which = blockIdx.z % 3;
    const size_t EE = (size_t)E_ * E_;
    const float* Wl = (which == 0 ? Wq : which == 1 ? Wk : Wv) + l * EE;
    Th += (size_t)l * 3 * EE + (size_t)which * EE;
    int n0 = blockIdx.x * 32, k0 = blockIdx.y * 64;
    int tx = threadIdx.x, ty = threadIdx.y;
    int tid = ty * 32 + tx;
#pragma unroll
    for (int i = 0; i < 8; i++) {
        int e = tid + 256 * i;
        int n = e & 31, k = e >> 5;
        s[n][k] = Wl[(size_t)(k0 + k) * E_ + n0 + n];
    }
    __syncthreads();
#pragma unroll
    for (int i = 0; i < 4; i++) {
        int n = ty + 8 * i;
        __half2 h = __floats2half2_rn(s[n][2 * tx], s[n][2 * tx + 1]);
        *(__half2*)&Th[(size_t)(n0 + n) * E_ + k0 + 2 * tx] = h;
    }
}

// Plain f32 -> f16 copy for Wout (layout preserved [K,N])
__global__ void wcvt_kernel(const float* __restrict__ W, __half* __restrict__ Th) {
    size_t i = ((size_t)blockIdx.x * 256 + threadIdx.x) * 4;
    float4 v = *(const float4*)(W + i);
    __half2 a = __floats2half2_rn(v.x, v.y);
    __half2 b = __floats2half2_rn(v.z, v.w);
    *(__half2*)&Th[i]     = a;
    *(__half2*)&Th[i + 2] = b;
}

// Pack per-layer QKV biases into [L, 3E]
__global__ void bpack_kernel(const float* __restrict__ bq, const float* __restrict__ bk,
                             const float* __restrict__ bv, float* __restrict__ out) {
    int i = blockIdx.x * 256 + threadIdx.x;
    int l = i / 3072, j = i % 3072;
    float v = (j < 1024) ? bq[l * 1024 + j]
            : (j < 2048) ? bk[l * 1024 + j - 1024]
                         : bv[l * 1024 + j - 2048];
    out[i] = v;
}

// ---------------------------------------------------------------------------
// Embedding / LayerNorm
// ---------------------------------------------------------------------------
__global__ void embed_kernel(const int* __restrict__ x, const float* __restrict__ tok,
                             const float* __restrict__ pos, float* __restrict__ h) {
    int i = blockIdx.x * 256 + threadIdx.x;
    int row = i >> 10, e = i & 1023;
    int tkn = x[row];
    int t = row & (T_ - 1);
    h[i] = tok[(size_t)tkn * E_ + e] + pos[(size_t)t * E_ + e];
}

__global__ __launch_bounds__(256) void ln_kernel(const float* __restrict__ in,
                                                 const float* __restrict__ gam,
                                                 const float* __restrict__ bet,
                                                 __half* __restrict__ outh) {
    int row = blockIdx.x;
    const float* xr = in + (size_t)row * E_;
    float v0[4];
    float s = 0.f;
#pragma unroll
    for (int i = 0; i < 4; i++) { v0[i] = xr[threadIdx.x + 256 * i]; s += v0[i]; }

    __shared__ float sh[8];
    float t = s;
#pragma unroll
    for (int o = 16; o > 0; o >>= 1) t += __shfl_xor_sync(0xffffffffu, t, o);
    if ((threadIdx.x & 31) == 0) sh[threadIdx.x >> 5] = t;
    __syncthreads();
    float tot = 0.f;
#pragma unroll
    for (int i = 0; i < 8; i++) tot += sh[i];
    float mean = tot * (1.0f / E_);

    float vs = 0.f;
#pragma unroll
    for (int i = 0; i < 4; i++) { float d = v0[i] - mean; vs += d * d; }
    __syncthreads();
    t = vs;
#pragma unroll
    for (int o = 16; o > 0; o >>= 1) t += __shfl_xor_sync(0xffffffffu, t, o);
    if ((threadIdx.x & 31) == 0) sh[threadIdx.x >> 5] = t;
    __syncthreads();
    tot = 0.f;
#pragma unroll
    for (int i = 0; i < 8; i++) tot += sh[i];
    float rstd = rsqrtf(tot * (1.0f / E_) + 1e-5f);

#pragma unroll
    for (int i = 0; i < 4; i++) {
        int e = threadIdx.x + 256 * i;
        float y = (v0[i] - mean) * rstd * gam[e] + bet[e];
        outh[(size_t)row * E_ + e] = __float2half(y);
    }
}

// ---------------------------------------------------------------------------
// Host orchestration
// ---------------------------------------------------------------------------
extern "C" void kernel_launch(void* const* d_in, const int* in_sizes, int n_in,
                              void* d_out, int out_size) {
    const int*   x    = (const int*)  d_in[0];
    const float* tok  = (const float*)d_in[1];
    const float* pos  = (const float*)d_in[2];
    const float* Wq   = (const float*)d_in[3];
    const float* bq   = (const float*)d_in[4];
    const float* Wk   = (const float*)d_in[5];
    const float* bk   = (const float*)d_in[6];
    const float* Wv   = (const float*)d_in[7];
    const float* bv   = (const float*)d_in[8];
    const float* Wo   = (const float*)d_in[9];
    const float* bo   = (const float*)d_in[10];
    const float* ln1g = (const float*)d_in[11];
    const float* ln1b = (const float*)d_in[12];
    const float* W1   = (const float*)d_in[13];
    const float* b1   = (const float*)d_in[14];
    const float* W2   = (const float*)d_in[15];
    const float* b2   = (const float*)d_in[16];
    const float* ln2g = (const float*)d_in[17];
    const float* ln2b = (const float*)d_in[18];
    const float* lnfg = (const float*)d_in[19];
    const float* lnfb = (const float*)d_in[20];
    const float* Wout = (const float*)d_in[21];
    const float* bout = (const float*)d_in[22];
    float* out = (float*)d_out;

    float *h, *bqkv;
    __half *qkvh, *xn, *o, *mlp;
    __half *qkvT, *woT, *w1T, *w2T, *wouC;
    cudaGetSymbolAddress((void**)&h,    g_h);
    cudaGetSymbolAddress((void**)&qkvh, g_qkv);
    cudaGetSymbolAddress((void**)&bqkv, g_bqkv);
    cudaGetSymbolAddress((void**)&xn,   g_xn);
    cudaGetSymbolAddress((void**)&o,    g_o);
    cudaGetSymbolAddress((void**)&mlp,  g_mlp);
    cudaGetSymbolAddress((void**)&qkvT, g_qkvT);
    cudaGetSymbolAddress((void**)&woT,  g_woT);
    cudaGetSymbolAddress((void**)&w1T,  g_w1T);
    cudaGetSymbolAddress((void**)&w2T,  g_w2T);
    cudaGetSymbolAddress((void**)&wouC, g_woutC);

    cudaFuncSetAttribute((const void*)btgemm_kernel<1>, cudaFuncAttributeMaxDynamicSharedMemorySize, BT_SMEM);
    cudaFuncSetAttribute((const void*)btgemm_kernel<2>, cudaFuncAttributeMaxDynamicSharedMemorySize, BT_SMEM);
    cudaFuncSetAttribute((const void*)wtgemm_kernel,    cudaFuncAttributeMaxDynamicSharedMemorySize, WT_SMEM);
    cudaFuncSetAttribute((const void*)tgemm_res_kernel, cudaFuncAttributeMaxDynamicSharedMemorySize, SMEM_G);

    const size_t EE = (size_t)E_ * E_, EF = (size_t)E_ * F_;
    dim3 tb(32, 8);

    embed_kernel<<<(M_ * E_) / 256, 256>>>(x, tok, pos, h);                          // 0
    wconvT_qkv_kernel<<<dim3(32, 16, 3 * L_), tb>>>(Wq, Wk, Wv, qkvT);               // 1
    bpack_kernel<<<(L_ * 3 * E_) / 256, 256>>>(bq, bk, bv, bqkv);                    // 2
    ln_kernel<<<M_, 256>>>(h, ln1g, ln1b, xn);                                       // 3
    btgemm_kernel<2><<<dim3(M_ / 128, 12), 512, BT_SMEM>>>(                          // 4
        xn, qkvT, bqkv, nullptr, qkvh, 3 * E_, E_);
    wconvT_kernel<<<dim3(32, 16, L_), tb>>>(Wo, woT, E_, E_, EE, EE);                // 5
    wconvT_kernel<<<dim3(128, 16, L_), tb>>>(W1, w1T, E_, F_, EF, EF);               // 6
    wconvT_kernel<<<dim3(32, 64, L_), tb>>>(W2, w2T, F_, E_, EF, EF);                // 7
    wcvt_kernel<<<32000, 256>>>(Wout, wouC);                                         // 8

    for (int l = 0; l < L_; l++) {
        if (l > 0) {
            ln_kernel<<<M_, 256>>>(h, ln1g + l * E_, ln1b + l * E_, xn);
            btgemm_kernel<2><<<dim3(M_ / 128, 12), 512, BT_SMEM>>>(
                xn, qkvT + l * 3 * EE, bqkv + l * 3 * E_, nullptr, qkvh, 3 * E_, E_);
        }
        fattn_kernel<<<B_ * H_ * (T_ / 64), 128>>>(qkvh, o);
        tgemm_res_kernel<<<dim3(M_ / 128, 8), 256, SMEM_G>>>(
            o, woT + l * EE, bo + l * E_, h, h, E_, E_);
        ln_kernel<<<M_, 256>>>(h, ln2g + l * E_, ln2b + l * E_, xn);
        btgemm_kernel<1><<<dim3(M_ / 128, F_ / 256), 512, BT_SMEM>>>(
            xn, w1T + l * EF, b1 + l * F_, nullptr, mlp, F_, E_);
        tgemm_res_kernel<<<dim3(M_ / 128, 8), 256, SMEM_G>>>(
            mlp, w2T + l * EF, b2 + l * E_, h, h, E_, F_);
    }

    ln_kernel<<<M_, 256>>>(h, lnfg, lnfb, xn);
    wtgemm_kernel<<<dim3(M_ / 128, V_ / 256), 512, WT_SMEM>>>(
        xn, wouC, bout, out, V_, E_);
}

// round 13
// speedup vs baseline: 1.5150x; 1.0518x over previous
#include <cuda_runtime.h>
#include <cuda_fp16.h>
#include <math.h>
#include <stdint.h>

// Problem dims
#define V_ 32000
#define E_ 1024
#define H_ 16
#define F_ 4096
#define L_ 4
#define T_ 2048
#define B_ 2
#define D_ 64
#define M_ (B_*T_)   // 4096

// ---------------------------------------------------------------------------
// Scratch (device globals; allocation APIs are forbidden)
// ---------------------------------------------------------------------------
__device__ float g_h  [M_*E_];
__device__ __half g_qkv[M_*3*E_];
__device__ float g_bqkv[L_*3*E_];
__device__ __half g_xn [M_*E_];
__device__ __half g_o  [M_*E_];
__device__ __half g_mlp[M_*F_];
__device__ __half g_qkvT[L_*3*E_*E_];
__device__ __half g_woT [L_*E_*E_];
__device__ __half g_w1T [L_*F_*E_];
__device__ __half g_w2T [L_*E_*F_];
__device__ __half g_woutT[(size_t)V_*E_];

// ---------------------------------------------------------------------------
// PTX helpers
// ---------------------------------------------------------------------------
__device__ __forceinline__ uint32_t smem_u32(const void* p) {
    uint32_t a;
    asm("{ .reg .u64 t; cvta.to.shared.u64 t, %1; cvt.u32.u64 %0, t; }" : "=r"(a) : "l"(p));
    return a;
}
static __device__ __forceinline__ void cpa16(uint32_t s, const void* g) {
    asm volatile("cp.async.cg.shared.global [%0], [%1], 16;" :: "r"(s), "l"(g) : "memory");
}
#define CP_COMMIT() asm volatile("cp.async.commit_group;" ::: "memory")
#define CP_WAIT0()  asm volatile("cp.async.wait_group 0;" ::: "memory")
#define CP_WAIT1()  asm volatile("cp.async.wait_group 1;" ::: "memory")

struct Frag4 { uint32_t x, y, z, w; };

static __device__ __forceinline__ Frag4 ldsm_x4(uint32_t addr) {
    Frag4 r;
    asm volatile("ldmatrix.sync.aligned.m8n8.x4.shared.b16 {%0,%1,%2,%3}, [%4];"
                 : "=r"(r.x), "=r"(r.y), "=r"(r.z), "=r"(r.w) : "r"(addr));
    return r;
}
static __device__ __forceinline__ Frag4 ldsm_x4_t(uint32_t addr) {
    Frag4 r;
    asm volatile("ldmatrix.sync.aligned.m8n8.x4.trans.shared.b16 {%0,%1,%2,%3}, [%4];"
                 : "=r"(r.x), "=r"(r.y), "=r"(r.z), "=r"(r.w) : "r"(addr));
    return r;
}

static __device__ __forceinline__ void mma_f16(float* c, const Frag4& a,
                                               uint32_t b0, uint32_t b1) {
    asm volatile(
        "mma.sync.aligned.m16n8k16.row.col.f32.f16.f16.f32 "
        "{%0,%1,%2,%3}, {%4,%5,%6,%7}, {%8,%9}, {%0,%1,%2,%3};"
        : "+f"(c[0]), "+f"(c[1]), "+f"(c[2]), "+f"(c[3])
        : "r"(a.x), "r"(a.y), "r"(a.z), "r"(a.w), "r"(b0), "r"(b1));
}
static __device__ __forceinline__ void mma4(float* c, uint32_t a0, uint32_t a1,
                                            uint32_t a2, uint32_t a3,
                                            uint32_t b0, uint32_t b1) {
    asm volatile(
        "mma.sync.aligned.m16n8k16.row.col.f32.f16.f16.f32 "
        "{%0,%1,%2,%3}, {%4,%5,%6,%7}, {%8,%9}, {%0,%1,%2,%3};"
        : "+f"(c[0]), "+f"(c[1]), "+f"(c[2]), "+f"(c[3])
        : "r"(a0), "r"(a1), "r"(a2), "r"(a3), "r"(b0), "r"(b1));
}

static __device__ __forceinline__ float ex2f(float x) {
    float y;
    asm("ex2.approx.ftz.f32 %0, %1;" : "=f"(y) : "f"(x));
    return y;
}

__device__ __forceinline__ float gelu_exact(float x) {
    return 0.5f * x * (1.0f + erff(x * 0.70710678118654752f));
}

// ===========================================================================
// BIG-TILE GEMM (QKV, MLP1, Wout): CTA 128x256, 512 threads (16 warps, 2x8),
// warptile 64x32, BK=64, 3-stage. EPI: 0 = fp32+bias ; 1 = gelu->fp16 ; 2 = fp16
// ===========================================================================
#define ROWB     144
#define BT_TA    (128 * ROWB)               // 18432
#define BT_TB    (256 * ROWB)               // 36864
#define BT_STG   (BT_TA + BT_TB)            // 55296
#define BT_SMEM  (3 * BT_STG)               // 165888

static __device__ __forceinline__ void bt_load(
    uint32_t st, const __half* __restrict__ A, const __half* __restrict__ Bm,
    int bm, int bn, int k0, int K, int tid)
{
#pragma unroll
    for (int i = 0; i < 2; i++) {
        int c = tid + (i << 9);
        int r = c >> 3, q = c & 7;
        cpa16(st + (uint32_t)(r * ROWB + q * 16),
              A + (size_t)(bm + r) * K + k0 + (q << 3));
    }
#pragma unroll
    for (int i = 0; i < 4; i++) {
        int c = tid + (i << 9);
        int r = c >> 3, q = c & 7;
        cpa16(st + BT_TA + (uint32_t)(r * ROWB + q * 16),
              Bm + (size_t)(bn + r) * K + k0 + (q << 3));
    }
}

template<int EPI>
__global__ __launch_bounds__(512, 1) void btgemm_kernel(
    const __half* __restrict__ A, const __half* __restrict__ Bm,
    const float* __restrict__ bias,
    float* __restrict__ Cf, __half* __restrict__ Ch,
    int N, int K)
{
    extern __shared__ __align__(1024) unsigned char smem[];
    uint32_t sb = smem_u32(smem);
    int tid = threadIdx.x, wid = tid >> 5, lane = tid & 31;
    int bm = blockIdx.x * 128, bn = blockIdx.y * 256;
    int wm = wid & 1, wn = wid >> 1;

    uint32_t a_lane = (uint32_t)((wm * 64 + (lane & 15)) * ROWB + ((lane >> 4) << 4));
    uint32_t b_lane = (uint32_t)(BT_TA + ((lane & 7) + ((lane >> 4) << 3)) * ROWB
                                 + (((lane >> 3) & 1) << 4));

    float acc[4][4][4];
#pragma unroll
    for (int i = 0; i < 4; i++)
#pragma unroll
        for (int j = 0; j < 4; j++)
#pragma unroll
            for (int e = 0; e < 4; e++) acc[i][j][e] = 0.f;

    int nk = K >> 6;
    bt_load(sb,          A, Bm, bm, bn, 0,  K, tid); CP_COMMIT();
    bt_load(sb + BT_STG, A, Bm, bm, bn, 64, K, tid); CP_COMMIT();

    uint32_t stg[3] = {sb, sb + BT_STG, sb + 2 * BT_STG};
    int cur = 0, nxt = 2;
    for (int kt = 0; kt < nk; kt++) {
        CP_WAIT1();
        __syncthreads();

        int kf = kt + 2;
        if (kf < nk)
            bt_load(stg[nxt], A, Bm, bm, bn, kf << 6, K, tid);
        CP_COMMIT();

        uint32_t st = stg[cur];
        cur = (cur + 1) % 3; nxt = (nxt + 1) % 3;
#pragma unroll
        for (int ks = 0; ks < 4; ks++) {
            uint32_t kb = ks << 5;
            Frag4 ah[4];
#pragma unroll
            for (int mt = 0; mt < 4; mt++)
                ah[mt] = ldsm_x4(st + a_lane + mt * (16 * ROWB) + kb);
#pragma unroll
            for (int np = 0; np < 2; np++) {
                Frag4 bf = ldsm_x4(st + b_lane + (wn * 32 + np * 16) * ROWB + kb);
#pragma unroll
                for (int mt = 0; mt < 4; mt++) {
                    mma_f16(acc[mt][np * 2],     ah[mt], bf.x, bf.y);
                    mma_f16(acc[mt][np * 2 + 1], ah[mt], bf.z, bf.w);
                }
            }
        }
    }
    __syncthreads();

    int row_in = lane >> 2;
    int col2   = (lane & 3) << 1;
#pragma unroll
    for (int mt = 0; mt < 4; mt++) {
#pragma unroll
        for (int nt = 0; nt < 4; nt++) {
            int col = bn + wn * 32 + nt * 8 + col2;
            float bx = bias[col], by = bias[col + 1];
#pragma unroll
            for (int half = 0; half < 2; half++) {
                int row = bm + wm * 64 + mt * 16 + row_in + half * 8;
                size_t off = (size_t)row * N + col;
                float v0 = acc[mt][nt][half * 2 + 0] + bx;
                float v1 = acc[mt][nt][half * 2 + 1] + by;
                if (EPI == 0) {
                    *(float2*)&Cf[off] = make_float2(v0, v1);
                } else if (EPI == 1) {
                    __half2 hh;
                    hh.x = __float2half(gelu_exact(v0));
                    hh.y = __float2half(gelu_exact(v1));
                    *(__half2*)&Ch[off] = hh;
                } else {
                    __half2 hh;
                    hh.x = __float2half(v0);
                    hh.y = __float2half(v1);
                    *(__half2*)&Ch[off] = hh;
                }
            }
        }
    }
}

// ===========================================================================
// SMALL-TILE GEMM (N=1024): CTA 128x128, BK=64, 3-stage, 2 CTAs/SM.
// fp32 out: +bias +residual
// ===========================================================================
#define TILE_A  (128 * ROWB)
#define STAGE_B (2 * TILE_A)
#define SMEM_G  (3 * STAGE_B)         // 110592

static __device__ __forceinline__ void load_stage(
    uint32_t st, const __half* __restrict__ A, const __half* __restrict__ Bm,
    int bm, int bn, int k0, int K, int tid)
{
#pragma unroll
    for (int i = 0; i < 4; i++) {
        int c = tid + (i << 8);
        int r = c >> 3, q = c & 7;
        uint32_t so = (uint32_t)(r * ROWB + q * 16);
        cpa16(st + so, A + (size_t)(bm + r) * K + k0 + (q << 3));
    }
#pragma unroll
    for (int i = 0; i < 4; i++) {
        int c = tid + (i << 8);
        int r = c >> 3, q = c & 7;
        uint32_t so = (uint32_t)(r * ROWB + q * 16);
        cpa16(st + TILE_A + so, Bm + (size_t)(bn + r) * K + k0 + (q << 3));
    }
}

__global__ __launch_bounds__(256, 2) void tgemm_res_kernel(
    const __half* __restrict__ A, const __half* __restrict__ Bm,
    const float* __restrict__ bias, const float* __restrict__ res,
    float* __restrict__ Cf, int N, int K)
{
    extern __shared__ __align__(1024) unsigned char smem[];
    uint32_t sb = smem_u32(smem);
    int tid = threadIdx.x, wid = tid >> 5, lane = tid & 31;
    int bm = blockIdx.x * 128, bn = blockIdx.y * 128;
    int wm = wid & 1, wn = wid >> 1;

    uint32_t a_lane = (uint32_t)((wm * 64 + (lane & 15)) * ROWB + ((lane >> 4) << 4));
    uint32_t b_lane = (uint32_t)(TILE_A + ((lane & 7) + ((lane >> 4) << 3)) * ROWB
                                 + (((lane >> 3) & 1) << 4));

    float acc[4][4][4];
#pragma unroll
    for (int i = 0; i < 4; i++)
#pragma unroll
        for (int j = 0; j < 4; j++)
#pragma unroll
            for (int e = 0; e < 4; e++) acc[i][j][e] = 0.f;

    int nk = K >> 6;
    load_stage(sb,           A, Bm, bm, bn, 0,  K, tid); CP_COMMIT();
    load_stage(sb + STAGE_B, A, Bm, bm, bn, 64, K, tid); CP_COMMIT();

    uint32_t stg[3] = {sb, sb + STAGE_B, sb + 2 * STAGE_B};
    int cur = 0, nxt = 2;
    for (int kt = 0; kt < nk; kt++) {
        CP_WAIT1();
        __syncthreads();

        int kf = kt + 2;
        if (kf < nk)
            load_stage(stg[nxt], A, Bm, bm, bn, kf << 6, K, tid);
        CP_COMMIT();

        uint32_t st = stg[cur];
        cur = (cur + 1) % 3; nxt = (nxt + 1) % 3;
#pragma unroll
        for (int ks = 0; ks < 4; ks++) {
            uint32_t kb = ks << 5;
            Frag4 ah[4];
#pragma unroll
            for (int mt = 0; mt < 4; mt++)
                ah[mt] = ldsm_x4(st + a_lane + mt * (16 * ROWB) + kb);
#pragma unroll
            for (int np = 0; np < 2; np++) {
                Frag4 bf = ldsm_x4(st + b_lane + (wn * 32 + np * 16) * ROWB + kb);
#pragma unroll
                for (int mt = 0; mt < 4; mt++) {
                    mma_f16(acc[mt][np * 2],     ah[mt], bf.x, bf.y);
                    mma_f16(acc[mt][np * 2 + 1], ah[mt], bf.z, bf.w);
                }
            }
        }
    }
    __syncthreads();

    int row_in = lane >> 2;
    int col2   = (lane & 3) << 1;
#pragma unroll
    for (int mt = 0; mt < 4; mt++) {
#pragma unroll
        for (int nt = 0; nt < 4; nt++) {
            int col = bn + wn * 32 + nt * 8 + col2;
            float bx = bias[col], by = bias[col + 1];
#pragma unroll
            for (int half = 0; half < 2; half++) {
                int row = bm + wm * 64 + mt * 16 + row_in + half * 8;
                size_t off = (size_t)row * N + col;
                float2 rv = *(const float2*)&res[off];
                *(float2*)&Cf[off] = make_float2(acc[mt][nt][half * 2 + 0] + bx + rv.x,
                                                 acc[mt][nt][half * 2 + 1] + by + rv.y);
            }
        }
    }
}

// ===========================================================================
// Flash attention (HMMA fp16, fp32 softmax). qkv fp16 [M,3E] -> oh fp16 [M,E]
// ===========================================================================
__global__ __launch_bounds__(128) void fattn_kernel(const __half* __restrict__ qkv,
                                                    __half* __restrict__ oh) {
    __shared__ __half Qs[64 * 72];
    __shared__ __half Ks[2][64 * 72];
    __shared__ __half Vs[2][64 * 72];

    int tid = threadIdx.x, wid = tid >> 5, lane = tid & 31;
    int qt = 31 - (blockIdx.x & 31);         // long blocks first
    int bh = blockIdx.x >> 5;
    int b  = bh >> 4, hh = bh & 15;
    int q0 = qt * 64;

    for (int i = tid; i < 512; i += 128) {
        int r = i >> 3, c8 = (i & 7) << 3;
        *(uint4*)&Qs[r * 72 + c8] =
            *(const uint4*)(qkv + (size_t)(b * T_ + q0 + r) * 3072 + hh * 64 + c8);
    }
    __syncthreads();

    uint32_t qbase = smem_u32(Qs);
    Frag4 qf[4];
    {
        int rr = wid * 16 + (lane & 15);
#pragma unroll
        for (int kd = 0; kd < 4; kd++)
            qf[kd] = ldsm_x4(qbase + (uint32_t)(rr * 144 + kd * 32 + ((lane >> 4) << 4)));
    }

    uint32_t ksb[2] = {smem_u32(Ks[0]), smem_u32(Ks[1])};
    uint32_t vsb[2] = {smem_u32(Vs[0]), smem_u32(Vs[1])};

    float o[8][4];
#pragma unroll
    for (int t = 0; t < 8; t++)
#pragma unroll
        for (int e = 0; e < 4; e++) o[t][e] = 0.f;
    float m0 = -1e30f, m1 = -1e30f, l0 = 0.f, l1 = 0.f;

    const float SC = 0.18033688011f;   // 0.125 * log2(e)
    int ntiles = qt + 1;

    for (int i = tid; i < 512; i += 128) {
        int r = i >> 3, c8 = (i & 7) << 3;
        size_t base = (size_t)(b * T_ + r) * 3072 + hh * 64 + c8;
        cpa16(ksb[0] + (uint32_t)(r * 144 + c8 * 2), qkv + base + 1024);
        cpa16(vsb[0] + (uint32_t)(r * 144 + c8 * 2), qkv + base + 2048);
    }
    CP_COMMIT();

    for (int t = 0; t < ntiles; t++) {
        if (t + 1 < ntiles) {
            int kb = (t + 1) * 64;
            int buf = (t + 1) & 1;
            for (int i = tid; i < 512; i += 128) {
                int r = i >> 3, c8 = (i & 7) << 3;
                size_t base = (size_t)(b * T_ + kb + r) * 3072 + hh * 64 + c8;
                cpa16(ksb[buf] + (uint32_t)(r * 144 + c8 * 2), qkv + base + 1024);
                cpa16(vsb[buf] + (uint32_t)(r * 144 + c8 * 2), qkv + base + 2048);
            }
            CP_COMMIT();
            CP_WAIT1();
        } else {
            CP_WAIT0();
        }
        __syncthreads();

        int buf = t & 1;
        uint32_t kb_s = ksb[buf], vb_s = vsb[buf];

        float s[8][4];
#pragma unroll
        for (int j = 0; j < 8; j++)
#pragma unroll
            for (int e = 0; e < 4; e++) s[j][e] = 0.f;
#pragma unroll
        for (int kd = 0; kd < 4; kd++) {
#pragma unroll
            for (int np = 0; np < 4; np++) {
                Frag4 bf = ldsm_x4(kb_s + (uint32_t)((np * 16 + (lane & 7) + ((lane >> 4) << 3)) * 144
                                                     + kd * 32 + (((lane >> 3) & 1) << 4)));
                mma_f16(s[np * 2],     qf[kd], bf.x, bf.y);
                mma_f16(s[np * 2 + 1], qf[kd], bf.z, bf.w);
            }
        }

#pragma unroll
        for (int j = 0; j < 8; j++)
#pragma unroll
            for (int e = 0; e < 4; e++) s[j][e] *= SC;

        if (t == qt) {
            int lr0 = wid * 16 + (lane >> 2);
#pragma unroll
            for (int j = 0; j < 8; j++) {
                int c = 8 * j + 2 * (lane & 3);
                if (c     > lr0)     s[j][0] = -1e30f;
                if (c + 1 > lr0)     s[j][1] = -1e30f;
                if (c     > lr0 + 8) s[j][2] = -1e30f;
                if (c + 1 > lr0 + 8) s[j][3] = -1e30f;
            }
        }

        float mr0 = -1e30f, mr1 = -1e30f;
#pragma unroll
        for (int j = 0; j < 8; j++) {
            mr0 = fmaxf(mr0, fmaxf(s[j][0], s[j][1]));
            mr1 = fmaxf(mr1, fmaxf(s[j][2], s[j][3]));
        }
        mr0 = fmaxf(mr0, __shfl_xor_sync(0xffffffffu, mr0, 1));
        mr0 = fmaxf(mr0, __shfl_xor_sync(0xffffffffu, mr0, 2));
        mr1 = fmaxf(mr1, __shfl_xor_sync(0xffffffffu, mr1, 1));
        mr1 = fmaxf(mr1, __shfl_xor_sync(0xffffffffu, mr1, 2));

        float nm0 = fmaxf(m0, mr0), nm1 = fmaxf(m1, mr1);
        float c0 = ex2f(m0 - nm0), c1 = ex2f(m1 - nm1);
        m0 = nm0; m1 = nm1;
        l0 *= c0; l1 *= c1;

        uint32_t pf[8][2];
        float ps0 = 0.f, ps1 = 0.f;
#pragma unroll
        for (int j = 0; j < 8; j++) {
            float p0 = ex2f(s[j][0] - m0), p1 = ex2f(s[j][1] - m0);
            float p2 = ex2f(s[j][2] - m1), p3 = ex2f(s[j][3] - m1);
            ps0 += p0 + p1; ps1 += p2 + p3;
            __half2 h01 = __floats2half2_rn(p0, p1);
            __half2 h23 = __floats2half2_rn(p2, p3);
            pf[j][0] = *(uint32_t*)&h01;
            pf[j][1] = *(uint32_t*)&h23;
        }
        l0 += ps0; l1 += ps1;

#pragma unroll
        for (int tt = 0; tt < 8; tt++) {
            o[tt][0] *= c0; o[tt][1] *= c0;
            o[tt][2] *= c1; o[tt][3] *= c1;
        }

#pragma unroll
        for (int j = 0; j < 4; j++) {
            uint32_t a0 = pf[2 * j][0],     a1 = pf[2 * j][1];
            uint32_t a2 = pf[2 * j + 1][0], a3 = pf[2 * j + 1][1];
#pragma unroll
            for (int t2 = 0; t2 < 4; t2++) {
                Frag4 vf = ldsm_x4_t(vb_s + (uint32_t)((j * 16 + (lane & 7) + (((lane >> 3) & 1) << 3)) * 144
                                                       + t2 * 32 + ((lane >> 4) << 4)));
                mma4(o[2 * t2],     a0, a1, a2, a3, vf.x, vf.y);
                mma4(o[2 * t2 + 1], a0, a1, a2, a3, vf.z, vf.w);
            }
        }
        __syncthreads();
    }

    l0 += __shfl_xor_sync(0xffffffffu, l0, 1);
    l0 += __shfl_xor_sync(0xffffffffu, l0, 2);
    l1 += __shfl_xor_sync(0xffffffffu, l1, 1);
    l1 += __shfl_xor_sync(0xffffffffu, l1, 2);
    float li0 = 1.0f / l0, li1 = 1.0f / l1;

    int r0g = q0 + wid * 16 + (lane >> 2);
    int dbase = hh * 64 + 2 * (lane & 3);
#pragma unroll
    for (int tt = 0; tt < 8; tt++) {
        __half2 h01 = __floats2half2_rn(o[tt][0] * li0, o[tt][1] * li0);
        __half2 h23 = __floats2half2_rn(o[tt][2] * li1, o[tt][3] * li1);
        *(__half2*)&oh[(size_t)(b * T_ + r0g) * E_ + dbase + tt * 8]       = h01;
        *(__half2*)&oh[(size_t)(b * T_ + r0g + 8) * E_ + dbase + tt * 8]   = h23;
    }
}

// ---------------------------------------------------------------------------
// Weight transpose + fp16 (128B-coalesced writes): W[K,N] -> T[N,K]
// tile = 32 n x 64 k, block (32,8)
// ---------------------------------------------------------------------------
__global__ void wconvT_kernel(const float* __restrict__ W,
                              __half* __restrict__ Th,
                              int K, int N, size_t inLs, size_t outLs)
{
    __shared__ float s[32][65];
    const float* Wl = W + blockIdx.z * inLs;
    Th += blockIdx.z * outLs;
    int n0 = blockIdx.x * 32, k0 = blockIdx.y * 64;
    int tx = threadIdx.x, ty = threadIdx.y;
    int tid = ty * 32 + tx;
#pragma unroll
    for (int i = 0; i < 8; i++) {
        int e = tid + 256 * i;
        int n = e & 31, k = e >> 5;
        s[n][k] = Wl[(size_t)(k0 + k) * N + n0 + n];
    }
    __syncthreads();
#pragma unroll
    for (int i = 0; i < 4; i++) {
        int n = ty + 8 * i;
        __half2 h = __floats2half2_rn(s[n][2 * tx], s[n][2 * tx + 1]);
        *(__half2*)&Th[(size_t)(n0 + n) * K + k0 + 2 * tx] = h;
    }
}

// QKV variant: grid.z = l*3 + which
__global__ void wconvT_qkv_kernel(const float* __restrict__ Wq,
                                  const float* __restrict__ Wk,
                                  const float* __restrict__ Wv,
                                  __half* __restrict__ Th)
{
    __shared__ float s[32][65];
    int l = blockIdx.z / 3, which = blockIdx.z % 3;
    const size_t EE = (size_t)E_ * E_;
    const float* Wl = (which == 0 ? Wq : which == 1 ? Wk : Wv) + l * EE;
    Th += (size_t)l * 3 * EE + (size_t)which * EE;
    int n0 = blockIdx.x * 32, k0 = blockIdx.y * 64;
    int tx = threadIdx.x, ty = threadIdx.y;
    int tid = ty * 32 + tx;
#pragma unroll
    for (int i = 0; i < 8; i++) {
        int e = tid + 256 * i;
        int n = e & 31, k = e >> 5;
        s[n][k] = Wl[(size_t)(k0 + k) * E_ + n0 + n];
    }
    __syncthreads();
#pragma unroll
    for (int i = 0; i < 4; i++) {
        int n = ty + 8 * i;
        __half2 h = __floats2half2_rn(s[n][2 * tx], s[n][2 * tx + 1]);
        *(__half2*)&Th[(size_t)(n0 + n) * E_ + k0 + 2 * tx] = h;
    }
}

// Pack per-layer QKV biases into [L, 3E]
__global__ void bpack_kernel(const float* __restrict__ bq, const float* __restrict__ bk,
                             const float* __restrict__ bv, float* __restrict__ out) {
    int i = blockIdx.x * 256 + threadIdx.x;
    int l = i / 3072, j = i % 3072;
    float v = (j < 1024) ? bq[l * 1024 + j]
            : (j < 2048) ? bk[l * 1024 + j - 1024]
                         : bv[l * 1024 + j - 2048];
    out[i] = v;
}

// ---------------------------------------------------------------------------
// Embedding / LayerNorm (float4-vectorized)
// ---------------------------------------------------------------------------
__global__ void embed_kernel(const int* __restrict__ x, const float* __restrict__ tok,
                             const float* __restrict__ pos, float* __restrict__ h) {
    int i = blockIdx.x * 256 + threadIdx.x;
    int row = i >> 8, e4 = (i & 255) << 2;          // 256 threads cover one row (1024 f32)
    int tkn = x[row];
    int t = row & (T_ - 1);
    float4 a = *(const float4*)(tok + (size_t)tkn * E_ + e4);
    float4 p = *(const float4*)(pos + (size_t)t * E_ + e4);
    *(float4*)(h + (size_t)row * E_ + e4) =
        make_float4(a.x + p.x, a.y + p.y, a.z + p.z, a.w + p.w);
}

__global__ __launch_bounds__(256) void ln_kernel(const float* __restrict__ in,
                                                 const float* __restrict__ gam,
                                                 const float* __restrict__ bet,
                                                 __half* __restrict__ outh) {
    int row = blockIdx.x;
    int e = threadIdx.x << 2;
    float4 v = *(const float4*)(in + (size_t)row * E_ + e);
    float s = v.x + v.y + v.z + v.w;

    __shared__ float sh[8];
    float t = s;
#pragma unroll
    for (int o = 16; o > 0; o >>= 1) t += __shfl_xor_sync(0xffffffffu, t, o);
    if ((threadIdx.x & 31) == 0) sh[threadIdx.x >> 5] = t;
    __syncthreads();
    float tot = 0.f;
#pragma unroll
    for (int i = 0; i < 8; i++) tot += sh[i];
    float mean = tot * (1.0f / E_);

    float dx = v.x - mean, dy = v.y - mean, dz = v.z - mean, dw = v.w - mean;
    float vs = dx * dx + dy * dy + dz * dz + dw * dw;
    __syncthreads();
    t = vs;
#pragma unroll
    for (int o = 16; o > 0; o >>= 1) t += __shfl_xor_sync(0xffffffffu, t, o);
    if ((threadIdx.x & 31) == 0) sh[threadIdx.x >> 5] = t;
    __syncthreads();
    tot = 0.f;
#pragma unroll
    for (int i = 0; i < 8; i++) tot += sh[i];
    float rstd = rsqrtf(tot * (1.0f / E_) + 1e-5f);

    float4 g = *(const float4*)(gam + e);
    float4 bb = *(const float4*)(bet + e);
    __half2 h0 = __floats2half2_rn(dx * rstd * g.x + bb.x, dy * rstd * g.y + bb.y);
    __half2 h1 = __floats2half2_rn(dz * rstd * g.z + bb.z, dw * rstd * g.w + bb.w);
    *(__half2*)&outh[(size_t)row * E_ + e]     = h0;
    *(__half2*)&outh[(size_t)row * E_ + e + 2] = h1;
}

// ---------------------------------------------------------------------------
// Host orchestration
// ---------------------------------------------------------------------------
extern "C" void kernel_launch(void* const* d_in, const int* in_sizes, int n_in,
                              void* d_out, int out_size) {
    const int*   x    = (const int*)  d_in[0];
    const float* tok  = (const float*)d_in[1];
    const float* pos  = (const float*)d_in[2];
    const float* Wq   = (const float*)d_in[3];
    const float* bq   = (const float*)d_in[4];
    const float* Wk   = (const float*)d_in[5];
    const float* bk   = (const float*)d_in[6];
    const float* Wv   = (const float*)d_in[7];
    const float* bv   = (const float*)d_in[8];
    const float* Wo   = (const float*)d_in[9];
    const float* bo   = (const float*)d_in[10];
    const float* ln1g = (const float*)d_in[11];
    const float* ln1b = (const float*)d_in[12];
    const float* W1   = (const float*)d_in[13];
    const float* b1   = (const float*)d_in[14];
    const float* W2   = (const float*)d_in[15];
    const float* b2   = (const float*)d_in[16];
    const float* ln2g = (const float*)d_in[17];
    const float* ln2b = (const float*)d_in[18];
    const float* lnfg = (const float*)d_in[19];
    const float* lnfb = (const float*)d_in[20];
    const float* Wout = (const float*)d_in[21];
    const float* bout = (const float*)d_in[22];
    float* out = (float*)d_out;

    float *h, *bqkv;
    __half *qkvh, *xn, *o, *mlp;
    __half *qkvT, *woT, *w1T, *w2T, *wouT;
    cudaGetSymbolAddress((void**)&h,    g_h);
    cudaGetSymbolAddress((void**)&qkvh, g_qkv);
    cudaGetSymbolAddress((void**)&bqkv, g_bqkv);
    cudaGetSymbolAddress((void**)&xn,   g_xn);
    cudaGetSymbolAddress((void**)&o,    g_o);
    cudaGetSymbolAddress((void**)&mlp,  g_mlp);
    cudaGetSymbolAddress((void**)&qkvT, g_qkvT);
    cudaGetSymbolAddress((void**)&woT,  g_woT);
    cudaGetSymbolAddress((void**)&w1T,  g_w1T);
    cudaGetSymbolAddress((void**)&w2T,  g_w2T);
    cudaGetSymbolAddress((void**)&wouT, g_woutT);

    cudaFuncSetAttribute((const void*)btgemm_kernel<0>, cudaFuncAttributeMaxDynamicSharedMemorySize, BT_SMEM);
    cudaFuncSetAttribute((const void*)btgemm_kernel<1>, cudaFuncAttributeMaxDynamicSharedMemorySize, BT_SMEM);
    cudaFuncSetAttribute((const void*)btgemm_kernel<2>, cudaFuncAttributeMaxDynamicSharedMemorySize, BT_SMEM);
    cudaFuncSetAttribute((const void*)tgemm_res_kernel, cudaFuncAttributeMaxDynamicSharedMemorySize, SMEM_G);

    const size_t EE = (size_t)E_ * E_, EF = (size_t)E_ * F_;
    dim3 tb(32, 8);

    embed_kernel<<<(M_ * E_) / (256 * 4), 256>>>(x, tok, pos, h);                    // 0
    wconvT_qkv_kernel<<<dim3(32, 16, 3 * L_), tb>>>(Wq, Wk, Wv, qkvT);               // 1
    bpack_kernel<<<(L_ * 3 * E_) / 256, 256>>>(bq, bk, bv, bqkv);                    // 2
    ln_kernel<<<M_, 256>>>(h, ln1g, ln1b, xn);                                       // 3
    btgemm_kernel<2><<<dim3(M_ / 128, 12), 512, BT_SMEM>>>(                          // 4
        xn, qkvT, bqkv, nullptr, qkvh, 3 * E_, E_);
    wconvT_kernel<<<dim3(32, 16, L_), tb>>>(Wo, woT, E_, E_, EE, EE);                // 5
    wconvT_kernel<<<dim3(128, 16, L_), tb>>>(W1, w1T, E_, F_, EF, EF);               // 6
    wconvT_kernel<<<dim3(32, 64, L_), tb>>>(W2, w2T, F_, E_, EF, EF);                // 7
    wconvT_kernel<<<dim3(1000, 16, 1), tb>>>(Wout, wouT, E_, V_, 0, 0);              // 8

    for (int l = 0; l < L_; l++) {
        if (l > 0) {
            ln_kernel<<<M_, 256>>>(h, ln1g + l * E_, ln1b + l * E_, xn);
            btgemm_kernel<2><<<dim3(M_ / 128, 12), 512, BT_SMEM>>>(
                xn, qkvT + l * 3 * EE, bqkv + l * 3 * E_, nullptr, qkvh, 3 * E_, E_);
        }
        fattn_kernel<<<B_ * H_ * (T_ / 64), 128>>>(qkvh, o);
        tgemm_res_kernel<<<dim3(M_ / 128, 8), 256, SMEM_G>>>(
            o, woT + l * EE, bo + l * E_, h, h, E_, E_);
        ln_kernel<<<M_, 256>>>(h, ln2g + l * E_, ln2b + l * E_, xn);
        btgemm_kernel<1><<<dim3(M_ / 128, F_ / 256), 512, BT_SMEM>>>(
            xn, w1T + l * EF, b1 + l * F_, nullptr, mlp, F_, E_);
        tgemm_res_kernel<<<dim3(M_ / 128, 8), 256, SMEM_G>>>(
            mlp, w2T + l * EF, b2 + l * E_, h, h, E_, F_);
    }

    ln_kernel<<<M_, 256>>>(h, lnfg, lnfb, xn);
    btgemm_kernel<0><<<dim3(M_ / 128, V_ / 256), 512, BT_SMEM>>>(
        xn, wouT, bout, out, nullptr, V_, E_);
}

// round 14
// speedup vs baseline: 1.5920x; 1.0509x over previous
#include <cuda_runtime.h>
#include <cuda_fp16.h>
#include <math.h>
#include <stdint.h>

// Problem dims
#define V_ 32000
#define E_ 1024
#define H_ 16
#define F_ 4096
#define L_ 4
#define T_ 2048
#define B_ 2
#define D_ 64
#define M_ (B_*T_)   // 4096

// ---------------------------------------------------------------------------
// Scratch (device globals)
// ---------------------------------------------------------------------------
__device__ float g_h  [M_*E_];
__device__ __half g_qkv[M_*3*E_];
__device__ float g_bqkv[L_*3*E_];
__device__ __half g_xn [M_*E_];
__device__ __half g_o  [M_*E_];
__device__ __half g_mlp[M_*F_];
__device__ __half g_qkvT[L_*3*E_*E_];
__device__ __half g_woT [L_*E_*E_];
__device__ __half g_w1T [L_*F_*E_];
__device__ __half g_w2T [L_*E_*F_];
__device__ __half g_woutT[(size_t)V_*E_];

// ---------------------------------------------------------------------------
// PTX helpers
// ---------------------------------------------------------------------------
__device__ __forceinline__ uint32_t smem_u32(const void* p) {
    uint32_t a;
    asm("{ .reg .u64 t; cvta.to.shared.u64 t, %1; cvt.u32.u64 %0, t; }" : "=r"(a) : "l"(p));
    return a;
}
static __device__ __forceinline__ void cpa16(uint32_t s, const void* g) {
    asm volatile("cp.async.cg.shared.global [%0], [%1], 16;" :: "r"(s), "l"(g) : "memory");
}
#define CP_COMMIT() asm volatile("cp.async.commit_group;" ::: "memory")
#define CP_WAIT0()  asm volatile("cp.async.wait_group 0;" ::: "memory")
#define CP_WAIT1()  asm volatile("cp.async.wait_group 1;" ::: "memory")

#define MBAR_INIT(a, c) asm volatile("mbarrier.init.shared.b64 [%0], %1;" :: "r"((uint32_t)(a)), "r"((uint32_t)(c)) : "memory")
#define MBAR_EXPECT(a, n) asm volatile("mbarrier.arrive.expect_tx.shared.b64 _, [%0], %1;" :: "r"((uint32_t)(a)), "r"((uint32_t)(n)) : "memory")
static __device__ __forceinline__ void bulk_g2s(uint32_t s, const void* g, uint32_t bytes, uint32_t mbar) {
    asm volatile("cp.async.bulk.shared::cta.global.mbarrier::complete_tx::bytes [%0], [%1], %2, [%3];"
                 :: "r"(s), "l"(g), "r"(bytes), "r"(mbar) : "memory");
}
#define MBAR_WAIT(addr, par) do {                                              \
    uint32_t _m = (uint32_t)(addr), _p = (uint32_t)(par), _d;                  \
    asm volatile("{\n\t.reg .pred p;\n\t"                                      \
        "mbarrier.try_wait.parity.shared.b64 p, [%1], %2;\n\t"                 \
        "selp.b32 %0, 1, 0, p;\n\t}" : "=r"(_d) : "r"(_m), "r"(_p) : "memory");\
    if (!_d) {                                                                 \
        asm volatile("{\n\t.reg .pred P1;\n\t"                                 \
            "WL_%=:\n\t"                                                       \
            "mbarrier.try_wait.parity.shared.b64 P1, [%0], %1;\n\t"            \
            "@P1 bra.uni WD_%=;\n\t"                                           \
            "bra.uni WL_%=;\n\t"                                               \
            "WD_%=:\n\t}" :: "r"(_m), "r"(_p) : "memory");                     \
    }                                                                          \
} while (0)

struct Frag4 { uint32_t x, y, z, w; };

static __device__ __forceinline__ Frag4 ldsm_x4(uint32_t addr) {
    Frag4 r;
    asm volatile("ldmatrix.sync.aligned.m8n8.x4.shared.b16 {%0,%1,%2,%3}, [%4];"
                 : "=r"(r.x), "=r"(r.y), "=r"(r.z), "=r"(r.w) : "r"(addr));
    return r;
}
static __device__ __forceinline__ Frag4 ldsm_x4_t(uint32_t addr) {
    Frag4 r;
    asm volatile("ldmatrix.sync.aligned.m8n8.x4.trans.shared.b16 {%0,%1,%2,%3}, [%4];"
                 : "=r"(r.x), "=r"(r.y), "=r"(r.z), "=r"(r.w) : "r"(addr));
    return r;
}

static __device__ __forceinline__ void mma_f16(float* c, const Frag4& a,
                                               uint32_t b0, uint32_t b1) {
    asm volatile(
        "mma.sync.aligned.m16n8k16.row.col.f32.f16.f16.f32 "
        "{%0,%1,%2,%3}, {%4,%5,%6,%7}, {%8,%9}, {%0,%1,%2,%3};"
        : "+f"(c[0]), "+f"(c[1]), "+f"(c[2]), "+f"(c[3])
        : "r"(a.x), "r"(a.y), "r"(a.z), "r"(a.w), "r"(b0), "r"(b1));
}
static __device__ __forceinline__ void mma4(float* c, uint32_t a0, uint32_t a1,
                                            uint32_t a2, uint32_t a3,
                                            uint32_t b0, uint32_t b1) {
    asm volatile(
        "mma.sync.aligned.m16n8k16.row.col.f32.f16.f16.f32 "
        "{%0,%1,%2,%3}, {%4,%5,%6,%7}, {%8,%9}, {%0,%1,%2,%3};"
        : "+f"(c[0]), "+f"(c[1]), "+f"(c[2]), "+f"(c[3])
        : "r"(a0), "r"(a1), "r"(a2), "r"(a3), "r"(b0), "r"(b1));
}

static __device__ __forceinline__ float ex2f(float x) {
    float y;
    asm("ex2.approx.ftz.f32 %0, %1;" : "=f"(y) : "f"(x));
    return y;
}
static __device__ __forceinline__ uint32_t pkh2(float a, float b) {
    __half2 h = __floats2half2_rn(a, b);
    return *(uint32_t*)&h;
}
__device__ __forceinline__ float gelu_exact(float x) {
    return 0.5f * x * (1.0f + erff(x * 0.70710678118654752f));
}

// ===========================================================================
// BIG-TILE GEMM (QKV, MLP1, Wout): CTA 128x256, 512 threads, warptile 64x32,
// BK=64, 3-stage. A via cp.async (144B-pad rows), B via cp.async.bulk from
// TILED weights (dense 128B rows, XOR granule swizzle).
// EPI: 0 = fp32+bias ; 1 = gelu->fp16 ; 2 = fp16
// ===========================================================================
#define ROWB     144
#define BT_TA    (128 * ROWB)               // 18432
#define BT_TB    32768                      // 256 x 128B dense
#define BT_STG   (BT_TA + BT_TB)            // 51200
#define BT_SMEM  (3 * BT_STG + 64)          // + mbarriers

template<int EPI>
__global__ __launch_bounds__(512, 1) void btgemm_kernel(
    const __half* __restrict__ A, const __half* __restrict__ Bt,   // Bt tiled
    const float* __restrict__ bias,
    float* __restrict__ Cf, __half* __restrict__ Ch,
    int N, int K)
{
    extern __shared__ __align__(1024) unsigned char smem[];
    uint32_t sb = smem_u32(smem);
    int tid = threadIdx.x, wid = tid >> 5, lane = tid & 31;
    int bm = blockIdx.x * 128, bn = blockIdx.y * 256;
    int wm = wid & 1, wn = wid >> 1;
    int nkt = K >> 6;

    uint32_t stg[3] = {sb, sb + BT_STG, sb + 2u * BT_STG};
    uint32_t mb0 = sb + 3u * BT_STG;
    if (tid == 0) { MBAR_INIT(mb0, 1); MBAR_INIT(mb0 + 8, 1); MBAR_INIT(mb0 + 16, 1); }
    __syncthreads();

    uint32_t a_lane = (uint32_t)((wm * 64 + (lane & 15)) * ROWB + ((lane >> 4) << 4));
    int l7 = lane & 7, b1 = (lane >> 3) & 1;
    int rbase = (lane & 7) + ((lane >> 4) << 3);
    uint32_t brow0 = (uint32_t)((wn * 32 + rbase) * 128);        // np=0
    uint32_t brow1 = (uint32_t)((wn * 32 + 16 + rbase) * 128);   // np=1

    float acc[4][4][4];
#pragma unroll
    for (int i = 0; i < 4; i++)
#pragma unroll
        for (int j = 0; j < 4; j++)
#pragma unroll
            for (int e = 0; e < 4; e++) acc[i][j][e] = 0.f;

    // prologue: stages 0,1
#pragma unroll
    for (int s = 0; s < 2; s++) {
        if (tid == 0) {
            MBAR_EXPECT(mb0 + s * 8, BT_TB);
            size_t tile = (size_t)(bn >> 8) * nkt + s;
            bulk_g2s(stg[s] + BT_TA, Bt + tile * (BT_TB / 2), BT_TB, mb0 + s * 8);
        }
#pragma unroll
        for (int i = 0; i < 2; i++) {
            int c = tid + (i << 9);
            int r = c >> 3, q = c & 7;
            cpa16(stg[s] + (uint32_t)(r * ROWB + q * 16),
                  A + (size_t)(bm + r) * K + (s << 6) + (q << 3));
        }
        CP_COMMIT();
    }

    int cur = 0, nxt = 2;
    int phbits = 0;
    for (int kt = 0; kt < nkt; kt++) {
        CP_WAIT1();
        MBAR_WAIT(mb0 + cur * 8, (phbits >> cur) & 1);
        phbits ^= (1 << cur);
        __syncthreads();

        int kf = kt + 2;
        if (kf < nkt) {
            if (tid == 0) {
                MBAR_EXPECT(mb0 + nxt * 8, BT_TB);
                size_t tile = (size_t)(bn >> 8) * nkt + kf;
                bulk_g2s(stg[nxt] + BT_TA, Bt + tile * (BT_TB / 2), BT_TB, mb0 + nxt * 8);
            }
#pragma unroll
            for (int i = 0; i < 2; i++) {
                int c = tid + (i << 9);
                int r = c >> 3, q = c & 7;
                cpa16(stg[nxt] + (uint32_t)(r * ROWB + q * 16),
                      A + (size_t)(bm + r) * K + (kf << 6) + (q << 3));
            }
        }
        CP_COMMIT();

        uint32_t st = stg[cur];
        uint32_t bB = st + BT_TA;
        cur = (cur + 1) % 3; nxt = (nxt + 1) % 3;
#pragma unroll
        for (int ks = 0; ks < 4; ks++) {
            uint32_t kb = ks << 5;
            uint32_t gp = (uint32_t)(((ks << 1) + b1) ^ l7) << 4;
            Frag4 ah[4];
#pragma unroll
            for (int mt = 0; mt < 4; mt++)
                ah[mt] = ldsm_x4(st + a_lane + mt * (16 * ROWB) + kb);
            Frag4 bf0 = ldsm_x4(bB + brow0 + gp);
            Frag4 bf1 = ldsm_x4(bB + brow1 + gp);
#pragma unroll
            for (int mt = 0; mt < 4; mt++) {
                mma_f16(acc[mt][0], ah[mt], bf0.x, bf0.y);
                mma_f16(acc[mt][1], ah[mt], bf0.z, bf0.w);
                mma_f16(acc[mt][2], ah[mt], bf1.x, bf1.y);
                mma_f16(acc[mt][3], ah[mt], bf1.z, bf1.w);
            }
        }
    }
    __syncthreads();

    int row_in = lane >> 2;
    int col2   = (lane & 3) << 1;
#pragma unroll
    for (int mt = 0; mt < 4; mt++) {
#pragma unroll
        for (int nt = 0; nt < 4; nt++) {
            int col = bn + wn * 32 + nt * 8 + col2;
            float bx = bias[col], by = bias[col + 1];
#pragma unroll
            for (int half = 0; half < 2; half++) {
                int row = bm + wm * 64 + mt * 16 + row_in + half * 8;
                size_t off = (size_t)row * N + col;
                float v0 = acc[mt][nt][half * 2 + 0] + bx;
                float v1 = acc[mt][nt][half * 2 + 1] + by;
                if (EPI == 0) {
                    *(float2*)&Cf[off] = make_float2(v0, v1);
                } else if (EPI == 1) {
                    __half2 hh;
                    hh.x = __float2half(gelu_exact(v0));
                    hh.y = __float2half(gelu_exact(v1));
                    *(__half2*)&Ch[off] = hh;
                } else {
                    __half2 hh;
                    hh.x = __float2half(v0);
                    hh.y = __float2half(v1);
                    *(__half2*)&Ch[off] = hh;
                }
            }
        }
    }
}

// ===========================================================================
// SMALL-TILE GEMM (N=1024, residual): CTA 128x128, 256 threads, BK=64,
// 3-stage, 2 CTAs/SM. B tiled 128x64 via bulk.
// ===========================================================================
#define ST_TB    16384                      // 128 x 128B
#define ST_STG   (BT_TA + ST_TB)            // 34816
#define ST_SMEM  (3 * ST_STG + 64)          // 104512

__global__ __launch_bounds__(256, 2) void tgemm_res_kernel(
    const __half* __restrict__ A, const __half* __restrict__ Bt,
    const float* __restrict__ bias, const float* __restrict__ res,
    float* __restrict__ Cf, int N, int K)
{
    extern __shared__ __align__(1024) unsigned char smem[];
    uint32_t sb = smem_u32(smem);
    int tid = threadIdx.x, wid = tid >> 5, lane = tid & 31;
    int bm = blockIdx.x * 128, bn = blockIdx.y * 128;
    int wm = wid & 1, wn = wid >> 1;
    int nkt = K >> 6;

    uint32_t stg[3] = {sb, sb + ST_STG, sb + 2u * ST_STG};
    uint32_t mb0 = sb + 3u * ST_STG;
    if (tid == 0) { MBAR_INIT(mb0, 1); MBAR_INIT(mb0 + 8, 1); MBAR_INIT(mb0 + 16, 1); }
    __syncthreads();

    uint32_t a_lane = (uint32_t)((wm * 64 + (lane & 15)) * ROWB + ((lane >> 4) << 4));
    int l7 = lane & 7, b1 = (lane >> 3) & 1;
    int rbase = (lane & 7) + ((lane >> 4) << 3);
    uint32_t brow0 = (uint32_t)((wn * 32 + rbase) * 128);
    uint32_t brow1 = (uint32_t)((wn * 32 + 16 + rbase) * 128);

    float acc[4][4][4];
#pragma unroll
    for (int i = 0; i < 4; i++)
#pragma unroll
        for (int j = 0; j < 4; j++)
#pragma unroll
            for (int e = 0; e < 4; e++) acc[i][j][e] = 0.f;

#pragma unroll
    for (int s = 0; s < 2; s++) {
        if (tid == 0) {
            MBAR_EXPECT(mb0 + s * 8, ST_TB);
            size_t tile = (size_t)(bn >> 7) * nkt + s;
            bulk_g2s(stg[s] + BT_TA, Bt + tile * (ST_TB / 2), ST_TB, mb0 + s * 8);
        }
#pragma unroll
        for (int i = 0; i < 4; i++) {
            int c = tid + (i << 8);
            int r = c >> 3, q = c & 7;
            cpa16(stg[s] + (uint32_t)(r * ROWB + q * 16),
                  A + (size_t)(bm + r) * K + (s << 6) + (q << 3));
        }
        CP_COMMIT();
    }

    int cur = 0, nxt = 2;
    int phbits = 0;
    for (int kt = 0; kt < nkt; kt++) {
        CP_WAIT1();
        MBAR_WAIT(mb0 + cur * 8, (phbits >> cur) & 1);
        phbits ^= (1 << cur);
        __syncthreads();

        int kf = kt + 2;
        if (kf < nkt) {
            if (tid == 0) {
                MBAR_EXPECT(mb0 + nxt * 8, ST_TB);
                size_t tile = (size_t)(bn >> 7) * nkt + kf;
                bulk_g2s(stg[nxt] + BT_TA, Bt + tile * (ST_TB / 2), ST_TB, mb0 + nxt * 8);
            }
#pragma unroll
            for (int i = 0; i < 4; i++) {
                int c = tid + (i << 8);
                int r = c >> 3, q = c & 7;
                cpa16(stg[nxt] + (uint32_t)(r * ROWB + q * 16),
                      A + (size_t)(bm + r) * K + (kf << 6) + (q << 3));
            }
        }
        CP_COMMIT();

        uint32_t st = stg[cur];
        uint32_t bB = st + BT_TA;
        cur = (cur + 1) % 3; nxt = (nxt + 1) % 3;
#pragma unroll
        for (int ks = 0; ks < 4; ks++) {
            uint32_t kb = ks << 5;
            uint32_t gp = (uint32_t)(((ks << 1) + b1) ^ l7) << 4;
            Frag4 ah[4];
#pragma unroll
            for (int mt = 0; mt < 4; mt++)
                ah[mt] = ldsm_x4(st + a_lane + mt * (16 * ROWB) + kb);
            Frag4 bf0 = ldsm_x4(bB + brow0 + gp);
            Frag4 bf1 = ldsm_x4(bB + brow1 + gp);
#pragma unroll
            for (int mt = 0; mt < 4; mt++) {
                mma_f16(acc[mt][0], ah[mt], bf0.x, bf0.y);
                mma_f16(acc[mt][1], ah[mt], bf0.z, bf0.w);
                mma_f16(acc[mt][2], ah[mt], bf1.x, bf1.y);
                mma_f16(acc[mt][3], ah[mt], bf1.z, bf1.w);
            }
        }
    }
    __syncthreads();

    int row_in = lane >> 2;
    int col2   = (lane & 3) << 1;
#pragma unroll
    for (int mt = 0; mt < 4; mt++) {
#pragma unroll
        for (int nt = 0; nt < 4; nt++) {
            int col = bn + wn * 32 + nt * 8 + col2;
            float bx = bias[col], by = bias[col + 1];
#pragma unroll
            for (int half = 0; half < 2; half++) {
                int row = bm + wm * 64 + mt * 16 + row_in + half * 8;
                size_t off = (size_t)row * N + col;
                float2 rv = *(const float2*)&res[off];
                *(float2*)&Cf[off] = make_float2(acc[mt][nt][half * 2 + 0] + bx + rv.x,
                                                 acc[mt][nt][half * 2 + 1] + by + rv.y);
            }
        }
    }
}

// ===========================================================================
// Flash attention (unchanged from R13 best)
// ===========================================================================
__global__ __launch_bounds__(128) void fattn_kernel(const __half* __restrict__ qkv,
                                                    __half* __restrict__ oh) {
    __shared__ __half Qs[64 * 72];
    __shared__ __half Ks[2][64 * 72];
    __shared__ __half Vs[2][64 * 72];

    int tid = threadIdx.x, wid = tid >> 5, lane = tid & 31;
    int qt = 31 - (blockIdx.x & 31);
    int bh = blockIdx.x >> 5;
    int b  = bh >> 4, hh = bh & 15;
    int q0 = qt * 64;

    for (int i = tid; i < 512; i += 128) {
        int r = i >> 3, c8 = (i & 7) << 3;
        *(uint4*)&Qs[r * 72 + c8] =
            *(const uint4*)(qkv + (size_t)(b * T_ + q0 + r) * 3072 + hh * 64 + c8);
    }
    __syncthreads();

    uint32_t qbase = smem_u32(Qs);
    Frag4 qf[4];
    {
        int rr = wid * 16 + (lane & 15);
#pragma unroll
        for (int kd = 0; kd < 4; kd++)
            qf[kd] = ldsm_x4(qbase + (uint32_t)(rr * 144 + kd * 32 + ((lane >> 4) << 4)));
    }

    uint32_t ksb[2] = {smem_u32(Ks[0]), smem_u32(Ks[1])};
    uint32_t vsb[2] = {smem_u32(Vs[0]), smem_u32(Vs[1])};

    float o[8][4];
#pragma unroll
    for (int t = 0; t < 8; t++)
#pragma unroll
        for (int e = 0; e < 4; e++) o[t][e] = 0.f;
    float m0 = -1e30f, m1 = -1e30f, l0 = 0.f, l1 = 0.f;

    const float SC = 0.18033688011f;
    int ntiles = qt + 1;

    for (int i = tid; i < 512; i += 128) {
        int r = i >> 3, c8 = (i & 7) << 3;
        size_t base = (size_t)(b * T_ + r) * 3072 + hh * 64 + c8;
        cpa16(ksb[0] + (uint32_t)(r * 144 + c8 * 2), qkv + base + 1024);
        cpa16(vsb[0] + (uint32_t)(r * 144 + c8 * 2), qkv + base + 2048);
    }
    CP_COMMIT();

    for (int t = 0; t < ntiles; t++) {
        if (t + 1 < ntiles) {
            int kb = (t + 1) * 64;
            int buf = (t + 1) & 1;
            for (int i = tid; i < 512; i += 128) {
                int r = i >> 3, c8 = (i & 7) << 3;
                size_t base = (size_t)(b * T_ + kb + r) * 3072 + hh * 64 + c8;
                cpa16(ksb[buf] + (uint32_t)(r * 144 + c8 * 2), qkv + base + 1024);
                cpa16(vsb[buf] + (uint32_t)(r * 144 + c8 * 2), qkv + base + 2048);
            }
            CP_COMMIT();
            CP_WAIT1();
        } else {
            CP_WAIT0();
        }
        __syncthreads();

        int buf = t & 1;
        uint32_t kb_s = ksb[buf], vb_s = vsb[buf];

        float s[8][4];
#pragma unroll
        for (int j = 0; j < 8; j++)
#pragma unroll
            for (int e = 0; e < 4; e++) s[j][e] = 0.f;
#pragma unroll
        for (int kd = 0; kd < 4; kd++) {
#pragma unroll
            for (int np = 0; np < 4; np++) {
                Frag4 bf = ldsm_x4(kb_s + (uint32_t)((np * 16 + (lane & 7) + ((lane >> 4) << 3)) * 144
                                                     + kd * 32 + (((lane >> 3) & 1) << 4)));
                mma_f16(s[np * 2],     qf[kd], bf.x, bf.y);
                mma_f16(s[np * 2 + 1], qf[kd], bf.z, bf.w);
            }
        }

#pragma unroll
        for (int j = 0; j < 8; j++)
#pragma unroll
            for (int e = 0; e < 4; e++) s[j][e] *= SC;

        if (t == qt) {
            int lr0 = wid * 16 + (lane >> 2);
#pragma unroll
            for (int j = 0; j < 8; j++) {
                int c = 8 * j + 2 * (lane & 3);
                if (c     > lr0)     s[j][0] = -1e30f;
                if (c + 1 > lr0)     s[j][1] = -1e30f;
                if (c     > lr0 + 8) s[j][2] = -1e30f;
                if (c + 1 > lr0 + 8) s[j][3] = -1e30f;
            }
        }

        float mr0 = -1e30f, mr1 = -1e30f;
#pragma unroll
        for (int j = 0; j < 8; j++) {
            mr0 = fmaxf(mr0, fmaxf(s[j][0], s[j][1]));
            mr1 = fmaxf(mr1, fmaxf(s[j][2], s[j][3]));
        }
        mr0 = fmaxf(mr0, __shfl_xor_sync(0xffffffffu, mr0, 1));
        mr0 = fmaxf(mr0, __shfl_xor_sync(0xffffffffu, mr0, 2));
        mr1 = fmaxf(mr1, __shfl_xor_sync(0xffffffffu, mr1, 1));
        mr1 = fmaxf(mr1, __shfl_xor_sync(0xffffffffu, mr1, 2));

        float nm0 = fmaxf(m0, mr0), nm1 = fmaxf(m1, mr1);
        float c0 = ex2f(m0 - nm0), c1 = ex2f(m1 - nm1);
        m0 = nm0; m1 = nm1;
        l0 *= c0; l1 *= c1;

        uint32_t pf[8][2];
        float ps0 = 0.f, ps1 = 0.f;
#pragma unroll
        for (int j = 0; j < 8; j++) {
            float p0 = ex2f(s[j][0] - m0), p1 = ex2f(s[j][1] - m0);
            float p2 = ex2f(s[j][2] - m1), p3 = ex2f(s[j][3] - m1);
            ps0 += p0 + p1; ps1 += p2 + p3;
            pf[j][0] = pkh2(p0, p1);
            pf[j][1] = pkh2(p2, p3);
        }
        l0 += ps0; l1 += ps1;

#pragma unroll
        for (int tt = 0; tt < 8; tt++) {
            o[tt][0] *= c0; o[tt][1] *= c0;
            o[tt][2] *= c1; o[tt][3] *= c1;
        }

#pragma unroll
        for (int j = 0; j < 4; j++) {
            uint32_t a0 = pf[2 * j][0],     a1 = pf[2 * j][1];
            uint32_t a2 = pf[2 * j + 1][0], a3 = pf[2 * j + 1][1];
#pragma unroll
            for (int t2 = 0; t2 < 4; t2++) {
                Frag4 vf = ldsm_x4_t(vb_s + (uint32_t)((j * 16 + (lane & 7) + (((lane >> 3) & 1) << 3)) * 144
                                                       + t2 * 32 + ((lane >> 4) << 4)));
                mma4(o[2 * t2],     a0, a1, a2, a3, vf.x, vf.y);
                mma4(o[2 * t2 + 1], a0, a1, a2, a3, vf.z, vf.w);
            }
        }
        __syncthreads();
    }

    l0 += __shfl_xor_sync(0xffffffffu, l0, 1);
    l0 += __shfl_xor_sync(0xffffffffu, l0, 2);
    l1 += __shfl_xor_sync(0xffffffffu, l1, 1);
    l1 += __shfl_xor_sync(0xffffffffu, l1, 2);
    float li0 = 1.0f / l0, li1 = 1.0f / l1;

    int r0g = q0 + wid * 16 + (lane >> 2);
    int dbase = hh * 64 + 2 * (lane & 3);
#pragma unroll
    for (int tt = 0; tt < 8; tt++) {
        __half2 h01 = __floats2half2_rn(o[tt][0] * li0, o[tt][1] * li0);
        __half2 h23 = __floats2half2_rn(o[tt][2] * li1, o[tt][3] * li1);
        *(__half2*)&oh[(size_t)(b * T_ + r0g) * E_ + dbase + tt * 8]       = h01;
        *(__half2*)&oh[(size_t)(b * T_ + r0g + 8) * E_ + dbase + tt * 8]   = h23;
    }
}

// ===========================================================================
// Weight tiling: W[K,N] f32 -> fp16 tiles of (tileN x 64k), dense 128B rows,
// granule XOR swizzle. Block (32,8) covers 64n x 64k.
// ===========================================================================
__global__ void wtile_kernel(const float* __restrict__ W, __half* __restrict__ out,
                             int K, int N, int tshift,   // tileN = 1<<tshift
                             size_t inLs, size_t outLs)
{
    __shared__ float s[64][65];
    const float* Wl = W + blockIdx.z * inLs;
    out += blockIdx.z * outLs;
    int n0 = blockIdx.x * 64, k0g = blockIdx.y;   // k block index
    int tid = threadIdx.y * 32 + threadIdx.x;
    int nkt = K >> 6;
    int tileN = 1 << tshift;
#pragma unroll
    for (int i = 0; i < 16; i++) {
        int idx = tid + i * 256;
        int k = idx >> 6, n = idx & 63;
        s[k][n] = Wl[(size_t)(k0g * 64 + k) * N + n0 + n];
    }
    __syncthreads();
#pragma unroll
    for (int pass = 0; pass < 2; pass++) {
        int n = (tid >> 3) + pass * 32;
        int g = tid & 7;
        int gn = n0 + n;
        int tile = (gn >> tshift) * nkt + k0g;
        int nl = gn & (tileN - 1);
        uint32_t gp = (uint32_t)g ^ (uint32_t)(nl & 7);
        uint4 u;
        u.x = pkh2(s[g * 8 + 0][n], s[g * 8 + 1][n]);
        u.y = pkh2(s[g * 8 + 2][n], s[g * 8 + 3][n]);
        u.z = pkh2(s[g * 8 + 4][n], s[g * 8 + 5][n]);
        u.w = pkh2(s[g * 8 + 6][n], s[g * 8 + 7][n]);
        *(uint4*)&out[(size_t)tile * (tileN * 64) + nl * 64 + gp * 8] = u;
    }
}

// QKV variant: n spans 3*1024 across Wq/Wk/Wv; tileN=256, K=1024 (nkt=16)
__global__ void wtile_qkv_kernel(const float* __restrict__ Wq,
                                 const float* __restrict__ Wk,
                                 const float* __restrict__ Wv,
                                 __half* __restrict__ out)
{
    __shared__ float s[64][65];
    const size_t EE = (size_t)E_ * E_;
    int l = blockIdx.z;
    int gn0 = blockIdx.x * 64;
    int which = gn0 >> 10;
    const float* Wl = (which == 0 ? Wq : which == 1 ? Wk : Wv) + l * EE;
    int n0 = gn0 & 1023;
    int k0g = blockIdx.y;
    out += (size_t)l * 3 * EE;
    int tid = threadIdx.y * 32 + threadIdx.x;
#pragma unroll
    for (int i = 0; i < 16; i++) {
        int idx = tid + i * 256;
        int k = idx >> 6, n = idx & 63;
        s[k][n] = Wl[(size_t)(k0g * 64 + k) * E_ + n0 + n];
    }
    __syncthreads();
#pragma unroll
    for (int pass = 0; pass < 2; pass++) {
        int n = (tid >> 3) + pass * 32;
        int g = tid & 7;
        int gn = gn0 + n;
        int tile = (gn >> 8) * 16 + k0g;
        int nl = gn & 255;
        uint32_t gp = (uint32_t)g ^ (uint32_t)(nl & 7);
        uint4 u;
        u.x = pkh2(s[g * 8 + 0][n], s[g * 8 + 1][n]);
        u.y = pkh2(s[g * 8 + 2][n], s[g * 8 + 3][n]);
        u.z = pkh2(s[g * 8 + 4][n], s[g * 8 + 5][n]);
        u.w = pkh2(s[g * 8 + 6][n], s[g * 8 + 7][n]);
        *(uint4*)&out[(size_t)tile * (256 * 64) + nl * 64 + gp * 8] = u;
    }
}

// Pack per-layer QKV biases into [L, 3E]
__global__ void bpack_kernel(const float* __restrict__ bq, const float* __restrict__ bk,
                             const float* __restrict__ bv, float* __restrict__ out) {
    int i = blockIdx.x * 256 + threadIdx.x;
    int l = i / 3072, j = i % 3072;
    float v = (j < 1024) ? bq[l * 1024 + j]
            : (j < 2048) ? bk[l * 1024 + j - 1024]
                         : bv[l * 1024 + j - 2048];
    out[i] = v;
}

// ---------------------------------------------------------------------------
// Embedding / LayerNorm (warp-per-row, single pass, no block barriers)
// ---------------------------------------------------------------------------
__global__ void embed_kernel(const int* __restrict__ x, const float* __restrict__ tok,
                             const float* __restrict__ pos, float* __restrict__ h) {
    int i = blockIdx.x * 256 + threadIdx.x;
    int row = i >> 8, e4 = (i & 255) << 2;
    int tkn = x[row];
    int t = row & (T_ - 1);
    float4 a = *(const float4*)(tok + (size_t)tkn * E_ + e4);
    float4 p = *(const float4*)(pos + (size_t)t * E_ + e4);
    *(float4*)(h + (size_t)row * E_ + e4) =
        make_float4(a.x + p.x, a.y + p.y, a.z + p.z, a.w + p.w);
}

__global__ __launch_bounds__(256) void ln_kernel(const float* __restrict__ in,
                                                 const float* __restrict__ gam,
                                                 const float* __restrict__ bet,
                                                 __half* __restrict__ outh) {
    int row = blockIdx.x * 8 + (threadIdx.x >> 5);
    int lane = threadIdx.x & 31;
    const float4* rp = (const float4*)(in + (size_t)row * E_) + lane;
    float4 v[8];
    float s = 0.f, sq = 0.f;
#pragma unroll
    for (int i = 0; i < 8; i++) {
        v[i] = rp[i * 32];
        s  += v[i].x + v[i].y + v[i].z + v[i].w;
        sq += v[i].x * v[i].x + v[i].y * v[i].y + v[i].z * v[i].z + v[i].w * v[i].w;
    }
#pragma unroll
    for (int o = 16; o > 0; o >>= 1) {
        s  += __shfl_xor_sync(0xffffffffu, s,  o);
        sq += __shfl_xor_sync(0xffffffffu, sq, o);
    }
    float mean = s * (1.0f / E_);
    float var  = sq * (1.0f / E_) - mean * mean;
    float rstd = rsqrtf(var + 1e-5f);

#pragma unroll
    for (int i = 0; i < 8; i++) {
        int e = (lane + i * 32) * 4;
        float4 g = *(const float4*)(gam + e);
        float4 bb = *(const float4*)(bet + e);
        __half2 h0 = __floats2half2_rn((v[i].x - mean) * rstd * g.x + bb.x,
                                       (v[i].y - mean) * rstd * g.y + bb.y);
        __half2 h1 = __floats2half2_rn((v[i].z - mean) * rstd * g.z + bb.z,
                                       (v[i].w - mean) * rstd * g.w + bb.w);
        *(__half2*)&outh[(size_t)row * E_ + e]     = h0;
        *(__half2*)&outh[(size_t)row * E_ + e + 2] = h1;
    }
}

// ---------------------------------------------------------------------------
// Host orchestration
// ---------------------------------------------------------------------------
extern "C" void kernel_launch(void* const* d_in, const int* in_sizes, int n_in,
                              void* d_out, int out_size) {
    const int*   x    = (const int*)  d_in[0];
    const float* tok  = (const float*)d_in[1];
    const float* pos  = (const float*)d_in[2];
    const float* Wq   = (const float*)d_in[3];
    const float* bq   = (const float*)d_in[4];
    const float* Wk   = (const float*)d_in[5];
    const float* bk   = (const float*)d_in[6];
    const float* Wv   = (const float*)d_in[7];
    const float* bv   = (const float*)d_in[8];
    const float* Wo   = (const float*)d_in[9];
    const float* bo   = (const float*)d_in[10];
    const float* ln1g = (const float*)d_in[11];
    const float* ln1b = (const float*)d_in[12];
    const float* W1   = (const float*)d_in[13];
    const float* b1   = (const float*)d_in[14];
    const float* W2   = (const float*)d_in[15];
    const float* b2   = (const float*)d_in[16];
    const float* ln2g = (const float*)d_in[17];
    const float* ln2b = (const float*)d_in[18];
    const float* lnfg = (const float*)d_in[19];
    const float* lnfb = (const float*)d_in[20];
    const float* Wout = (const float*)d_in[21];
    const float* bout = (const float*)d_in[22];
    float* out = (float*)d_out;

    float *h, *bqkv;
    __half *qkvh, *xn, *o, *mlp;
    __half *qkvT, *woT, *w1T, *w2T, *wouT;
    cudaGetSymbolAddress((void**)&h,    g_h);
    cudaGetSymbolAddress((void**)&qkvh, g_qkv);
    cudaGetSymbolAddress((void**)&bqkv, g_bqkv);
    cudaGetSymbolAddress((void**)&xn,   g_xn);
    cudaGetSymbolAddress((void**)&o,    g_o);
    cudaGetSymbolAddress((void**)&mlp,  g_mlp);
    cudaGetSymbolAddress((void**)&qkvT, g_qkvT);
    cudaGetSymbolAddress((void**)&woT,  g_woT);
    cudaGetSymbolAddress((void**)&w1T,  g_w1T);
    cudaGetSymbolAddress((void**)&w2T,  g_w2T);
    cudaGetSymbolAddress((void**)&wouT, g_woutT);

    cudaFuncSetAttribute((const void*)btgemm_kernel<0>, cudaFuncAttributeMaxDynamicSharedMemorySize, BT_SMEM);
    cudaFuncSetAttribute((const void*)btgemm_kernel<1>, cudaFuncAttributeMaxDynamicSharedMemorySize, BT_SMEM);
    cudaFuncSetAttribute((const void*)btgemm_kernel<2>, cudaFuncAttributeMaxDynamicSharedMemorySize, BT_SMEM);
    cudaFuncSetAttribute((const void*)tgemm_res_kernel, cudaFuncAttributeMaxDynamicSharedMemorySize, ST_SMEM);

    const size_t EE = (size_t)E_ * E_, EF = (size_t)E_ * F_;
    dim3 tb(32, 8);

    embed_kernel<<<(M_ * E_) / (256 * 4), 256>>>(x, tok, pos, h);                    // 0
    wtile_qkv_kernel<<<dim3(48, 16, L_), tb>>>(Wq, Wk, Wv, qkvT);                    // 1
    bpack_kernel<<<(L_ * 3 * E_) / 256, 256>>>(bq, bk, bv, bqkv);                    // 2
    ln_kernel<<<M_ / 8, 256>>>(h, ln1g, ln1b, xn);                                   // 3
    btgemm_kernel<2><<<dim3(M_ / 128, 12), 512, BT_SMEM>>>(                          // 4
        xn, qkvT, bqkv, nullptr, qkvh, 3 * E_, E_);
    wtile_kernel<<<dim3(16, 16, L_), tb>>>(Wo, woT, E_, E_, 7, EE, EE);              // 5
    wtile_kernel<<<dim3(64, 16, L_), tb>>>(W1, w1T, E_, F_, 8, EF, EF);              // 6
    wtile_kernel<<<dim3(16, 64, L_), tb>>>(W2, w2T, F_, E_, 7, EF, EF);              // 7
    wtile_kernel<<<dim3(500, 16, 1), tb>>>(Wout, wouT, E_, V_, 8, 0, 0);             // 8

    for (int l = 0; l < L_; l++) {
        if (l > 0) {
            ln_kernel<<<M_ / 8, 256>>>(h, ln1g + l * E_, ln1b + l * E_, xn);
            btgemm_kernel<2><<<dim3(M_ / 128, 12), 512, BT_SMEM>>>(
                xn, qkvT + l * 3 * EE, bqkv + l * 3 * E_, nullptr, qkvh, 3 * E_, E_);
        }
        fattn_kernel<<<B_ * H_ * (T_ / 64), 128>>>(qkvh, o);
        tgemm_res_kernel<<<dim3(M_ / 128, 8), 256, ST_SMEM>>>(
            o, woT + l * EE, bo + l * E_, h, h, E_, E_);
        ln_kernel<<<M_ / 8, 256>>>(h, ln2g + l * E_, ln2b + l * E_, xn);
        btgemm_kernel<1><<<dim3(M_ / 128, F_ / 256), 512, BT_SMEM>>>(
            xn, w1T + l * EF, b1 + l * F_, nullptr, mlp, F_, E_);
        tgemm_res_kernel<<<dim3(M_ / 128, 8), 256, ST_SMEM>>>(
            mlp, w2T + l * EF, b2 + l * E_, h, h, E_, F_);
    }

    ln_kernel<<<M_ / 8, 256>>>(h, lnfg, lnfb, xn);
    btgemm_kernel<0><<<dim3(M_ / 128, V_ / 256), 512, BT_SMEM>>>(
        xn, wouT, bout, out, nullptr, V_, E_);
}

// round 15
// speedup vs baseline: 1.6722x; 1.0503x over previous
#include <cuda_runtime.h>
#include <cuda_fp16.h>
#include <math.h>
#include <stdint.h>

// Problem dims
#define V_ 32000
#define E_ 1024
#define H_ 16
#define F_ 4096
#define L_ 4
#define T_ 2048
#define B_ 2
#define D_ 64
#define M_ (B_*T_)   // 4096

// ---------------------------------------------------------------------------
// Scratch (device globals). Activations xn/o/mlp stored TILED:
// tile = 128 rows x 64 k (fp16, dense 128B rows, granule XOR swizzle g^(r&7)),
// tile index = (m>>7)*(K>>6) + (k>>6), 8192 halves per tile.
// ---------------------------------------------------------------------------
__device__ float g_h  [M_*E_];
__device__ __half g_qkv[M_*3*E_];      // row-major (attention reads rows)
__device__ float g_bqkv[L_*3*E_];
__device__ __half g_xn [M_*E_];        // tiled
__device__ __half g_o  [M_*E_];        // tiled
__device__ __half g_mlp[M_*F_];        // tiled
__device__ __half g_qkvT[L_*3*E_*E_];
__device__ __half g_woT [L_*E_*E_];
__device__ __half g_w1T [L_*F_*E_];
__device__ __half g_w2T [L_*E_*F_];
__device__ __half g_woutT[(size_t)V_*E_];

// ---------------------------------------------------------------------------
// PTX helpers
// ---------------------------------------------------------------------------
__device__ __forceinline__ uint32_t smem_u32(const void* p) {
    uint32_t a;
    asm("{ .reg .u64 t; cvta.to.shared.u64 t, %1; cvt.u32.u64 %0, t; }" : "=r"(a) : "l"(p));
    return a;
}
static __device__ __forceinline__ void cpa16(uint32_t s, const void* g) {
    asm volatile("cp.async.cg.shared.global [%0], [%1], 16;" :: "r"(s), "l"(g) : "memory");
}
#define CP_COMMIT() asm volatile("cp.async.commit_group;" ::: "memory")
#define CP_WAIT0()  asm volatile("cp.async.wait_group 0;" ::: "memory")
#define CP_WAIT1()  asm volatile("cp.async.wait_group 1;" ::: "memory")

#define MBAR_INIT(a, c) asm volatile("mbarrier.init.shared.b64 [%0], %1;" :: "r"((uint32_t)(a)), "r"((uint32_t)(c)) : "memory")
#define MBAR_EXPECT(a, n) asm volatile("mbarrier.arrive.expect_tx.shared.b64 _, [%0], %1;" :: "r"((uint32_t)(a)), "r"((uint32_t)(n)) : "memory")
static __device__ __forceinline__ void bulk_g2s(uint32_t s, const void* g, uint32_t bytes, uint32_t mbar) {
    asm volatile("cp.async.bulk.shared::cta.global.mbarrier::complete_tx::bytes [%0], [%1], %2, [%3];"
                 :: "r"(s), "l"(g), "r"(bytes), "r"(mbar) : "memory");
}
#define MBAR_WAIT(addr, par) do {                                              \
    uint32_t _m = (uint32_t)(addr), _p = (uint32_t)(par), _d;                  \
    asm volatile("{\n\t.reg .pred p;\n\t"                                      \
        "mbarrier.try_wait.parity.shared.b64 p, [%1], %2;\n\t"                 \
        "selp.b32 %0, 1, 0, p;\n\t}" : "=r"(_d) : "r"(_m), "r"(_p) : "memory");\
    if (!_d) {                                                                 \
        asm volatile("{\n\t.reg .pred P1;\n\t"                                 \
            "WL_%=:\n\t"                                                       \
            "mbarrier.try_wait.parity.shared.b64 P1, [%0], %1;\n\t"            \
            "@P1 bra.uni WD_%=;\n\t"                                           \
            "bra.uni WL_%=;\n\t"                                               \
            "WD_%=:\n\t}" :: "r"(_m), "r"(_p) : "memory");                     \
    }                                                                          \
} while (0)

struct Frag4 { uint32_t x, y, z, w; };

static __device__ __forceinline__ Frag4 ldsm_x4(uint32_t addr) {
    Frag4 r;
    asm volatile("ldmatrix.sync.aligned.m8n8.x4.shared.b16 {%0,%1,%2,%3}, [%4];"
                 : "=r"(r.x), "=r"(r.y), "=r"(r.z), "=r"(r.w) : "r"(addr));
    return r;
}
static __device__ __forceinline__ Frag4 ldsm_x4_t(uint32_t addr) {
    Frag4 r;
    asm volatile("ldmatrix.sync.aligned.m8n8.x4.trans.shared.b16 {%0,%1,%2,%3}, [%4];"
                 : "=r"(r.x), "=r"(r.y), "=r"(r.z), "=r"(r.w) : "r"(addr));
    return r;
}

static __device__ __forceinline__ void mma_f16(float* c, const Frag4& a,
                                               uint32_t b0, uint32_t b1) {
    asm volatile(
        "mma.sync.aligned.m16n8k16.row.col.f32.f16.f16.f32 "
        "{%0,%1,%2,%3}, {%4,%5,%6,%7}, {%8,%9}, {%0,%1,%2,%3};"
        : "+f"(c[0]), "+f"(c[1]), "+f"(c[2]), "+f"(c[3])
        : "r"(a.x), "r"(a.y), "r"(a.z), "r"(a.w), "r"(b0), "r"(b1));
}
static __device__ __forceinline__ void mma4(float* c, uint32_t a0, uint32_t a1,
                                            uint32_t a2, uint32_t a3,
                                            uint32_t b0, uint32_t b1) {
    asm volatile(
        "mma.sync.aligned.m16n8k16.row.col.f32.f16.f16.f32 "
        "{%0,%1,%2,%3}, {%4,%5,%6,%7}, {%8,%9}, {%0,%1,%2,%3};"
        : "+f"(c[0]), "+f"(c[1]), "+f"(c[2]), "+f"(c[3])
        : "r"(a0), "r"(a1), "r"(a2), "r"(a3), "r"(b0), "r"(b1));
}

static __device__ __forceinline__ float ex2f(float x) {
    float y;
    asm("ex2.approx.ftz.f32 %0, %1;" : "=f"(y) : "f"(x));
    return y;
}
static __device__ __forceinline__ uint32_t pkh2(float a, float b) {
    __half2 h = __floats2half2_rn(a, b);
    return *(uint32_t*)&h;
}
__device__ __forceinline__ float gelu_exact(float x) {
    return 0.5f * x * (1.0f + erff(x * 0.70710678118654752f));
}

// half index into tiled activation of width K (tiles of 128x64)
static __device__ __forceinline__ size_t atile_idx(int row, int col, int Kd64) {
    int gp = ((col >> 3) & 7) ^ (row & 7);
    return ((size_t)(row >> 7) * Kd64 + (col >> 6)) * 8192
           + (size_t)(row & 127) * 64 + gp * 8 + (col & 7);
}

// ===========================================================================
// BIG-TILE GEMM (QKV, MLP1, Wout): CTA 128x256, 512 threads, warptile 64x32,
// BK=64, 3-stage. A (tiled) + B (tiled) both via cp.async.bulk, one mbar/stage.
// EPI: 0 = fp32+bias ; 1 = gelu->fp16 TILED ; 2 = fp16 row-major
// ===========================================================================
#define BT_TA    16384                      // 128 x 128B dense
#define BT_TB    32768                      // 256 x 128B dense
#define BT_STG   (BT_TA + BT_TB)            // 49152
#define BT_SMEM  (3 * BT_STG + 64)

template<int EPI>
__global__ __launch_bounds__(512, 1) void btgemm_kernel(
    const __half* __restrict__ At, const __half* __restrict__ Bt,
    const float* __restrict__ bias,
    float* __restrict__ Cf, __half* __restrict__ Ch,
    int N, int K)
{
    extern __shared__ __align__(1024) unsigned char smem[];
    uint32_t sb = smem_u32(smem);
    int tid = threadIdx.x, wid = tid >> 5, lane = tid & 31;
    int bm = blockIdx.x * 128, bn = blockIdx.y * 256;
    int wm = wid & 1, wn = wid >> 1;
    int nkt = K >> 6;

    uint32_t stg[3] = {sb, sb + BT_STG, sb + 2u * BT_STG};
    uint32_t mb0 = sb + 3u * BT_STG;
    if (tid == 0) { MBAR_INIT(mb0, 1); MBAR_INIT(mb0 + 8, 1); MBAR_INIT(mb0 + 16, 1); }
    __syncthreads();

    int l7 = lane & 7, bA = lane >> 4, b1 = (lane >> 3) & 1;
    uint32_t a_row = (uint32_t)((wm * 64 + (lane & 15)) * 128);
    int rbase = (lane & 7) + ((lane >> 4) << 3);
    uint32_t brow0 = (uint32_t)(BT_TA + (wn * 32 + rbase) * 128);
    uint32_t brow1 = (uint32_t)(BT_TA + (wn * 32 + 16 + rbase) * 128);

    float acc[4][4][4];
#pragma unroll
    for (int i = 0; i < 4; i++)
#pragma unroll
        for (int j = 0; j < 4; j++)
#pragma unroll
            for (int e = 0; e < 4; e++) acc[i][j][e] = 0.f;

#pragma unroll
    for (int s = 0; s < 2; s++) {
        if (tid == 0) {
            MBAR_EXPECT(mb0 + s * 8, BT_STG);
            bulk_g2s(stg[s], At + ((size_t)(bm >> 7) * nkt + s) * 8192, BT_TA, mb0 + s * 8);
            bulk_g2s(stg[s] + BT_TA, Bt + ((size_t)(bn >> 8) * nkt + s) * 16384, BT_TB, mb0 + s * 8);
        }
    }

    int cur = 0, nxt = 2;
    int phbits = 0;
    for (int kt = 0; kt < nkt; kt++) {
        MBAR_WAIT(mb0 + cur * 8, (phbits >> cur) & 1);
        phbits ^= (1 << cur);
        __syncthreads();

        int kf = kt + 2;
        if (kf < nkt && tid == 0) {
            MBAR_EXPECT(mb0 + nxt * 8, BT_STG);
            bulk_g2s(stg[nxt], At + ((size_t)(bm >> 7) * nkt + kf) * 8192, BT_TA, mb0 + nxt * 8);
            bulk_g2s(stg[nxt] + BT_TA, Bt + ((size_t)(bn >> 8) * nkt + kf) * 16384, BT_TB, mb0 + nxt * 8);
        }

        uint32_t st = stg[cur];
        cur = (cur + 1) % 3; nxt = (nxt + 1) % 3;
#pragma unroll
        for (int ks = 0; ks < 4; ks++) {
            uint32_t gpA = (uint32_t)(((ks << 1) + bA) ^ l7) << 4;
            uint32_t gpB = (uint32_t)(((ks << 1) + b1) ^ l7) << 4;
            Frag4 ah[4];
#pragma unroll
            for (int mt = 0; mt < 4; mt++)
                ah[mt] = ldsm_x4(st + a_row + mt * 2048 + gpA);
            Frag4 bf0 = ldsm_x4(st + brow0 + gpB);
            Frag4 bf1 = ldsm_x4(st + brow1 + gpB);
#pragma unroll
            for (int mt = 0; mt < 4; mt++) {
                mma_f16(acc[mt][0], ah[mt], bf0.x, bf0.y);
                mma_f16(acc[mt][1], ah[mt], bf0.z, bf0.w);
                mma_f16(acc[mt][2], ah[mt], bf1.x, bf1.y);
                mma_f16(acc[mt][3], ah[mt], bf1.z, bf1.w);
            }
        }
        __syncthreads();
    }

    int row_in = lane >> 2;
    int col2   = (lane & 3) << 1;
    int Nd64 = N >> 6;
#pragma unroll
    for (int mt = 0; mt < 4; mt++) {
#pragma unroll
        for (int nt = 0; nt < 4; nt++) {
            int col = bn + wn * 32 + nt * 8 + col2;
            float bx = bias[col], by = bias[col + 1];
#pragma unroll
            for (int half = 0; half < 2; half++) {
                int row = bm + wm * 64 + mt * 16 + row_in + half * 8;
                float v0 = acc[mt][nt][half * 2 + 0] + bx;
                float v1 = acc[mt][nt][half * 2 + 1] + by;
                if (EPI == 0) {
                    *(float2*)&Cf[(size_t)row * N + col] = make_float2(v0, v1);
                } else if (EPI == 1) {
                    __half2 hh;
                    hh.x = __float2half(gelu_exact(v0));
                    hh.y = __float2half(gelu_exact(v1));
                    *(__half2*)&Ch[atile_idx(row, col, Nd64)] = hh;
                } else {
                    __half2 hh;
                    hh.x = __float2half(v0);
                    hh.y = __float2half(v1);
                    *(__half2*)&Ch[(size_t)row * N + col] = hh;
                }
            }
        }
    }
}

// ===========================================================================
// SMALL-TILE GEMM (N=1024, residual): CTA 128x128, 256 threads, BK=64,
// 3-stage, 2 CTAs/SM. A (tiled) + B (tiled) via bulk.
// ===========================================================================
#define ST_STG   (BT_TA + 16384)            // 32768
#define ST_SMEM  (3 * ST_STG + 64)

__global__ __launch_bounds__(256, 2) void tgemm_res_kernel(
    const __half* __restrict__ At, const __half* __restrict__ Bt,
    const float* __restrict__ bias, const float* __restrict__ res,
    float* __restrict__ Cf, int N, int K)
{
    extern __shared__ __align__(1024) unsigned char smem[];
    uint32_t sb = smem_u32(smem);
    int tid = threadIdx.x, wid = tid >> 5, lane = tid & 31;
    int bm = blockIdx.x * 128, bn = blockIdx.y * 128;
    int wm = wid & 1, wn = wid >> 1;
    int nkt = K >> 6;

    uint32_t stg[3] = {sb, sb + ST_STG, sb + 2u * ST_STG};
    uint32_t mb0 = sb + 3u * ST_STG;
    if (tid == 0) { MBAR_INIT(mb0, 1); MBAR_INIT(mb0 + 8, 1); MBAR_INIT(mb0 + 16, 1); }
    __syncthreads();

    int l7 = lane & 7, bA = lane >> 4, b1 = (lane >> 3) & 1;
    uint32_t a_row = (uint32_t)((wm * 64 + (lane & 15)) * 128);
    int rbase = (lane & 7) + ((lane >> 4) << 3);
    uint32_t brow0 = (uint32_t)(BT_TA + (wn * 32 + rbase) * 128);
    uint32_t brow1 = (uint32_t)(BT_TA + (wn * 32 + 16 + rbase) * 128);

    float acc[4][4][4];
#pragma unroll
    for (int i = 0; i < 4; i++)
#pragma unroll
        for (int j = 0; j < 4; j++)
#pragma unroll
            for (int e = 0; e < 4; e++) acc[i][j][e] = 0.f;

#pragma unroll
    for (int s = 0; s < 2; s++) {
        if (tid == 0) {
            MBAR_EXPECT(mb0 + s * 8, ST_STG);
            bulk_g2s(stg[s], At + ((size_t)(bm >> 7) * nkt + s) * 8192, BT_TA, mb0 + s * 8);
            bulk_g2s(stg[s] + BT_TA, Bt + ((size_t)(bn >> 7) * nkt + s) * 8192, 16384, mb0 + s * 8);
        }
    }

    int cur = 0, nxt = 2;
    int phbits = 0;
    for (int kt = 0; kt < nkt; kt++) {
        MBAR_WAIT(mb0 + cur * 8, (phbits >> cur) & 1);
        phbits ^= (1 << cur);
        __syncthreads();

        int kf = kt + 2;
        if (kf < nkt && tid == 0) {
            MBAR_EXPECT(mb0 + nxt * 8, ST_STG);
            bulk_g2s(stg[nxt], At + ((size_t)(bm >> 7) * nkt + kf) * 8192, BT_TA, mb0 + nxt * 8);
            bulk_g2s(stg[nxt] + BT_TA, Bt + ((size_t)(bn >> 7) * nkt + kf) * 8192, 16384, mb0 + nxt * 8);
        }

        uint32_t st = stg[cur];
        cur = (cur + 1) % 3; nxt = (nxt + 1) % 3;
#pragma unroll
        for (int ks = 0; ks < 4; ks++) {
            uint32_t gpA = (uint32_t)(((ks << 1) + bA) ^ l7) << 4;
            uint32_t gpB = (uint32_t)(((ks << 1) + b1) ^ l7) << 4;
            Frag4 ah[4];
#pragma unroll
            for (int mt = 0; mt < 4; mt++)
                ah[mt] = ldsm_x4(st + a_row + mt * 2048 + gpA);
            Frag4 bf0 = ldsm_x4(st + brow0 + gpB);
            Frag4 bf1 = ldsm_x4(st + brow1 + gpB);
#pragma unroll
            for (int mt = 0; mt < 4; mt++) {
                mma_f16(acc[mt][0], ah[mt], bf0.x, bf0.y);
                mma_f16(acc[mt][1], ah[mt], bf0.z, bf0.w);
                mma_f16(acc[mt][2], ah[mt], bf1.x, bf1.y);
                mma_f16(acc[mt][3], ah[mt], bf1.z, bf1.w);
            }
        }
        __syncthreads();
    }

    int row_in = lane >> 2;
    int col2   = (lane & 3) << 1;
#pragma unroll
    for (int mt = 0; mt < 4; mt++) {
#pragma unroll
        for (int nt = 0; nt < 4; nt++) {
            int col = bn + wn * 32 + nt * 8 + col2;
            float bx = bias[col], by = bias[col + 1];
#pragma unroll
            for (int half = 0; half < 2; half++) {
                int row = bm + wm * 64 + mt * 16 + row_in + half * 8;
                size_t off = (size_t)row * N + col;
                float2 rv = *(const float2*)&res[off];
                *(float2*)&Cf[off] = make_float2(acc[mt][nt][half * 2 + 0] + bx + rv.x,
                                                 acc[mt][nt][half * 2 + 1] + by + rv.y);
            }
        }
    }
}

// ===========================================================================
// Flash attention: qkv row-major fp16 [M,3E] -> o TILED fp16 [M,E]
// ===========================================================================
__global__ __launch_bounds__(128) void fattn_kernel(const __half* __restrict__ qkv,
                                                    __half* __restrict__ oh) {
    __shared__ __half Qs[64 * 72];
    __shared__ __half Ks[2][64 * 72];
    __shared__ __half Vs[2][64 * 72];

    int tid = threadIdx.x, wid = tid >> 5, lane = tid & 31;
    int qt = 31 - (blockIdx.x & 31);
    int bh = blockIdx.x >> 5;
    int b  = bh >> 4, hh = bh & 15;
    int q0 = qt * 64;

    for (int i = tid; i < 512; i += 128) {
        int r = i >> 3, c8 = (i & 7) << 3;
        *(uint4*)&Qs[r * 72 + c8] =
            *(const uint4*)(qkv + (size_t)(b * T_ + q0 + r) * 3072 + hh * 64 + c8);
    }
    __syncthreads();

    uint32_t qbase = smem_u32(Qs);
    Frag4 qf[4];
    {
        int rr = wid * 16 + (lane & 15);
#pragma unroll
        for (int kd = 0; kd < 4; kd++)
            qf[kd] = ldsm_x4(qbase + (uint32_t)(rr * 144 + kd * 32 + ((lane >> 4) << 4)));
    }

    uint32_t ksb[2] = {smem_u32(Ks[0]), smem_u32(Ks[1])};
    uint32_t vsb[2] = {smem_u32(Vs[0]), smem_u32(Vs[1])};

    float o[8][4];
#pragma unroll
    for (int t = 0; t < 8; t++)
#pragma unroll
        for (int e = 0; e < 4; e++) o[t][e] = 0.f;
    float m0 = -1e30f, m1 = -1e30f, l0 = 0.f, l1 = 0.f;

    const float SC = 0.18033688011f;
    int ntiles = qt + 1;

    for (int i = tid; i < 512; i += 128) {
        int r = i >> 3, c8 = (i & 7) << 3;
        size_t base = (size_t)(b * T_ + r) * 3072 + hh * 64 + c8;
        cpa16(ksb[0] + (uint32_t)(r * 144 + c8 * 2), qkv + base + 1024);
        cpa16(vsb[0] + (uint32_t)(r * 144 + c8 * 2), qkv + base + 2048);
    }
    CP_COMMIT();

    for (int t = 0; t < ntiles; t++) {
        if (t + 1 < ntiles) {
            int kb = (t + 1) * 64;
            int buf = (t + 1) & 1;
            for (int i = tid; i < 512; i += 128) {
                int r = i >> 3, c8 = (i & 7) << 3;
                size_t base = (size_t)(b * T_ + kb + r) * 3072 + hh * 64 + c8;
                cpa16(ksb[buf] + (uint32_t)(r * 144 + c8 * 2), qkv + base + 1024);
                cpa16(vsb[buf] + (uint32_t)(r * 144 + c8 * 2), qkv + base + 2048);
            }
            CP_COMMIT();
            CP_WAIT1();
        } else {
            CP_WAIT0();
        }
        __syncthreads();

        int buf = t & 1;
        uint32_t kb_s = ksb[buf], vb_s = vsb[buf];

        float s[8][4];
#pragma unroll
        for (int j = 0; j < 8; j++)
#pragma unroll
            for (int e = 0; e < 4; e++) s[j][e] = 0.f;
#pragma unroll
        for (int kd = 0; kd < 4; kd++) {
#pragma unroll
            for (int np = 0; np < 4; np++) {
                Frag4 bf = ldsm_x4(kb_s + (uint32_t)((np * 16 + (lane & 7) + ((lane >> 4) << 3)) * 144
                                                     + kd * 32 + (((lane >> 3) & 1) << 4)));
                mma_f16(s[np * 2],     qf[kd], bf.x, bf.y);
                mma_f16(s[np * 2 + 1], qf[kd], bf.z, bf.w);
            }
        }

#pragma unroll
        for (int j = 0; j < 8; j++)
#pragma unroll
            for (int e = 0; e < 4; e++) s[j][e] *= SC;

        if (t == qt) {
            int lr0 = wid * 16 + (lane >> 2);
#pragma unroll
            for (int j = 0; j < 8; j++) {
                int c = 8 * j + 2 * (lane & 3);
                if (c     > lr0)     s[j][0] = -1e30f;
                if (c + 1 > lr0)     s[j][1] = -1e30f;
                if (c     > lr0 + 8) s[j][2] = -1e30f;
                if (c + 1 > lr0 + 8) s[j][3] = -1e30f;
            }
        }

        float mr0 = -1e30f, mr1 = -1e30f;
#pragma unroll
        for (int j = 0; j < 8; j++) {
            mr0 = fmaxf(mr0, fmaxf(s[j][0], s[j][1]));
            mr1 = fmaxf(mr1, fmaxf(s[j][2], s[j][3]));
        }
        mr0 = fmaxf(mr0, __shfl_xor_sync(0xffffffffu, mr0, 1));
        mr0 = fmaxf(mr0, __shfl_xor_sync(0xffffffffu, mr0, 2));
        mr1 = fmaxf(mr1, __shfl_xor_sync(0xffffffffu, mr1, 1));
        mr1 = fmaxf(mr1, __shfl_xor_sync(0xffffffffu, mr1, 2));

        float nm0 = fmaxf(m0, mr0), nm1 = fmaxf(m1, mr1);
        float c0 = ex2f(m0 - nm0), c1 = ex2f(m1 - nm1);
        m0 = nm0; m1 = nm1;
        l0 *= c0; l1 *= c1;

        uint32_t pf[8][2];
        float ps0 = 0.f, ps1 = 0.f;
#pragma unroll
        for (int j = 0; j < 8; j++) {
            float p0 = ex2f(s[j][0] - m0), p1 = ex2f(s[j][1] - m0);
            float p2 = ex2f(s[j][2] - m1), p3 = ex2f(s[j][3] - m1);
            ps0 += p0 + p1; ps1 += p2 + p3;
            pf[j][0] = pkh2(p0, p1);
            pf[j][1] = pkh2(p2, p3);
        }
        l0 += ps0; l1 += ps1;

#pragma unroll
        for (int tt = 0; tt < 8; tt++) {
            o[tt][0] *= c0; o[tt][1] *= c0;
            o[tt][2] *= c1; o[tt][3] *= c1;
        }

#pragma unroll
        for (int j = 0; j < 4; j++) {
            uint32_t a0 = pf[2 * j][0],     a1 = pf[2 * j][1];
            uint32_t a2 = pf[2 * j + 1][0], a3 = pf[2 * j + 1][1];
#pragma unroll
            for (int t2 = 0; t2 < 4; t2++) {
                Frag4 vf = ldsm_x4_t(vb_s + (uint32_t)((j * 16 + (lane & 7) + (((lane >> 3) & 1) << 3)) * 144
                                                       + t2 * 32 + ((lane >> 4) << 4)));
                mma4(o[2 * t2],     a0, a1, a2, a3, vf.x, vf.y);
                mma4(o[2 * t2 + 1], a0, a1, a2, a3, vf.z, vf.w);
            }
        }
        __syncthreads();
    }

    l0 += __shfl_xor_sync(0xffffffffu, l0, 1);
    l0 += __shfl_xor_sync(0xffffffffu, l0, 2);
    l1 += __shfl_xor_sync(0xffffffffu, l1, 1);
    l1 += __shfl_xor_sync(0xffffffffu, l1, 2);
    float li0 = 1.0f / l0, li1 = 1.0f / l1;

    int r0g = q0 + wid * 16 + (lane >> 2);
    int dbase = hh * 64 + 2 * (lane & 3);
#pragma unroll
    for (int tt = 0; tt < 8; tt++) {
        int col = dbase + tt * 8;
        __half2 h01 = __floats2half2_rn(o[tt][0] * li0, o[tt][1] * li0);
        __half2 h23 = __floats2half2_rn(o[tt][2] * li1, o[tt][3] * li1);
        *(__half2*)&oh[atile_idx(b * T_ + r0g,     col, 16)] = h01;
        *(__half2*)&oh[atile_idx(b * T_ + r0g + 8, col, 16)] = h23;
    }
}

// ===========================================================================
// Weight tiling (unchanged from R14)
// ===========================================================================
__global__ void wtile_kernel(const float* __restrict__ W, __half* __restrict__ out,
                             int K, int N, int tshift,
                             size_t inLs, size_t outLs)
{
    __shared__ float s[64][65];
    const float* Wl = W + blockIdx.z * inLs;
    out += blockIdx.z * outLs;
    int n0 = blockIdx.x * 64, k0g = blockIdx.y;
    int tid = threadIdx.y * 32 + threadIdx.x;
    int nkt = K >> 6;
    int tileN = 1 << tshift;
#pragma unroll
    for (int i = 0; i < 16; i++) {
        int idx = tid + i * 256;
        int k = idx >> 6, n = idx & 63;
        s[k][n] = Wl[(size_t)(k0g * 64 + k) * N + n0 + n];
    }
    __syncthreads();
#pragma unroll
    for (int pass = 0; pass < 2; pass++) {
        int n = (tid >> 3) + pass * 32;
        int g = tid & 7;
        int gn = n0 + n;
        int tile = (gn >> tshift) * nkt + k0g;
        int nl = gn & (tileN - 1);
        uint32_t gp = (uint32_t)g ^ (uint32_t)(nl & 7);
        uint4 u;
        u.x = pkh2(s[g * 8 + 0][n], s[g * 8 + 1][n]);
        u.y = pkh2(s[g * 8 + 2][n], s[g * 8 + 3][n]);
        u.z = pkh2(s[g * 8 + 4][n], s[g * 8 + 5][n]);
        u.w = pkh2(s[g * 8 + 6][n], s[g * 8 + 7][n]);
        *(uint4*)&out[(size_t)tile * (tileN * 64) + nl * 64 + gp * 8] = u;
    }
}

__global__ void wtile_qkv_kernel(const float* __restrict__ Wq,
                                 const float* __restrict__ Wk,
                                 const float* __restrict__ Wv,
                                 __half* __restrict__ out)
{
    __shared__ float s[64][65];
    const size_t EE = (size_t)E_ * E_;
    int l = blockIdx.z;
    int gn0 = blockIdx.x * 64;
    int which = gn0 >> 10;
    const float* Wl = (which == 0 ? Wq : which == 1 ? Wk : Wv) + l * EE;
    int n0 = gn0 & 1023;
    int k0g = blockIdx.y;
    out += (size_t)l * 3 * EE;
    int tid = threadIdx.y * 32 + threadIdx.x;
#pragma unroll
    for (int i = 0; i < 16; i++) {
        int idx = tid + i * 256;
        int k = idx >> 6, n = idx & 63;
        s[k][n] = Wl[(size_t)(k0g * 64 + k) * E_ + n0 + n];
    }
    __syncthreads();
#pragma unroll
    for (int pass = 0; pass < 2; pass++) {
        int n = (tid >> 3) + pass * 32;
        int g = tid & 7;
        int gn = gn0 + n;
        int tile = (gn >> 8) * 16 + k0g;
        int nl = gn & 255;
        uint32_t gp = (uint32_t)g ^ (uint32_t)(nl & 7);
        uint4 u;
        u.x = pkh2(s[g * 8 + 0][n], s[g * 8 + 1][n]);
        u.y = pkh2(s[g * 8 + 2][n], s[g * 8 + 3][n]);
        u.z = pkh2(s[g * 8 + 4][n], s[g * 8 + 5][n]);
        u.w = pkh2(s[g * 8 + 6][n], s[g * 8 + 7][n]);
        *(uint4*)&out[(size_t)tile * (256 * 64) + nl * 64 + gp * 8] = u;
    }
}

__global__ void bpack_kernel(const float* __restrict__ bq, const float* __restrict__ bk,
                             const float* __restrict__ bv, float* __restrict__ out) {
    int i = blockIdx.x * 256 + threadIdx.x;
    int l = i / 3072, j = i % 3072;
    float v = (j < 1024) ? bq[l * 1024 + j]
            : (j < 2048) ? bk[l * 1024 + j - 1024]
                         : bv[l * 1024 + j - 2048];
    out[i] = v;
}

// ---------------------------------------------------------------------------
// Embedding / LayerNorm (warp-per-row; LN writes TILED fp16)
// ---------------------------------------------------------------------------
__global__ void embed_kernel(const int* __restrict__ x, const float* __restrict__ tok,
                             const float* __restrict__ pos, float* __restrict__ h) {
    int i = blockIdx.x * 256 + threadIdx.x;
    int row = i >> 8, e4 = (i & 255) << 2;
    int tkn = x[row];
    int t = row & (T_ - 1);
    float4 a = *(const float4*)(tok + (size_t)tkn * E_ + e4);
    float4 p = *(const float4*)(pos + (size_t)t * E_ + e4);
    *(float4*)(h + (size_t)row * E_ + e4) =
        make_float4(a.x + p.x, a.y + p.y, a.z + p.z, a.w + p.w);
}

__global__ __launch_bounds__(256) void ln_kernel(const float* __restrict__ in,
                                                 const float* __restrict__ gam,
                                                 const float* __restrict__ bet,
                                                 __half* __restrict__ outh) {
    int row = blockIdx.x * 8 + (threadIdx.x >> 5);
    int lane = threadIdx.x & 31;
    const float4* rp = (const float4*)(in + (size_t)row * E_) + lane;
    float4 v[8];
    float s = 0.f, sq = 0.f;
#pragma unroll
    for (int i = 0; i < 8; i++) {
        v[i] = rp[i * 32];
        s  += v[i].x + v[i].y + v[i].z + v[i].w;
        sq += v[i].x * v[i].x + v[i].y * v[i].y + v[i].z * v[i].z + v[i].w * v[i].w;
    }
#pragma unroll
    for (int o = 16; o > 0; o >>= 1) {
        s  += __shfl_xor_sync(0xffffffffu, s,  o);
        sq += __shfl_xor_sync(0xffffffffu, sq, o);
    }
    float mean = s * (1.0f / E_);
    float var  = sq * (1.0f / E_) - mean * mean;
    float rstd = rsqrtf(var + 1e-5f);

#pragma unroll
    for (int i = 0; i < 8; i++) {
        int e = (lane + i * 32) * 4;   // col of first of 4 halves
        float4 g = *(const float4*)(gam + e);
        float4 bb = *(const float4*)(bet + e);
        __half2 h0 = __floats2half2_rn((v[i].x - mean) * rstd * g.x + bb.x,
                                       (v[i].y - mean) * rstd * g.y + bb.y);
        __half2 h1 = __floats2half2_rn((v[i].z - mean) * rstd * g.z + bb.z,
                                       (v[i].w - mean) * rstd * g.w + bb.w);
        size_t a0 = atile_idx(row, e, 16);   // e%8 in {0,4}: both halves same granule
        *(__half2*)&outh[a0]     = h0;
        *(__half2*)&outh[a0 + 2] = h1;
    }
}

// ---------------------------------------------------------------------------
// Host orchestration
// ---------------------------------------------------------------------------
extern "C" void kernel_launch(void* const* d_in, const int* in_sizes, int n_in,
                              void* d_out, int out_size) {
    const int*   x    = (const int*)  d_in[0];
    const float* tok  = (const float*)d_in[1];
    const float* pos  = (const float*)d_in[2];
    const float* Wq   = (const float*)d_in[3];
    const float* bq   = (const float*)d_in[4];
    const float* Wk   = (const float*)d_in[5];
    const float* bk   = (const float*)d_in[6];
    const float* Wv   = (const float*)d_in[7];
    const float* bv   = (const float*)d_in[8];
    const float* Wo   = (const float*)d_in[9];
    const float* bo   = (const float*)d_in[10];
    const float* ln1g = (const float*)d_in[11];
    const float* ln1b = (const float*)d_in[12];
    const float* W1   = (const float*)d_in[13];
    const float* b1   = (const float*)d_in[14];
    const float* W2   = (const float*)d_in[15];
    const float* b2   = (const float*)d_in[16];
    const float* ln2g = (const float*)d_in[17];
    const float* ln2b = (const float*)d_in[18];
    const float* lnfg = (const float*)d_in[19];
    const float* lnfb = (const float*)d_in[20];
    const float* Wout = (const float*)d_in[21];
    const float* bout = (const float*)d_in[22];
    float* out = (float*)d_out;

    float *h, *bqkv;
    __half *qkvh, *xn, *o, *mlp;
    __half *qkvT, *woT, *w1T, *w2T, *wouT;
    cudaGetSymbolAddress((void**)&h,    g_h);
    cudaGetSymbolAddress((void**)&qkvh, g_qkv);
    cudaGetSymbolAddress((void**)&bqkv, g_bqkv);
    cudaGetSymbolAddress((void**)&xn,   g_xn);
    cudaGetSymbolAddress((void**)&o,    g_o);
    cudaGetSymbolAddress((void**)&mlp,  g_mlp);
    cudaGetSymbolAddress((void**)&qkvT, g_qkvT);
    cudaGetSymbolAddress((void**)&woT,  g_woT);
    cudaGetSymbolAddress((void**)&w1T,  g_w1T);
    cudaGetSymbolAddress((void**)&w2T,  g_w2T);
    cudaGetSymbolAddress((void**)&wouT, g_woutT);

    cudaFuncSetAttribute((const void*)btgemm_kernel<0>, cudaFuncAttributeMaxDynamicSharedMemorySize, BT_SMEM);
    cudaFuncSetAttribute((const void*)btgemm_kernel<1>, cudaFuncAttributeMaxDynamicSharedMemorySize, BT_SMEM);
    cudaFuncSetAttribute((const void*)btgemm_kernel<2>, cudaFuncAttributeMaxDynamicSharedMemorySize, BT_SMEM);
    cudaFuncSetAttribute((const void*)tgemm_res_kernel, cudaFuncAttributeMaxDynamicSharedMemorySize, ST_SMEM);

    const size_t EE = (size_t)E_ * E_, EF = (size_t)E_ * F_;
    dim3 tb(32, 8);

    embed_kernel<<<(M_ * E_) / (256 * 4), 256>>>(x, tok, pos, h);                    // 0
    wtile_qkv_kernel<<<dim3(48, 16, L_), tb>>>(Wq, Wk, Wv, qkvT);                    // 1
    bpack_kernel<<<(L_ * 3 * E_) / 256, 256>>>(bq, bk, bv, bqkv);                    // 2
    ln_kernel<<<M_ / 8, 256>>>(h, ln1g, ln1b, xn);                                   // 3
    btgemm_kernel<2><<<dim3(M_ / 128, 12), 512, BT_SMEM>>>(                          // 4
        xn, qkvT, bqkv, nullptr, qkvh, 3 * E_, E_);
    wtile_kernel<<<dim3(16, 16, L_), tb>>>(Wo, woT, E_, E_, 7, EE, EE);              // 5
    wtile_kernel<<<dim3(64, 16, L_), tb>>>(W1, w1T, E_, F_, 8, EF, EF);              // 6
    wtile_kernel<<<dim3(16, 64, L_), tb>>>(W2, w2T, F_, E_, 7, EF, EF);              // 7
    wtile_kernel<<<dim3(500, 16, 1), tb>>>(Wout, wouT, E_, V_, 8, 0, 0);             // 8

    for (int l = 0; l < L_; l++) {
        if (l > 0) {
            ln_kernel<<<M_ / 8, 256>>>(h, ln1g + l * E_, ln1b + l * E_, xn);
            btgemm_kernel<2><<<dim3(M_ / 128, 12), 512, BT_SMEM>>>(
                xn, qkvT + l * 3 * EE, bqkv + l * 3 * E_, nullptr, qkvh, 3 * E_, E_);
        }
        fattn_kernel<<<B_ * H_ * (T_ / 64), 128>>>(qkvh, o);
        tgemm_res_kernel<<<dim3(M_ / 128, 8), 256, ST_SMEM>>>(
            o, woT + l * EE, bo + l * E_, h, h, E_, E_);
        ln_kernel<<<M_ / 8, 256>>>(h, ln2g + l * E_, ln2b + l * E_, xn);
        btgemm_kernel<1><<<dim3(M_ / 128, F_ / 256), 512, BT_SMEM>>>(
            xn, w1T + l * EF, b1 + l * F_, nullptr, mlp, F_, E_);
        tgemm_res_kernel<<<dim3(M_ / 128, 8), 256, ST_SMEM>>>(
            mlp, w2T + l * EF, b2 + l * E_, h, h, E_, F_);
    }

    ln_kernel<<<M_ / 8, 256>>>(h, lnfg, lnfb, xn);
    btgemm_kernel<0><<<dim3(M_ / 128, V_ / 256), 512, BT_SMEM>>>(
        xn, wouT, bout, out, nullptr, V_, E_);
}

// round 16
// speedup vs baseline: 1.7230x; 1.0304x over previous
#include <cuda_runtime.h>
#include <cuda_fp16.h>
#include <math.h>
#include <stdint.h>

// Problem dims
#define V_ 32000
#define E_ 1024
#define H_ 16
#define F_ 4096
#define L_ 4
#define T_ 2048
#define B_ 2
#define D_ 64
#define M_ (B_*T_)   // 4096

// ---------------------------------------------------------------------------
// Scratch. Activations xn/o/mlp TILED (128 rows x 64 cols, dense 128B rows,
// granule XOR swizzle g^(r&7)). K/V stored per (b,h) in 64-key x 64-dim tiles.
// ---------------------------------------------------------------------------
__device__ float g_h  [M_*E_];
__device__ __half g_q  [M_*E_];        // Q row-major [M,1024]
__device__ __half g_kt [(size_t)B_*H_*T_*D_];   // K tiled
__device__ __half g_vt [(size_t)B_*H_*T_*D_];   // V tiled
__device__ float g_bqkv[L_*3*E_];
__device__ __half g_xn [M_*E_];        // tiled
__device__ __half g_o  [M_*E_];        // tiled
__device__ __half g_mlp[M_*F_];        // tiled
__device__ __half g_qkvT[L_*3*E_*E_];
__device__ __half g_woT [L_*E_*E_];
__device__ __half g_w1T [L_*F_*E_];
__device__ __half g_w2T [L_*E_*F_];
__device__ __half g_woutT[(size_t)V_*E_];

// ---------------------------------------------------------------------------
// PTX helpers
// ---------------------------------------------------------------------------
__device__ __forceinline__ uint32_t smem_u32(const void* p) {
    uint32_t a;
    asm("{ .reg .u64 t; cvta.to.shared.u64 t, %1; cvt.u32.u64 %0, t; }" : "=r"(a) : "l"(p));
    return a;
}
#define MBAR_INIT(a, c) asm volatile("mbarrier.init.shared.b64 [%0], %1;" :: "r"((uint32_t)(a)), "r"((uint32_t)(c)) : "memory")
#define MBAR_EXPECT(a, n) asm volatile("mbarrier.arrive.expect_tx.shared.b64 _, [%0], %1;" :: "r"((uint32_t)(a)), "r"((uint32_t)(n)) : "memory")
static __device__ __forceinline__ void bulk_g2s(uint32_t s, const void* g, uint32_t bytes, uint32_t mbar) {
    asm volatile("cp.async.bulk.shared::cta.global.mbarrier::complete_tx::bytes [%0], [%1], %2, [%3];"
                 :: "r"(s), "l"(g), "r"(bytes), "r"(mbar) : "memory");
}
#define MBAR_WAIT(addr, par) do {                                              \
    uint32_t _m = (uint32_t)(addr), _p = (uint32_t)(par), _d;                  \
    asm volatile("{\n\t.reg .pred p;\n\t"                                      \
        "mbarrier.try_wait.parity.shared.b64 p, [%1], %2;\n\t"                 \
        "selp.b32 %0, 1, 0, p;\n\t}" : "=r"(_d) : "r"(_m), "r"(_p) : "memory");\
    if (!_d) {                                                                 \
        asm volatile("{\n\t.reg .pred P1;\n\t"                                 \
            "WL_%=:\n\t"                                                       \
            "mbarrier.try_wait.parity.shared.b64 P1, [%0], %1;\n\t"            \
            "@P1 bra.uni WD_%=;\n\t"                                           \
            "bra.uni WL_%=;\n\t"                                               \
            "WD_%=:\n\t}" :: "r"(_m), "r"(_p) : "memory");                     \
    }                                                                          \
} while (0)

struct Frag4 { uint32_t x, y, z, w; };

static __device__ __forceinline__ Frag4 ldsm_x4(uint32_t addr) {
    Frag4 r;
    asm volatile("ldmatrix.sync.aligned.m8n8.x4.shared.b16 {%0,%1,%2,%3}, [%4];"
                 : "=r"(r.x), "=r"(r.y), "=r"(r.z), "=r"(r.w) : "r"(addr));
    return r;
}
static __device__ __forceinline__ Frag4 ldsm_x4_t(uint32_t addr) {
    Frag4 r;
    asm volatile("ldmatrix.sync.aligned.m8n8.x4.trans.shared.b16 {%0,%1,%2,%3}, [%4];"
                 : "=r"(r.x), "=r"(r.y), "=r"(r.z), "=r"(r.w) : "r"(addr));
    return r;
}

static __device__ __forceinline__ void mma_f16(float* c, const Frag4& a,
                                               uint32_t b0, uint32_t b1) {
    asm volatile(
        "mma.sync.aligned.m16n8k16.row.col.f32.f16.f16.f32 "
        "{%0,%1,%2,%3}, {%4,%5,%6,%7}, {%8,%9}, {%0,%1,%2,%3};"
        : "+f"(c[0]), "+f"(c[1]), "+f"(c[2]), "+f"(c[3])
        : "r"(a.x), "r"(a.y), "r"(a.z), "r"(a.w), "r"(b0), "r"(b1));
}
static __device__ __forceinline__ void mma4(float* c, uint32_t a0, uint32_t a1,
                                            uint32_t a2, uint32_t a3,
                                            uint32_t b0, uint32_t b1) {
    asm volatile(
        "mma.sync.aligned.m16n8k16.row.col.f32.f16.f16.f32 "
        "{%0,%1,%2,%3}, {%4,%5,%6,%7}, {%8,%9}, {%0,%1,%2,%3};"
        : "+f"(c[0]), "+f"(c[1]), "+f"(c[2]), "+f"(c[3])
        : "r"(a0), "r"(a1), "r"(a2), "r"(a3), "r"(b0), "r"(b1));
}

static __device__ __forceinline__ float ex2f(float x) {
    float y;
    asm("ex2.approx.ftz.f32 %0, %1;" : "=f"(y) : "f"(x));
    return y;
}
static __device__ __forceinline__ uint32_t pkh2(float a, float b) {
    __half2 h = __floats2half2_rn(a, b);
    return *(uint32_t*)&h;
}
__device__ __forceinline__ float gelu_exact(float x) {
    return 0.5f * x * (1.0f + erff(x * 0.70710678118654752f));
}

// half index into tiled activation of width K (tiles of 128x64)
static __device__ __forceinline__ size_t atile_idx(int row, int col, int Kd64) {
    int gp = ((col >> 3) & 7) ^ (row & 7);
    return ((size_t)(row >> 7) * Kd64 + (col >> 6)) * 8192
           + (size_t)(row & 127) * 64 + gp * 8 + (col & 7);
}

// ===========================================================================
// BIG-TILE GEMM: CTA 128x256, 512 threads, warptile 64x32, BK=64, 3-stage,
// A+B tiled via cp.async.bulk. EPI: 0 fp32+bias ; 1 gelu->fp16 tiled ;
// 3 QKV (q row-major + K/V head-tiled scatter)
// ===========================================================================
#define BT_TA    16384
#define BT_TB    32768
#define BT_STG   (BT_TA + BT_TB)            // 49152
#define BT_SMEM  (3 * BT_STG + 64)

template<int EPI>
__global__ __launch_bounds__(512, 1) void btgemm_kernel(
    const __half* __restrict__ At, const __half* __restrict__ Bt,
    const float* __restrict__ bias,
    float* __restrict__ Cf, __half* __restrict__ Ch,
    __half* __restrict__ Kt, __half* __restrict__ Vt,
    int N, int K)
{
    extern __shared__ __align__(1024) unsigned char smem[];
    uint32_t sb = smem_u32(smem);
    int tid = threadIdx.x, wid = tid >> 5, lane = tid & 31;
    int bm = blockIdx.x * 128, bn = blockIdx.y * 256;
    int wm = wid & 1, wn = wid >> 1;
    int nkt = K >> 6;

    uint32_t stg[3] = {sb, sb + BT_STG, sb + 2u * BT_STG};
    uint32_t mb0 = sb + 3u * BT_STG;
    if (tid == 0) { MBAR_INIT(mb0, 1); MBAR_INIT(mb0 + 8, 1); MBAR_INIT(mb0 + 16, 1); }
    __syncthreads();

    int l7 = lane & 7, bA = lane >> 4, b1 = (lane >> 3) & 1;
    uint32_t a_row = (uint32_t)((wm * 64 + (lane & 15)) * 128);
    int rbase = (lane & 7) + ((lane >> 4) << 3);
    uint32_t brow0 = (uint32_t)(BT_TA + (wn * 32 + rbase) * 128);
    uint32_t brow1 = (uint32_t)(BT_TA + (wn * 32 + 16 + rbase) * 128);

    float acc[4][4][4];
#pragma unroll
    for (int i = 0; i < 4; i++)
#pragma unroll
        for (int j = 0; j < 4; j++)
#pragma unroll
            for (int e = 0; e < 4; e++) acc[i][j][e] = 0.f;

#pragma unroll
    for (int s = 0; s < 2; s++) {
        if (tid == 0) {
            MBAR_EXPECT(mb0 + s * 8, BT_STG);
            bulk_g2s(stg[s], At + ((size_t)(bm >> 7) * nkt + s) * 8192, BT_TA, mb0 + s * 8);
            bulk_g2s(stg[s] + BT_TA, Bt + ((size_t)(bn >> 8) * nkt + s) * 16384, BT_TB, mb0 + s * 8);
        }
    }

    int cur = 0, nxt = 2;
    int phbits = 0;
    for (int kt = 0; kt < nkt; kt++) {
        MBAR_WAIT(mb0 + cur * 8, (phbits >> cur) & 1);
        phbits ^= (1 << cur);
        __syncthreads();

        int kf = kt + 2;
        if (kf < nkt && tid == 0) {
            MBAR_EXPECT(mb0 + nxt * 8, BT_STG);
            bulk_g2s(stg[nxt], At + ((size_t)(bm >> 7) * nkt + kf) * 8192, BT_TA, mb0 + nxt * 8);
            bulk_g2s(stg[nxt] + BT_TA, Bt + ((size_t)(bn >> 8) * nkt + kf) * 16384, BT_TB, mb0 + nxt * 8);
        }

        uint32_t st = stg[cur];
        cur = (cur + 1) % 3; nxt = (nxt + 1) % 3;
#pragma unroll
        for (int ks = 0; ks < 4; ks++) {
            uint32_t gpA = (uint32_t)(((ks << 1) + bA) ^ l7) << 4;
            uint32_t gpB = (uint32_t)(((ks << 1) + b1) ^ l7) << 4;
            Frag4 ah[4];
#pragma unroll
            for (int mt = 0; mt < 4; mt++)
                ah[mt] = ldsm_x4(st + a_row + mt * 2048 + gpA);
            Frag4 bf0 = ldsm_x4(st + brow0 + gpB);
            Frag4 bf1 = ldsm_x4(st + brow1 + gpB);
#pragma unroll
            for (int mt = 0; mt < 4; mt++) {
                mma_f16(acc[mt][0], ah[mt], bf0.x, bf0.y);
                mma_f16(acc[mt][1], ah[mt], bf0.z, bf0.w);
                mma_f16(acc[mt][2], ah[mt], bf1.x, bf1.y);
                mma_f16(acc[mt][3], ah[mt], bf1.z, bf1.w);
            }
        }
    }
    __syncthreads();

    int row_in = lane >> 2;
    int col2   = (lane & 3) << 1;
    int Nd64 = N >> 6;
#pragma unroll
    for (int mt = 0; mt < 4; mt++) {
#pragma unroll
        for (int nt = 0; nt < 4; nt++) {
            int col = bn + wn * 32 + nt * 8 + col2;
            float bx = bias[col], by = bias[col + 1];
#pragma unroll
            for (int half = 0; half < 2; half++) {
                int row = bm + wm * 64 + mt * 16 + row_in + half * 8;
                float v0 = acc[mt][nt][half * 2 + 0] + bx;
                float v1 = acc[mt][nt][half * 2 + 1] + by;
                if (EPI == 0) {
                    *(float2*)&Cf[(size_t)row * N + col] = make_float2(v0, v1);
                } else if (EPI == 1) {
                    __half2 hh;
                    hh.x = __float2half(gelu_exact(v0));
                    hh.y = __float2half(gelu_exact(v1));
                    *(__half2*)&Ch[atile_idx(row, col, Nd64)] = hh;
                } else {
                    __half2 hh;
                    hh.x = __float2half(v0);
                    hh.y = __float2half(v1);
                    int which = col >> 10;
                    if (which == 0) {
                        *(__half2*)&Ch[(size_t)row * 1024 + col] = hh;
                    } else {
                        int d = col & 1023;
                        int hhd = d >> 6, dl = d & 63;
                        int bb = row >> 11, key = row & 2047;
                        size_t base = ((size_t)((bb * 16 + hhd) * 32 + (key >> 6))) * 4096;
                        int gp = ((dl >> 3) ^ (key & 7)) & 7;
                        size_t idx = base + (size_t)(key & 63) * 64 + gp * 8 + (dl & 7);
                        __half* dst = (which == 1) ? Kt : Vt;
                        *(__half2*)&dst[idx] = hh;
                    }
                }
            }
        }
    }
}

// ===========================================================================
// SMALL-TILE GEMM (N=1024, residual): CTA 128x128, 256 threads, BK=64,
// 3-stage, 2 CTAs/SM.
// ===========================================================================
#define ST_STG   (BT_TA + 16384)            // 32768
#define ST_SMEM  (3 * ST_STG + 64)

__global__ __launch_bounds__(256, 2) void tgemm_res_kernel(
    const __half* __restrict__ At, const __half* __restrict__ Bt,
    const float* __restrict__ bias, const float* __restrict__ res,
    float* __restrict__ Cf, int N, int K)
{
    extern __shared__ __align__(1024) unsigned char smem[];
    uint32_t sb = smem_u32(smem);
    int tid = threadIdx.x, wid = tid >> 5, lane = tid & 31;
    int bm = blockIdx.x * 128, bn = blockIdx.y * 128;
    int wm = wid & 1, wn = wid >> 1;
    int nkt = K >> 6;

    uint32_t stg[3] = {sb, sb + ST_STG, sb + 2u * ST_STG};
    uint32_t mb0 = sb + 3u * ST_STG;
    if (tid == 0) { MBAR_INIT(mb0, 1); MBAR_INIT(mb0 + 8, 1); MBAR_INIT(mb0 + 16, 1); }
    __syncthreads();

    int l7 = lane & 7, bA = lane >> 4, b1 = (lane >> 3) & 1;
    uint32_t a_row = (uint32_t)((wm * 64 + (lane & 15)) * 128);
    int rbase = (lane & 7) + ((lane >> 4) << 3);
    uint32_t brow0 = (uint32_t)(BT_TA + (wn * 32 + rbase) * 128);
    uint32_t brow1 = (uint32_t)(BT_TA + (wn * 32 + 16 + rbase) * 128);

    float acc[4][4][4];
#pragma unroll
    for (int i = 0; i < 4; i++)
#pragma unroll
        for (int j = 0; j < 4; j++)
#pragma unroll
            for (int e = 0; e < 4; e++) acc[i][j][e] = 0.f;

#pragma unroll
    for (int s = 0; s < 2; s++) {
        if (tid == 0) {
            MBAR_EXPECT(mb0 + s * 8, ST_STG);
            bulk_g2s(stg[s], At + ((size_t)(bm >> 7) * nkt + s) * 8192, BT_TA, mb0 + s * 8);
            bulk_g2s(stg[s] + BT_TA, Bt + ((size_t)(bn >> 7) * nkt + s) * 8192, 16384, mb0 + s * 8);
        }
    }

    int cur = 0, nxt = 2;
    int phbits = 0;
    for (int kt = 0; kt < nkt; kt++) {
        MBAR_WAIT(mb0 + cur * 8, (phbits >> cur) & 1);
        phbits ^= (1 << cur);
        __syncthreads();

        int kf = kt + 2;
        if (kf < nkt && tid == 0) {
            MBAR_EXPECT(mb0 + nxt * 8, ST_STG);
            bulk_g2s(stg[nxt], At + ((size_t)(bm >> 7) * nkt + kf) * 8192, BT_TA, mb0 + nxt * 8);
            bulk_g2s(stg[nxt] + BT_TA, Bt + ((size_t)(bn >> 7) * nkt + kf) * 8192, 16384, mb0 + nxt * 8);
        }

        uint32_t st = stg[cur];
        cur = (cur + 1) % 3; nxt = (nxt + 1) % 3;
#pragma unroll
        for (int ks = 0; ks < 4; ks++) {
            uint32_t gpA = (uint32_t)(((ks << 1) + bA) ^ l7) << 4;
            uint32_t gpB = (uint32_t)(((ks << 1) + b1) ^ l7) << 4;
            Frag4 ah[4];
#pragma unroll
            for (int mt = 0; mt < 4; mt++)
                ah[mt] = ldsm_x4(st + a_row + mt * 2048 + gpA);
            Frag4 bf0 = ldsm_x4(st + brow0 + gpB);
            Frag4 bf1 = ldsm_x4(st + brow1 + gpB);
#pragma unroll
            for (int mt = 0; mt < 4; mt++) {
                mma_f16(acc[mt][0], ah[mt], bf0.x, bf0.y);
                mma_f16(acc[mt][1], ah[mt], bf0.z, bf0.w);
                mma_f16(acc[mt][2], ah[mt], bf1.x, bf1.y);
                mma_f16(acc[mt][3], ah[mt], bf1.z, bf1.w);
            }
        }
    }
    __syncthreads();

    int row_in = lane >> 2;
    int col2   = (lane & 3) << 1;
#pragma unroll
    for (int mt = 0; mt < 4; mt++) {
#pragma unroll
        for (int nt = 0; nt < 4; nt++) {
            int col = bn + wn * 32 + nt * 8 + col2;
            float bx = bias[col], by = bias[col + 1];
#pragma unroll
            for (int half = 0; half < 2; half++) {
                int row = bm + wm * 64 + mt * 16 + row_in + half * 8;
                size_t off = (size_t)row * N + col;
                float2 rv = *(const float2*)&res[off];
                *(float2*)&Cf[off] = make_float2(acc[mt][nt][half * 2 + 0] + bx + rv.x,
                                                 acc[mt][nt][half * 2 + 1] + by + rv.y);
            }
        }
    }
}

// ===========================================================================
// Flash attention: Q row-major [M,1024]; K/V tiled per (b,h) in 64x64 tiles,
// loaded via cp.async.bulk. Output o TILED.
// ===========================================================================
__global__ __launch_bounds__(128) void fattn_kernel(const __half* __restrict__ qh,
                                                    const __half* __restrict__ Kt,
                                                    const __half* __restrict__ Vt,
                                                    __half* __restrict__ oh) {
    __shared__ __align__(128) __half Qs[64 * 72];
    __shared__ __align__(128) __half Ksm[2][4096];
    __shared__ __align__(128) __half Vsm[2][4096];
    __shared__ __align__(8) uint64_t mbar[2];

    int tid = threadIdx.x, wid = tid >> 5, lane = tid & 31;
    int qt = 31 - (blockIdx.x & 31);
    int bh = blockIdx.x >> 5;
    int b  = bh >> 4, hh = bh & 15;
    int q0 = qt * 64;
    size_t kvbase = (size_t)((b * 16 + hh) * 32) * 4096;

    uint32_t mb = smem_u32(mbar);
    if (tid == 0) { MBAR_INIT(mb, 1); MBAR_INIT(mb + 8, 1); }

    for (int i = tid; i < 512; i += 128) {
        int r = i >> 3, c8 = (i & 7) << 3;
        *(uint4*)&Qs[r * 72 + c8] =
            *(const uint4*)(qh + (size_t)(b * T_ + q0 + r) * 1024 + hh * 64 + c8);
    }
    __syncthreads();

    uint32_t qbase = smem_u32(Qs);
    Frag4 qf[4];
    {
        int rr = wid * 16 + (lane & 15);
#pragma unroll
        for (int kd = 0; kd < 4; kd++)
            qf[kd] = ldsm_x4(qbase + (uint32_t)(rr * 144 + kd * 32 + ((lane >> 4) << 4)));
    }

    uint32_t ksb[2] = {smem_u32(Ksm[0]), smem_u32(Ksm[1])};
    uint32_t vsb[2] = {smem_u32(Vsm[0]), smem_u32(Vsm[1])};

    float o[8][4];
#pragma unroll
    for (int t = 0; t < 8; t++)
#pragma unroll
        for (int e = 0; e < 4; e++) o[t][e] = 0.f;
    float m0 = -1e30f, m1 = -1e30f, l0 = 0.f, l1 = 0.f;

    const float SC = 0.18033688011f;
    int ntiles = qt + 1;
    int l7 = lane & 7, b1 = (lane >> 3) & 1;
    int rbase = (lane & 7) + ((lane >> 4) << 3);

    if (tid == 0) {
        MBAR_EXPECT(mb, 16384);
        bulk_g2s(ksb[0], Kt + kvbase, 8192, mb);
        bulk_g2s(vsb[0], Vt + kvbase, 8192, mb);
    }

    int phbits = 0;
    for (int t = 0; t < ntiles; t++) {
        int buf = t & 1;
        if (t + 1 < ntiles && tid == 0) {
            int nb = (t + 1) & 1;
            MBAR_EXPECT(mb + nb * 8, 16384);
            bulk_g2s(ksb[nb], Kt + kvbase + (size_t)(t + 1) * 4096, 8192, mb + nb * 8);
            bulk_g2s(vsb[nb], Vt + kvbase + (size_t)(t + 1) * 4096, 8192, mb + nb * 8);
        }
        MBAR_WAIT(mb + buf * 8, (phbits >> buf) & 1);
        phbits ^= (1 << buf);

        uint32_t kb_s = ksb[buf], vb_s = vsb[buf];

        float s[8][4];
#pragma unroll
        for (int j = 0; j < 8; j++)
#pragma unroll
            for (int e = 0; e < 4; e++) s[j][e] = 0.f;
#pragma unroll
        for (int kd = 0; kd < 4; kd++) {
            uint32_t gp = (uint32_t)(((kd << 1) + b1) ^ l7) << 4;
#pragma unroll
            for (int np = 0; np < 4; np++) {
                Frag4 bf = ldsm_x4(kb_s + (uint32_t)((np * 16 + rbase) * 128) + gp);
                mma_f16(s[np * 2],     qf[kd], bf.x, bf.y);
                mma_f16(s[np * 2 + 1], qf[kd], bf.z, bf.w);
            }
        }

#pragma unroll
        for (int j = 0; j < 8; j++)
#pragma unroll
            for (int e = 0; e < 4; e++) s[j][e] *= SC;

        if (t == qt) {
            int lr0 = wid * 16 + (lane >> 2);
#pragma unroll
            for (int j = 0; j < 8; j++) {
                int c = 8 * j + 2 * (lane & 3);
                if (c     > lr0)     s[j][0] = -1e30f;
                if (c + 1 > lr0)     s[j][1] = -1e30f;
                if (c     > lr0 + 8) s[j][2] = -1e30f;
                if (c + 1 > lr0 + 8) s[j][3] = -1e30f;
            }
        }

        float mr0 = -1e30f, mr1 = -1e30f;
#pragma unroll
        for (int j = 0; j < 8; j++) {
            mr0 = fmaxf(mr0, fmaxf(s[j][0], s[j][1]));
            mr1 = fmaxf(mr1, fmaxf(s[j][2], s[j][3]));
        }
        mr0 = fmaxf(mr0, __shfl_xor_sync(0xffffffffu, mr0, 1));
        mr0 = fmaxf(mr0, __shfl_xor_sync(0xffffffffu, mr0, 2));
        mr1 = fmaxf(mr1, __shfl_xor_sync(0xffffffffu, mr1, 1));
        mr1 = fmaxf(mr1, __shfl_xor_sync(0xffffffffu, mr1, 2));

        float nm0 = fmaxf(m0, mr0), nm1 = fmaxf(m1, mr1);
        float c0 = ex2f(m0 - nm0), c1 = ex2f(m1 - nm1);
        m0 = nm0; m1 = nm1;
        l0 *= c0; l1 *= c1;

        uint32_t pf[8][2];
        float ps0 = 0.f, ps1 = 0.f;
#pragma unroll
        for (int j = 0; j < 8; j++) {
            float p0 = ex2f(s[j][0] - m0), p1 = ex2f(s[j][1] - m0);
            float p2 = ex2f(s[j][2] - m1), p3 = ex2f(s[j][3] - m1);
            ps0 += p0 + p1; ps1 += p2 + p3;
            pf[j][0] = pkh2(p0, p1);
            pf[j][1] = pkh2(p2, p3);
        }
        l0 += ps0; l1 += ps1;

#pragma unroll
        for (int tt = 0; tt < 8; tt++) {
            o[tt][0] *= c0; o[tt][1] *= c0;
            o[tt][2] *= c1; o[tt][3] *= c1;
        }

#pragma unroll
        for (int j = 0; j < 4; j++) {
            uint32_t a0 = pf[2 * j][0],     a1 = pf[2 * j][1];
            uint32_t a2 = pf[2 * j + 1][0], a3 = pf[2 * j + 1][1];
            int vrow = j * 16 + (lane & 7) + (((lane >> 3) & 1) << 3);
#pragma unroll
            for (int t2 = 0; t2 < 4; t2++) {
                uint32_t g = (uint32_t)(((t2 << 1) + (lane >> 4)) ^ l7) << 4;
                Frag4 vf = ldsm_x4_t(vb_s + (uint32_t)(vrow * 128) + g);
                mma4(o[2 * t2],     a0, a1, a2, a3, vf.x, vf.y);
                mma4(o[2 * t2 + 1], a0, a1, a2, a3, vf.z, vf.w);
            }
        }
        __syncthreads();
    }

    l0 += __shfl_xor_sync(0xffffffffu, l0, 1);
    l0 += __shfl_xor_sync(0xffffffffu, l0, 2);
    l1 += __shfl_xor_sync(0xffffffffu, l1, 1);
    l1 += __shfl_xor_sync(0xffffffffu, l1, 2);
    float li0 = 1.0f / l0, li1 = 1.0f / l1;

    int r0g = q0 + wid * 16 + (lane >> 2);
    int dbase = hh * 64 + 2 * (lane & 3);
#pragma unroll
    for (int tt = 0; tt < 8; tt++) {
        int col = dbase + tt * 8;
        __half2 h01 = __floats2half2_rn(o[tt][0] * li0, o[tt][1] * li0);
        __half2 h23 = __floats2half2_rn(o[tt][2] * li1, o[tt][3] * li1);
        *(__half2*)&oh[atile_idx(b * T_ + r0g,     col, 16)] = h01;
        *(__half2*)&oh[atile_idx(b * T_ + r0g + 8, col, 16)] = h23;
    }
}

// ===========================================================================
// Weight tiling (unchanged)
// ===========================================================================
__global__ void wtile_kernel(const float* __restrict__ W, __half* __restrict__ out,
                             int K, int N, int tshift,
                             size_t inLs, size_t outLs)
{
    __shared__ float s[64][65];
    const float* Wl = W + blockIdx.z * inLs;
    out += blockIdx.z * outLs;
    int n0 = blockIdx.x * 64, k0g = blockIdx.y;
    int tid = threadIdx.y * 32 + threadIdx.x;
    int nkt = K >> 6;
    int tileN = 1 << tshift;
#pragma unroll
    for (int i = 0; i < 16; i++) {
        int idx = tid + i * 256;
        int k = idx >> 6, n = idx & 63;
        s[k][n] = Wl[(size_t)(k0g * 64 + k) * N + n0 + n];
    }
    __syncthreads();
#pragma unroll
    for (int pass = 0; pass < 2; pass++) {
        int n = (tid >> 3) + pass * 32;
        int g = tid & 7;
        int gn = n0 + n;
        int tile = (gn >> tshift) * nkt + k0g;
        int nl = gn & (tileN - 1);
        uint32_t gp = (uint32_t)g ^ (uint32_t)(nl & 7);
        uint4 u;
        u.x = pkh2(s[g * 8 + 0][n], s[g * 8 + 1][n]);
        u.y = pkh2(s[g * 8 + 2][n], s[g * 8 + 3][n]);
        u.z = pkh2(s[g * 8 + 4][n], s[g * 8 + 5][n]);
        u.w = pkh2(s[g * 8 + 6][n], s[g * 8 + 7][n]);
        *(uint4*)&out[(size_t)tile * (tileN * 64) + nl * 64 + gp * 8] = u;
    }
}

__global__ void wtile_qkv_kernel(const float* __restrict__ Wq,
                                 const float* __restrict__ Wk,
                                 const float* __restrict__ Wv,
                                 __half* __restrict__ out)
{
    __shared__ float s[64][65];
    const size_t EE = (size_t)E_ * E_;
    int l = blockIdx.z;
    int gn0 = blockIdx.x * 64;
    int which = gn0 >> 10;
    const float* Wl = (which == 0 ? Wq : which == 1 ? Wk : Wv) + l * EE;
    int n0 = gn0 & 1023;
    int k0g = blockIdx.y;
    out += (size_t)l * 3 * EE;
    int tid = threadIdx.y * 32 + threadIdx.x;
#pragma unroll
    for (int i = 0; i < 16; i++) {
        int idx = tid + i * 256;
        int k = idx >> 6, n = idx & 63;
        s[k][n] = Wl[(size_t)(k0g * 64 + k) * E_ + n0 + n];
    }
    __syncthreads();
#pragma unroll
    for (int pass = 0; pass < 2; pass++) {
        int n = (tid >> 3) + pass * 32;
        int g = tid & 7;
        int gn = gn0 + n;
        int tile = (gn >> 8) * 16 + k0g;
        int nl = gn & 255;
        uint32_t gp = (uint32_t)g ^ (uint32_t)(nl & 7);
        uint4 u;
        u.x = pkh2(s[g * 8 + 0][n], s[g * 8 + 1][n]);
        u.y = pkh2(s[g * 8 + 2][n], s[g * 8 + 3][n]);
        u.z = pkh2(s[g * 8 + 4][n], s[g * 8 + 5][n]);
        u.w = pkh2(s[g * 8 + 6][n], s[g * 8 + 7][n]);
        *(uint4*)&out[(size_t)tile * (256 * 64) + nl * 64 + gp * 8] = u;
    }
}

__global__ void bpack_kernel(const float* __restrict__ bq, const float* __restrict__ bk,
                             const float* __restrict__ bv, float* __restrict__ out) {
    int i = blockIdx.x * 256 + threadIdx.x;
    int l = i / 3072, j = i % 3072;
    float v = (j < 1024) ? bq[l * 1024 + j]
            : (j < 2048) ? bk[l * 1024 + j - 1024]
                         : bv[l * 1024 + j - 2048];
    out[i] = v;
}

// ---------------------------------------------------------------------------
// Embedding / LayerNorm
// ---------------------------------------------------------------------------
__global__ void embed_kernel(const int* __restrict__ x, const float* __restrict__ tok,
                             const float* __restrict__ pos, float* __restrict__ h) {
    int i = blockIdx.x * 256 + threadIdx.x;
    int row = i >> 8, e4 = (i & 255) << 2;
    int tkn = x[row];
    int t = row & (T_ - 1);
    float4 a = *(const float4*)(tok + (size_t)tkn * E_ + e4);
    float4 p = *(const float4*)(pos + (size_t)t * E_ + e4);
    *(float4*)(h + (size_t)row * E_ + e4) =
        make_float4(a.x + p.x, a.y + p.y, a.z + p.z, a.w + p.w);
}

__global__ __launch_bounds__(256) void ln_kernel(const float* __restrict__ in,
                                                 const float* __restrict__ gam,
                                                 const float* __restrict__ bet,
                                                 __half* __restrict__ outh) {
    int row = blockIdx.x * 8 + (threadIdx.x >> 5);
    int lane = threadIdx.x & 31;
    const float4* rp = (const float4*)(in + (size_t)row * E_) + lane;
    float4 v[8];
    float s = 0.f, sq = 0.f;
#pragma unroll
    for (int i = 0; i < 8; i++) {
        v[i] = rp[i * 32];
        s  += v[i].x + v[i].y + v[i].z + v[i].w;
        sq += v[i].x * v[i].x + v[i].y * v[i].y + v[i].z * v[i].z + v[i].w * v[i].w;
    }
#pragma unroll
    for (int o = 16; o > 0; o >>= 1) {
        s  += __shfl_xor_sync(0xffffffffu, s,  o);
        sq += __shfl_xor_sync(0xffffffffu, sq, o);
    }
    float mean = s * (1.0f / E_);
    float var  = sq * (1.0f / E_) - mean * mean;
    float rstd = rsqrtf(var + 1e-5f);

#pragma unroll
    for (int i = 0; i < 8; i++) {
        int e = (lane + i * 32) * 4;
        float4 g = *(const float4*)(gam + e);
        float4 bb = *(const float4*)(bet + e);
        __half2 h0 = __floats2half2_rn((v[i].x - mean) * rstd * g.x + bb.x,
                                       (v[i].y - mean) * rstd * g.y + bb.y);
        __half2 h1 = __floats2half2_rn((v[i].z - mean) * rstd * g.z + bb.z,
                                       (v[i].w - mean) * rstd * g.w + bb.w);
        size_t a0 = atile_idx(row, e, 16);
        *(__half2*)&outh[a0]     = h0;
        *(__half2*)&outh[a0 + 2] = h1;
    }
}

// ---------------------------------------------------------------------------
// Host orchestration
// ---------------------------------------------------------------------------
extern "C" void kernel_launch(void* const* d_in, const int* in_sizes, int n_in,
                              void* d_out, int out_size) {
    const int*   x    = (const int*)  d_in[0];
    const float* tok  = (const float*)d_in[1];
    const float* pos  = (const float*)d_in[2];
    const float* Wq   = (const float*)d_in[3];
    const float* bq   = (const float*)d_in[4];
    const float* Wk   = (const float*)d_in[5];
    const float* bk   = (const float*)d_in[6];
    const float* Wv   = (const float*)d_in[7];
    const float* bv   = (const float*)d_in[8];
    const float* Wo   = (const float*)d_in[9];
    const float* bo   = (const float*)d_in[10];
    const float* ln1g = (const float*)d_in[11];
    const float* ln1b = (const float*)d_in[12];
    const float* W1   = (const float*)d_in[13];
    const float* b1   = (const float*)d_in[14];
    const float* W2   = (const float*)d_in[15];
    const float* b2   = (const float*)d_in[16];
    const float* ln2g = (const float*)d_in[17];
    const float* ln2b = (const float*)d_in[18];
    const float* lnfg = (const float*)d_in[19];
    const float* lnfb = (const float*)d_in[20];
    const float* Wout = (const float*)d_in[21];
    const float* bout = (const float*)d_in[22];
    float* out = (float*)d_out;

    float *h, *bqkv;
    __half *qh, *kt, *vt, *xn, *o, *mlp;
    __half *qkvT, *woT, *w1T, *w2T, *wouT;
    cudaGetSymbolAddress((void**)&h,    g_h);
    cudaGetSymbolAddress((void**)&qh,   g_q);
    cudaGetSymbolAddress((void**)&kt,   g_kt);
    cudaGetSymbolAddress((void**)&vt,   g_vt);
    cudaGetSymbolAddress((void**)&bqkv, g_bqkv);
    cudaGetSymbolAddress((void**)&xn,   g_xn);
    cudaGetSymbolAddress((void**)&o,    g_o);
    cudaGetSymbolAddress((void**)&mlp,  g_mlp);
    cudaGetSymbolAddress((void**)&qkvT, g_qkvT);
    cudaGetSymbolAddress((void**)&woT,  g_woT);
    cudaGetSymbolAddress((void**)&w1T,  g_w1T);
    cudaGetSymbolAddress((void**)&w2T,  g_w2T);
    cudaGetSymbolAddress((void**)&wouT, g_woutT);

    cudaFuncSetAttribute((const void*)btgemm_kernel<0>, cudaFuncAttributeMaxDynamicSharedMemorySize, BT_SMEM);
    cudaFuncSetAttribute((const void*)btgemm_kernel<1>, cudaFuncAttributeMaxDynamicSharedMemorySize, BT_SMEM);
    cudaFuncSetAttribute((const void*)btgemm_kernel<3>, cudaFuncAttributeMaxDynamicSharedMemorySize, BT_SMEM);
    cudaFuncSetAttribute((const void*)tgemm_res_kernel, cudaFuncAttributeMaxDynamicSharedMemorySize, ST_SMEM);

    const size_t EE = (size_t)E_ * E_, EF = (size_t)E_ * F_;
    dim3 tb(32, 8);

    embed_kernel<<<(M_ * E_) / (256 * 4), 256>>>(x, tok, pos, h);                    // 0
    wtile_qkv_kernel<<<dim3(48, 16, L_), tb>>>(Wq, Wk, Wv, qkvT);                    // 1
    bpack_kernel<<<(L_ * 3 * E_) / 256, 256>>>(bq, bk, bv, bqkv);                    // 2
    ln_kernel<<<M_ / 8, 256>>>(h, ln1g, ln1b, xn);                                   // 3
    btgemm_kernel<3><<<dim3(M_ / 128, 12), 512, BT_SMEM>>>(                          // 4
        xn, qkvT, bqkv, nullptr, qh, kt, vt, 3 * E_, E_);
    wtile_kernel<<<dim3(16, 16, L_), tb>>>(Wo, woT, E_, E_, 7, EE, EE);              // 5
    wtile_kernel<<<dim3(64, 16, L_), tb>>>(W1, w1T, E_, F_, 8, EF, EF);              // 6
    wtile_kernel<<<dim3(16, 64, L_), tb>>>(W2, w2T, F_, E_, 7, EF, EF);              // 7
    wtile_kernel<<<dim3(500, 16, 1), tb>>>(Wout, wouT, E_, V_, 8, 0, 0);             // 8

    for (int l = 0; l < L_; l++) {
        if (l > 0) {
            ln_kernel<<<M_ / 8, 256>>>(h, ln1g + l * E_, ln1b + l * E_, xn);
            btgemm_kernel<3><<<dim3(M_ / 128, 12), 512, BT_SMEM>>>(
                xn, qkvT + l * 3 * EE, bqkv + l * 3 * E_, nullptr, qh, kt, vt, 3 * E_, E_);
        }
        fattn_kernel<<<B_ * H_ * (T_ / 64), 128>>>(qh, kt, vt, o);
        tgemm_res_kernel<<<dim3(M_ / 128, 8), 256, ST_SMEM>>>(
            o, woT + l * EE, bo + l * E_, h, h, E_, E_);
        ln_kernel<<<M_ / 8, 256>>>(h, ln2g + l * E_, ln2b + l * E_, xn);
        btgemm_kernel<1><<<dim3(M_ / 128, F_ / 256), 512, BT_SMEM>>>(
            xn, w1T + l * EF, b1 + l * F_, nullptr, mlp, nullptr, nullptr, F_, E_);
        tgemm_res_kernel<<<dim3(M_ / 128, 8), 256, ST_SMEM>>>(
            mlp, w2T + l * EF, b2 + l * E_, h, h, E_, F_);
    }

    ln_kernel<<<M_ / 8, 256>>>(h, lnfg, lnfb, xn);
    btgemm_kernel<0><<<dim3(M_ / 128, V_ / 256), 512, BT_SMEM>>>(
        xn, wouT, bout, out, nullptr, nullptr, nullptr, V_, E_);
}

// round 17
// speedup vs baseline: 1.7774x; 1.0316x over previous
#include <cuda_runtime.h>
#include <cuda_fp16.h>
#include <math.h>
#include <stdint.h>

// Problem dims
#define V_ 32000
#define E_ 1024
#define H_ 16
#define F_ 4096
#define L_ 4
#define T_ 2048
#define B_ 2
#define D_ 64
#define M_ (B_*T_)   // 4096

// ---------------------------------------------------------------------------
// Scratch. Activations xn/o/mlp TILED (128x64, dense 128B rows, granule XOR
// swizzle g^(r&7)). K/V per (b,h) in 64-key x 64-dim tiles.
// ---------------------------------------------------------------------------
__device__ float g_h  [M_*E_];
__device__ __half g_q  [M_*E_];
__device__ __half g_kt [(size_t)B_*H_*T_*D_];
__device__ __half g_vt [(size_t)B_*H_*T_*D_];
__device__ float g_bqkv[L_*3*E_];
__device__ __half g_xn [M_*E_];
__device__ __half g_o  [M_*E_];
__device__ __half g_mlp[M_*F_];
__device__ __half g_qkvT[L_*3*E_*E_];
__device__ __half g_woT [L_*E_*E_];
__device__ __half g_w1T [L_*F_*E_];
__device__ __half g_w2T [L_*E_*F_];
__device__ __half g_woutT[(size_t)V_*E_];

// ---------------------------------------------------------------------------
// PTX helpers
// ---------------------------------------------------------------------------
__device__ __forceinline__ uint32_t smem_u32(const void* p) {
    uint32_t a;
    asm("{ .reg .u64 t; cvta.to.shared.u64 t, %1; cvt.u32.u64 %0, t; }" : "=r"(a) : "l"(p));
    return a;
}
#define MBAR_INIT(a, c) asm volatile("mbarrier.init.shared.b64 [%0], %1;" :: "r"((uint32_t)(a)), "r"((uint32_t)(c)) : "memory")
#define MBAR_EXPECT(a, n) asm volatile("mbarrier.arrive.expect_tx.shared.b64 _, [%0], %1;" :: "r"((uint32_t)(a)), "r"((uint32_t)(n)) : "memory")
static __device__ __forceinline__ void bulk_g2s(uint32_t s, const void* g, uint32_t bytes, uint32_t mbar) {
    asm volatile("cp.async.bulk.shared::cta.global.mbarrier::complete_tx::bytes [%0], [%1], %2, [%3];"
                 :: "r"(s), "l"(g), "r"(bytes), "r"(mbar) : "memory");
}
#define MBAR_WAIT(addr, par) do {                                              \
    uint32_t _m = (uint32_t)(addr), _p = (uint32_t)(par), _d;                  \
    asm volatile("{\n\t.reg .pred p;\n\t"                                      \
        "mbarrier.try_wait.parity.shared.b64 p, [%1], %2;\n\t"                 \
        "selp.b32 %0, 1, 0, p;\n\t}" : "=r"(_d) : "r"(_m), "r"(_p) : "memory");\
    if (!_d) {                                                                 \
        asm volatile("{\n\t.reg .pred P1;\n\t"                                 \
            "WL_%=:\n\t"                                                       \
            "mbarrier.try_wait.parity.shared.b64 P1, [%0], %1;\n\t"            \
            "@P1 bra.uni WD_%=;\n\t"                                           \
            "bra.uni WL_%=;\n\t"                                               \
            "WD_%=:\n\t}" :: "r"(_m), "r"(_p) : "memory");                     \
    }                                                                          \
} while (0)

struct Frag4 { uint32_t x, y, z, w; };

static __device__ __forceinline__ Frag4 ldsm_x4(uint32_t addr) {
    Frag4 r;
    asm volatile("ldmatrix.sync.aligned.m8n8.x4.shared.b16 {%0,%1,%2,%3}, [%4];"
                 : "=r"(r.x), "=r"(r.y), "=r"(r.z), "=r"(r.w) : "r"(addr));
    return r;
}
static __device__ __forceinline__ Frag4 ldsm_x4_t(uint32_t addr) {
    Frag4 r;
    asm volatile("ldmatrix.sync.aligned.m8n8.x4.trans.shared.b16 {%0,%1,%2,%3}, [%4];"
                 : "=r"(r.x), "=r"(r.y), "=r"(r.z), "=r"(r.w) : "r"(addr));
    return r;
}

static __device__ __forceinline__ void mma_f16(float* c, const Frag4& a,
                                               uint32_t b0, uint32_t b1) {
    asm volatile(
        "mma.sync.aligned.m16n8k16.row.col.f32.f16.f16.f32 "
        "{%0,%1,%2,%3}, {%4,%5,%6,%7}, {%8,%9}, {%0,%1,%2,%3};"
        : "+f"(c[0]), "+f"(c[1]), "+f"(c[2]), "+f"(c[3])
        : "r"(a.x), "r"(a.y), "r"(a.z), "r"(a.w), "r"(b0), "r"(b1));
}
static __device__ __forceinline__ void mma4(float* c, uint32_t a0, uint32_t a1,
                                            uint32_t a2, uint32_t a3,
                                            uint32_t b0, uint32_t b1) {
    asm volatile(
        "mma.sync.aligned.m16n8k16.row.col.f32.f16.f16.f32 "
        "{%0,%1,%2,%3}, {%4,%5,%6,%7}, {%8,%9}, {%0,%1,%2,%3};"
        : "+f"(c[0]), "+f"(c[1]), "+f"(c[2]), "+f"(c[3])
        : "r"(a0), "r"(a1), "r"(a2), "r"(a3), "r"(b0), "r"(b1));
}

static __device__ __forceinline__ float ex2f(float x) {
    float y;
    asm("ex2.approx.ftz.f32 %0, %1;" : "=f"(y) : "f"(x));
    return y;
}
static __device__ __forceinline__ uint32_t pkh2(float a, float b) {
    __half2 h = __floats2half2_rn(a, b);
    return *(uint32_t*)&h;
}
__device__ __forceinline__ float gelu_exact(float x) {
    return 0.5f * x * (1.0f + erff(x * 0.70710678118654752f));
}

static __device__ __forceinline__ size_t atile_idx(int row, int col, int Kd64) {
    int gp = ((col >> 3) & 7) ^ (row & 7);
    return ((size_t)(row >> 7) * Kd64 + (col >> 6)) * 8192
           + (size_t)(row & 127) * 64 + gp * 8 + (col & 7);
}

// ===========================================================================
// BIG-TILE GEMM: CTA 128x256, 256 threads (8 warps 2x4), warptile 64x64,
// BK=64, 3-stage, A+B via cp.async.bulk.
// EPI: 0 fp32+bias ; 1 gelu->fp16 tiled ; 3 QKV scatter
// ===========================================================================
#define BT_TA    16384
#define BT_TB    32768
#define BT_STG   (BT_TA + BT_TB)            // 49152
#define BT_SMEM  (3 * BT_STG + 64)

template<int EPI>
__global__ __launch_bounds__(256, 1) void btgemm_kernel(
    const __half* __restrict__ At, const __half* __restrict__ Bt,
    const float* __restrict__ bias,
    float* __restrict__ Cf, __half* __restrict__ Ch,
    __half* __restrict__ Kt, __half* __restrict__ Vt,
    int N, int K)
{
    extern __shared__ __align__(1024) unsigned char smem[];
    uint32_t sb = smem_u32(smem);
    int tid = threadIdx.x, wid = tid >> 5, lane = tid & 31;
    int bm = blockIdx.x * 128, bn = blockIdx.y * 256;
    int wm = wid & 1, wn = wid >> 1;     // 2 x 4 warps, warptile 64x64

    uint32_t stg[3] = {sb, sb + BT_STG, sb + 2u * BT_STG};
    uint32_t mb0 = sb + 3u * BT_STG;
    if (tid == 0) { MBAR_INIT(mb0, 1); MBAR_INIT(mb0 + 8, 1); MBAR_INIT(mb0 + 16, 1); }
    __syncthreads();

    int l7 = lane & 7, bA = lane >> 4, b1 = (lane >> 3) & 1;
    uint32_t a_row = (uint32_t)((wm * 64 + (lane & 15)) * 128);
    int rbase = (lane & 7) + ((lane >> 4) << 3);
    uint32_t brow[4];
#pragma unroll
    for (int np = 0; np < 4; np++)
        brow[np] = (uint32_t)(BT_TA + (wn * 64 + np * 16 + rbase) * 128);

    float acc[4][8][4];
#pragma unroll
    for (int i = 0; i < 4; i++)
#pragma unroll
        for (int j = 0; j < 8; j++)
#pragma unroll
            for (int e = 0; e < 4; e++) acc[i][j][e] = 0.f;

    int nkt = K >> 6;
#pragma unroll
    for (int s = 0; s < 2; s++) {
        if (tid == 0) {
            MBAR_EXPECT(mb0 + s * 8, BT_STG);
            bulk_g2s(stg[s], At + ((size_t)(bm >> 7) * nkt + s) * 8192, BT_TA, mb0 + s * 8);
            bulk_g2s(stg[s] + BT_TA, Bt + ((size_t)(bn >> 8) * nkt + s) * 16384, BT_TB, mb0 + s * 8);
        }
    }

    int cur = 0, nxt = 2;
    int phbits = 0;
    for (int kt = 0; kt < nkt; kt++) {
        MBAR_WAIT(mb0 + cur * 8, (phbits >> cur) & 1);
        phbits ^= (1 << cur);
        __syncthreads();

        int kf = kt + 2;
        if (kf < nkt && tid == 0) {
            MBAR_EXPECT(mb0 + nxt * 8, BT_STG);
            bulk_g2s(stg[nxt], At + ((size_t)(bm >> 7) * nkt + kf) * 8192, BT_TA, mb0 + nxt * 8);
            bulk_g2s(stg[nxt] + BT_TA, Bt + ((size_t)(bn >> 8) * nkt + kf) * 16384, BT_TB, mb0 + nxt * 8);
        }

        uint32_t st = stg[cur];
        cur = (cur + 1) % 3; nxt = (nxt + 1) % 3;
#pragma unroll
        for (int ks = 0; ks < 4; ks++) {
            uint32_t gpA = (uint32_t)(((ks << 1) + bA) ^ l7) << 4;
            uint32_t gpB = (uint32_t)(((ks << 1) + b1) ^ l7) << 4;
            Frag4 ah[4];
#pragma unroll
            for (int mt = 0; mt < 4; mt++)
                ah[mt] = ldsm_x4(st + a_row + mt * 2048 + gpA);
#pragma unroll
            for (int np = 0; np < 4; np++) {
                Frag4 bf = ldsm_x4(st + brow[np] + gpB);
#pragma unroll
                for (int mt = 0; mt < 4; mt++) {
                    mma_f16(acc[mt][np * 2],     ah[mt], bf.x, bf.y);
                    mma_f16(acc[mt][np * 2 + 1], ah[mt], bf.z, bf.w);
                }
            }
        }
    }
    __syncthreads();

    int row_in = lane >> 2;
    int col2   = (lane & 3) << 1;
    int Nd64 = N >> 6;
#pragma unroll
    for (int mt = 0; mt < 4; mt++) {
#pragma unroll
        for (int nt = 0; nt < 8; nt++) {
            int col = bn + wn * 64 + nt * 8 + col2;
            float bx = bias[col], by = bias[col + 1];
#pragma unroll
            for (int half = 0; half < 2; half++) {
                int row = bm + wm * 64 + mt * 16 + row_in + half * 8;
                float v0 = acc[mt][nt][half * 2 + 0] + bx;
                float v1 = acc[mt][nt][half * 2 + 1] + by;
                if (EPI == 0) {
                    *(float2*)&Cf[(size_t)row * N + col] = make_float2(v0, v1);
                } else if (EPI == 1) {
                    __half2 hh;
                    hh.x = __float2half(gelu_exact(v0));
                    hh.y = __float2half(gelu_exact(v1));
                    *(__half2*)&Ch[atile_idx(row, col, Nd64)] = hh;
                } else {
                    __half2 hh;
                    hh.x = __float2half(v0);
                    hh.y = __float2half(v1);
                    int which = col >> 10;
                    if (which == 0) {
                        *(__half2*)&Ch[(size_t)row * 1024 + col] = hh;
                    } else {
                        int d = col & 1023;
                        int hhd = d >> 6, dl = d & 63;
                        int bb = row >> 11, key = row & 2047;
                        size_t base = ((size_t)((bb * 16 + hhd) * 32 + (key >> 6))) * 4096;
                        int gp = ((dl >> 3) ^ (key & 7)) & 7;
                        size_t idx = base + (size_t)(key & 63) * 64 + gp * 8 + (dl & 7);
                        __half* dst = (which == 1) ? Kt : Vt;
                        *(__half2*)&dst[idx] = hh;
                    }
                }
            }
        }
    }
}

// ===========================================================================
// SMALL-TILE GEMM (N=1024, residual): unchanged from R16
// ===========================================================================
#define ST_STG   (BT_TA + 16384)            // 32768
#define ST_SMEM  (3 * ST_STG + 64)

__global__ __launch_bounds__(256, 2) void tgemm_res_kernel(
    const __half* __restrict__ At, const __half* __restrict__ Bt,
    const float* __restrict__ bias, const float* __restrict__ res,
    float* __restrict__ Cf, int N, int K)
{
    extern __shared__ __align__(1024) unsigned char smem[];
    uint32_t sb = smem_u32(smem);
    int tid = threadIdx.x, wid = tid >> 5, lane = tid & 31;
    int bm = blockIdx.x * 128, bn = blockIdx.y * 128;
    int wm = wid & 1, wn = wid >> 1;
    int nkt = K >> 6;

    uint32_t stg[3] = {sb, sb + ST_STG, sb + 2u * ST_STG};
    uint32_t mb0 = sb + 3u * ST_STG;
    if (tid == 0) { MBAR_INIT(mb0, 1); MBAR_INIT(mb0 + 8, 1); MBAR_INIT(mb0 + 16, 1); }
    __syncthreads();

    int l7 = lane & 7, bA = lane >> 4, b1 = (lane >> 3) & 1;
    uint32_t a_row = (uint32_t)((wm * 64 + (lane & 15)) * 128);
    int rbase = (lane & 7) + ((lane >> 4) << 3);
    uint32_t brow0 = (uint32_t)(BT_TA + (wn * 32 + rbase) * 128);
    uint32_t brow1 = (uint32_t)(BT_TA + (wn * 32 + 16 + rbase) * 128);

    float acc[4][4][4];
#pragma unroll
    for (int i = 0; i < 4; i++)
#pragma unroll
        for (int j = 0; j < 4; j++)
#pragma unroll
            for (int e = 0; e < 4; e++) acc[i][j][e] = 0.f;

#pragma unroll
    for (int s = 0; s < 2; s++) {
        if (tid == 0) {
            MBAR_EXPECT(mb0 + s * 8, ST_STG);
            bulk_g2s(stg[s], At + ((size_t)(bm >> 7) * nkt + s) * 8192, BT_TA, mb0 + s * 8);
            bulk_g2s(stg[s] + BT_TA, Bt + ((size_t)(bn >> 7) * nkt + s) * 8192, 16384, mb0 + s * 8);
        }
    }

    int cur = 0, nxt = 2;
    int phbits = 0;
    for (int kt = 0; kt < nkt; kt++) {
        MBAR_WAIT(mb0 + cur * 8, (phbits >> cur) & 1);
        phbits ^= (1 << cur);
        __syncthreads();

        int kf = kt + 2;
        if (kf < nkt && tid == 0) {
            MBAR_EXPECT(mb0 + nxt * 8, ST_STG);
            bulk_g2s(stg[nxt], At + ((size_t)(bm >> 7) * nkt + kf) * 8192, BT_TA, mb0 + nxt * 8);
            bulk_g2s(stg[nxt] + BT_TA, Bt + ((size_t)(bn >> 7) * nkt + kf) * 8192, 16384, mb0 + nxt * 8);
        }

        uint32_t st = stg[cur];
        cur = (cur + 1) % 3; nxt = (nxt + 1) % 3;
#pragma unroll
        for (int ks = 0; ks < 4; ks++) {
            uint32_t gpA = (uint32_t)(((ks << 1) + bA) ^ l7) << 4;
            uint32_t gpB = (uint32_t)(((ks << 1) + b1) ^ l7) << 4;
            Frag4 ah[4];
#pragma unroll
            for (int mt = 0; mt < 4; mt++)
                ah[mt] = ldsm_x4(st + a_row + mt * 2048 + gpA);
            Frag4 bf0 = ldsm_x4(st + brow0 + gpB);
            Frag4 bf1 = ldsm_x4(st + brow1 + gpB);
#pragma unroll
            for (int mt = 0; mt < 4; mt++) {
                mma_f16(acc[mt][0], ah[mt], bf0.x, bf0.y);
                mma_f16(acc[mt][1], ah[mt], bf0.z, bf0.w);
                mma_f16(acc[mt][2], ah[mt], bf1.x, bf1.y);
                mma_f16(acc[mt][3], ah[mt], bf1.z, bf1.w);
            }
        }
    }
    __syncthreads();

    int row_in = lane >> 2;
    int col2   = (lane & 3) << 1;
#pragma unroll
    for (int mt = 0; mt < 4; mt++) {
#pragma unroll
        for (int nt = 0; nt < 4; nt++) {
            int col = bn + wn * 32 + nt * 8 + col2;
            float bx = bias[col], by = bias[col + 1];
#pragma unroll
            for (int half = 0; half < 2; half++) {
                int row = bm + wm * 64 + mt * 16 + row_in + half * 8;
                size_t off = (size_t)row * N + col;
                float2 rv = *(const float2*)&res[off];
                *(float2*)&Cf[off] = make_float2(acc[mt][nt][half * 2 + 0] + bx + rv.x,
                                                 acc[mt][nt][half * 2 + 1] + by + rv.y);
            }
        }
    }
}

// ===========================================================================
// Flash attention (unchanged from R16)
// ===========================================================================
__global__ __launch_bounds__(128) void fattn_kernel(const __half* __restrict__ qh,
                                                    const __half* __restrict__ Kt,
                                                    const __half* __restrict__ Vt,
                                                    __half* __restrict__ oh) {
    __shared__ __align__(128) __half Qs[64 * 72];
    __shared__ __align__(128) __half Ksm[2][4096];
    __shared__ __align__(128) __half Vsm[2][4096];
    __shared__ __align__(8) uint64_t mbar[2];

    int tid = threadIdx.x, wid = tid >> 5, lane = tid & 31;
    int qt = 31 - (blockIdx.x & 31);
    int bh = blockIdx.x >> 5;
    int b  = bh >> 4, hh = bh & 15;
    int q0 = qt * 64;
    size_t kvbase = (size_t)((b * 16 + hh) * 32) * 4096;

    uint32_t mb = smem_u32(mbar);
    if (tid == 0) { MBAR_INIT(mb, 1); MBAR_INIT(mb + 8, 1); }

    for (int i = tid; i < 512; i += 128) {
        int r = i >> 3, c8 = (i & 7) << 3;
        *(uint4*)&Qs[r * 72 + c8] =
            *(const uint4*)(qh + (size_t)(b * T_ + q0 + r) * 1024 + hh * 64 + c8);
    }
    __syncthreads();

    uint32_t qbase = smem_u32(Qs);
    Frag4 qf[4];
    {
        int rr = wid * 16 + (lane & 15);
#pragma unroll
        for (int kd = 0; kd < 4; kd++)
            qf[kd] = ldsm_x4(qbase + (uint32_t)(rr * 144 + kd * 32 + ((lane >> 4) << 4)));
    }

    uint32_t ksb[2] = {smem_u32(Ksm[0]), smem_u32(Ksm[1])};
    uint32_t vsb[2] = {smem_u32(Vsm[0]), smem_u32(Vsm[1])};

    float o[8][4];
#pragma unroll
    for (int t = 0; t < 8; t++)
#pragma unroll
        for (int e = 0; e < 4; e++) o[t][e] = 0.f;
    float m0 = -1e30f, m1 = -1e30f, l0 = 0.f, l1 = 0.f;

    const float SC = 0.18033688011f;
    int ntiles = qt + 1;
    int l7 = lane & 7, b1 = (lane >> 3) & 1;
    int rbase = (lane & 7) + ((lane >> 4) << 3);

    if (tid == 0) {
        MBAR_EXPECT(mb, 16384);
        bulk_g2s(ksb[0], Kt + kvbase, 8192, mb);
        bulk_g2s(vsb[0], Vt + kvbase, 8192, mb);
    }

    int phbits = 0;
    for (int t = 0; t < ntiles; t++) {
        int buf = t & 1;
        if (t + 1 < ntiles && tid == 0) {
            int nb = (t + 1) & 1;
            MBAR_EXPECT(mb + nb * 8, 16384);
            bulk_g2s(ksb[nb], Kt + kvbase + (size_t)(t + 1) * 4096, 8192, mb + nb * 8);
            bulk_g2s(vsb[nb], Vt + kvbase + (size_t)(t + 1) * 4096, 8192, mb + nb * 8);
        }
        MBAR_WAIT(mb + buf * 8, (phbits >> buf) & 1);
        phbits ^= (1 << buf);

        uint32_t kb_s = ksb[buf], vb_s = vsb[buf];

        float s[8][4];
#pragma unroll
        for (int j = 0; j < 8; j++)
#pragma unroll
            for (int e = 0; e < 4; e++) s[j][e] = 0.f;
#pragma unroll
        for (int kd = 0; kd < 4; kd++) {
            uint32_t gp = (uint32_t)(((kd << 1) + b1) ^ l7) << 4;
#pragma unroll
            for (int np = 0; np < 4; np++) {
                Frag4 bf = ldsm_x4(kb_s + (uint32_t)((np * 16 + rbase) * 128) + gp);
                mma_f16(s[np * 2],     qf[kd], bf.x, bf.y);
                mma_f16(s[np * 2 + 1], qf[kd], bf.z, bf.w);
            }
        }

#pragma unroll
        for (int j = 0; j < 8; j++)
#pragma unroll
            for (int e = 0; e < 4; e++) s[j][e] *= SC;

        if (t == qt) {
            int lr0 = wid * 16 + (lane >> 2);
#pragma unroll
            for (int j = 0; j < 8; j++) {
                int c = 8 * j + 2 * (lane & 3);
                if (c     > lr0)     s[j][0] = -1e30f;
                if (c + 1 > lr0)     s[j][1] = -1e30f;
                if (c     > lr0 + 8) s[j][2] = -1e30f;
                if (c + 1 > lr0 + 8) s[j][3] = -1e30f;
            }
        }

        float mr0 = -1e30f, mr1 = -1e30f;
#pragma unroll
        for (int j = 0; j < 8; j++) {
            mr0 = fmaxf(mr0, fmaxf(s[j][0], s[j][1]));
            mr1 = fmaxf(mr1, fmaxf(s[j][2], s[j][3]));
        }
        mr0 = fmaxf(mr0, __shfl_xor_sync(0xffffffffu, mr0, 1));
        mr0 = fmaxf(mr0, __shfl_xor_sync(0xffffffffu, mr0, 2));
        mr1 = fmaxf(mr1, __shfl_xor_sync(0xffffffffu, mr1, 1));
        mr1 = fmaxf(mr1, __shfl_xor_sync(0xffffffffu, mr1, 2));

        float nm0 = fmaxf(m0, mr0), nm1 = fmaxf(m1, mr1);
        float c0 = ex2f(m0 - nm0), c1 = ex2f(m1 - nm1);
        m0 = nm0; m1 = nm1;
        l0 *= c0; l1 *= c1;

        uint32_t pf[8][2];
        float ps0 = 0.f, ps1 = 0.f;
#pragma unroll
        for (int j = 0; j < 8; j++) {
            float p0 = ex2f(s[j][0] - m0), p1 = ex2f(s[j][1] - m0);
            float p2 = ex2f(s[j][2] - m1), p3 = ex2f(s[j][3] - m1);
            ps0 += p0 + p1; ps1 += p2 + p3;
            pf[j][0] = pkh2(p0, p1);
            pf[j][1] = pkh2(p2, p3);
        }
        l0 += ps0; l1 += ps1;

#pragma unroll
        for (int tt = 0; tt < 8; tt++) {
            o[tt][0] *= c0; o[tt][1] *= c0;
            o[tt][2] *= c1; o[tt][3] *= c1;
        }

#pragma unroll
        for (int j = 0; j < 4; j++) {
            uint32_t a0 = pf[2 * j][0],     a1 = pf[2 * j][1];
            uint32_t a2 = pf[2 * j + 1][0], a3 = pf[2 * j + 1][1];
            int vrow = j * 16 + (lane & 7) + (((lane >> 3) & 1) << 3);
#pragma unroll
            for (int t2 = 0; t2 < 4; t2++) {
                uint32_t g = (uint32_t)(((t2 << 1) + (lane >> 4)) ^ l7) << 4;
                Frag4 vf = ldsm_x4_t(vb_s + (uint32_t)(vrow * 128) + g);
                mma4(o[2 * t2],     a0, a1, a2, a3, vf.x, vf.y);
                mma4(o[2 * t2 + 1], a0, a1, a2, a3, vf.z, vf.w);
            }
        }
        __syncthreads();
    }

    l0 += __shfl_xor_sync(0xffffffffu, l0, 1);
    l0 += __shfl_xor_sync(0xffffffffu, l0, 2);
    l1 += __shfl_xor_sync(0xffffffffu, l1, 1);
    l1 += __shfl_xor_sync(0xffffffffu, l1, 2);
    float li0 = 1.0f / l0, li1 = 1.0f / l1;

    int r0g = q0 + wid * 16 + (lane >> 2);
    int dbase = hh * 64 + 2 * (lane & 3);
#pragma unroll
    for (int tt = 0; tt < 8; tt++) {
        int col = dbase + tt * 8;
        __half2 h01 = __floats2half2_rn(o[tt][0] * li0, o[tt][1] * li0);
        __half2 h23 = __floats2half2_rn(o[tt][2] * li1, o[tt][3] * li1);
        *(__half2*)&oh[atile_idx(b * T_ + r0g,     col, 16)] = h01;
        *(__half2*)&oh[atile_idx(b * T_ + r0g + 8, col, 16)] = h23;
    }
}

// ===========================================================================
// Weight tiling (unchanged)
// ===========================================================================
__global__ void wtile_kernel(const float* __restrict__ W, __half* __restrict__ out,
                             int K, int N, int tshift,
                             size_t inLs, size_t outLs)
{
    __shared__ float s[64][65];
    const float* Wl = W + blockIdx.z * inLs;
    out += blockIdx.z * outLs;
    int n0 = blockIdx.x * 64, k0g = blockIdx.y;
    int tid = threadIdx.y * 32 + threadIdx.x;
    int nkt = K >> 6;
    int tileN = 1 << tshift;
#pragma unroll
    for (int i = 0; i < 16; i++) {
        int idx = tid + i * 256;
        int k = idx >> 6, n = idx & 63;
        s[k][n] = Wl[(size_t)(k0g * 64 + k) * N + n0 + n];
    }
    __syncthreads();
#pragma unroll
    for (int pass = 0; pass < 2; pass++) {
        int n = (tid >> 3) + pass * 32;
        int g = tid & 7;
        int gn = n0 + n;
        int tile = (gn >> tshift) * nkt + k0g;
        int nl = gn & (tileN - 1);
        uint32_t gp = (uint32_t)g ^ (uint32_t)(nl & 7);
        uint4 u;
        u.x = pkh2(s[g * 8 + 0][n], s[g * 8 + 1][n]);
        u.y = pkh2(s[g * 8 + 2][n], s[g * 8 + 3][n]);
        u.z = pkh2(s[g * 8 + 4][n], s[g * 8 + 5][n]);
        u.w = pkh2(s[g * 8 + 6][n], s[g * 8 + 7][n]);
        *(uint4*)&out[(size_t)tile * (tileN * 64) + nl * 64 + gp * 8] = u;
    }
}

__global__ void wtile_qkv_kernel(const float* __restrict__ Wq,
                                 const float* __restrict__ Wk,
                                 const float* __restrict__ Wv,
                                 __half* __restrict__ out)
{
    __shared__ float s[64][65];
    const size_t EE = (size_t)E_ * E_;
    int l = blockIdx.z;
    int gn0 = blockIdx.x * 64;
    int which = gn0 >> 10;
    const float* Wl = (which == 0 ? Wq : which == 1 ? Wk : Wv) + l * EE;
    int n0 = gn0 & 1023;
    int k0g = blockIdx.y;
    out += (size_t)l * 3 * EE;
    int tid = threadIdx.y * 32 + threadIdx.x;
#pragma unroll
    for (int i = 0; i < 16; i++) {
        int idx = tid + i * 256;
        int k = idx >> 6, n = idx & 63;
        s[k][n] = Wl[(size_t)(k0g * 64 + k) * E_ + n0 + n];
    }
    __syncthreads();
#pragma unroll
    for (int pass = 0; pass < 2; pass++) {
        int n = (tid >> 3) + pass * 32;
        int g = tid & 7;
        int gn = gn0 + n;
        int tile = (gn >> 8) * 16 + k0g;
        int nl = gn & 255;
        uint32_t gp = (uint32_t)g ^ (uint32_t)(nl & 7);
        uint4 u;
        u.x = pkh2(s[g * 8 + 0][n], s[g * 8 + 1][n]);
        u.y = pkh2(s[g * 8 + 2][n], s[g * 8 + 3][n]);
        u.z = pkh2(s[g * 8 + 4][n], s[g * 8 + 5][n]);
        u.w = pkh2(s[g * 8 + 6][n], s[g * 8 + 7][n]);
        *(uint4*)&out[(size_t)tile * (256 * 64) + nl * 64 + gp * 8] = u;
    }
}

__global__ void bpack_kernel(const float* __restrict__ bq, const float* __restrict__ bk,
                             const float* __restrict__ bv, float* __restrict__ out) {
    int i = blockIdx.x * 256 + threadIdx.x;
    int l = i / 3072, j = i % 3072;
    float v = (j < 1024) ? bq[l * 1024 + j]
            : (j < 2048) ? bk[l * 1024 + j - 1024]
                         : bv[l * 1024 + j - 2048];
    out[i] = v;
}

// ---------------------------------------------------------------------------
// Embedding / LayerNorm
// ---------------------------------------------------------------------------
__global__ void embed_kernel(const int* __restrict__ x, const float* __restrict__ tok,
                             const float* __restrict__ pos, float* __restrict__ h) {
    int i = blockIdx.x * 256 + threadIdx.x;
    int row = i >> 8, e4 = (i & 255) << 2;
    int tkn = x[row];
    int t = row & (T_ - 1);
    float4 a = *(const float4*)(tok + (size_t)tkn * E_ + e4);
    float4 p = *(const float4*)(pos + (size_t)t * E_ + e4);
    *(float4*)(h + (size_t)row * E_ + e4) =
        make_float4(a.x + p.x, a.y + p.y, a.z + p.z, a.w + p.w);
}

__global__ __launch_bounds__(256) void ln_kernel(const float* __restrict__ in,
                                                 const float* __restrict__ gam,
                                                 const float* __restrict__ bet,
                                                 __half* __restrict__ outh) {
    int row = blockIdx.x * 8 + (threadIdx.x >> 5);
    int lane = threadIdx.x & 31;
    const float4* rp = (const float4*)(in + (size_t)row * E_) + lane;
    float4 v[8];
    float s = 0.f, sq = 0.f;
#pragma unroll
    for (int i = 0; i < 8; i++) {
        v[i] = rp[i * 32];
        s  += v[i].x + v[i].y + v[i].z + v[i].w;
        sq += v[i].x * v[i].x + v[i].y * v[i].y + v[i].z * v[i].z + v[i].w * v[i].w;
    }
#pragma unroll
    for (int o = 16; o > 0; o >>= 1) {
        s  += __shfl_xor_sync(0xffffffffu, s,  o);
        sq += __shfl_xor_sync(0xffffffffu, sq, o);
    }
    float mean = s * (1.0f / E_);
    float var  = sq * (1.0f / E_) - mean * mean;
    float rstd = rsqrtf(var + 1e-5f);

#pragma unroll
    for (int i = 0; i < 8; i++) {
        int e = (lane + i * 32) * 4;
        float4 g = *(const float4*)(gam + e);
        float4 bb = *(const float4*)(bet + e);
        __half2 h0 = __floats2half2_rn((v[i].x - mean) * rstd * g.x + bb.x,
                                       (v[i].y - mean) * rstd * g.y + bb.y);
        __half2 h1 = __floats2half2_rn((v[i].z - mean) * rstd * g.z + bb.z,
                                       (v[i].w - mean) * rstd * g.w + bb.w);
        size_t a0 = atile_idx(row, e, 16);
        *(__half2*)&outh[a0]     = h0;
        *(__half2*)&outh[a0 + 2] = h1;
    }
}

// ---------------------------------------------------------------------------
// Host orchestration
// ---------------------------------------------------------------------------
extern "C" void kernel_launch(void* const* d_in, const int* in_sizes, int n_in,
                              void* d_out, int out_size) {
    const int*   x    = (const int*)  d_in[0];
    const float* tok  = (const float*)d_in[1];
    const float* pos  = (const float*)d_in[2];
    const float* Wq   = (const float*)d_in[3];
    const float* bq   = (const float*)d_in[4];
    const float* Wk   = (const float*)d_in[5];
    const float* bk   = (const float*)d_in[6];
    const float* Wv   = (const float*)d_in[7];
    const float* bv   = (const float*)d_in[8];
    const float* Wo   = (const float*)d_in[9];
    const float* bo   = (const float*)d_in[10];
    const float* ln1g = (const float*)d_in[11];
    const float* ln1b = (const float*)d_in[12];
    const float* W1   = (const float*)d_in[13];
    const float* b1   = (const float*)d_in[14];
    const float* W2   = (const float*)d_in[15];
    const float* b2   = (const float*)d_in[16];
    const float* ln2g = (const float*)d_in[17];
    const float* ln2b = (const float*)d_in[18];
    const float* lnfg = (const float*)d_in[19];
    const float* lnfb = (const float*)d_in[20];
    const float* Wout = (const float*)d_in[21];
    const float* bout = (const float*)d_in[22];
    float* out = (float*)d_out;

    float *h, *bqkv;
    __half *qh, *kt, *vt, *xn, *o, *mlp;
    __half *qkvT, *woT, *w1T, *w2T, *wouT;
    cudaGetSymbolAddress((void**)&h,    g_h);
    cudaGetSymbolAddress((void**)&qh,   g_q);
    cudaGetSymbolAddress((void**)&kt,   g_kt);
    cudaGetSymbolAddress((void**)&vt,   g_vt);
    cudaGetSymbolAddress((void**)&bqkv, g_bqkv);
    cudaGetSymbolAddress((void**)&xn,   g_xn);
    cudaGetSymbolAddress((void**)&o,    g_o);
    cudaGetSymbolAddress((void**)&mlp,  g_mlp);
    cudaGetSymbolAddress((void**)&qkvT, g_qkvT);
    cudaGetSymbolAddress((void**)&woT,  g_woT);
    cudaGetSymbolAddress((void**)&w1T,  g_w1T);
    cudaGetSymbolAddress((void**)&w2T,  g_w2T);
    cudaGetSymbolAddress((void**)&wouT, g_woutT);

    cudaFuncSetAttribute((const void*)btgemm_kernel<0>, cudaFuncAttributeMaxDynamicSharedMemorySize, BT_SMEM);
    cudaFuncSetAttribute((const void*)btgemm_kernel<1>, cudaFuncAttributeMaxDynamicSharedMemorySize, BT_SMEM);
    cudaFuncSetAttribute((const void*)btgemm_kernel<3>, cudaFuncAttributeMaxDynamicSharedMemorySize, BT_SMEM);
    cudaFuncSetAttribute((const void*)tgemm_res_kernel, cudaFuncAttributeMaxDynamicSharedMemorySize, ST_SMEM);

    const size_t EE = (size_t)E_ * E_, EF = (size_t)E_ * F_;
    dim3 tb(32, 8);

    embed_kernel<<<(M_ * E_) / (256 * 4), 256>>>(x, tok, pos, h);                    // 0
    wtile_qkv_kernel<<<dim3(48, 16, L_), tb>>>(Wq, Wk, Wv, qkvT);                    // 1
    bpack_kernel<<<(L_ * 3 * E_) / 256, 256>>>(bq, bk, bv, bqkv);                    // 2
    ln_kernel<<<M_ / 8, 256>>>(h, ln1g, ln1b, xn);                                   // 3
    btgemm_kernel<3><<<dim3(M_ / 128, 12), 256, BT_SMEM>>>(                          // 4
        xn, qkvT, bqkv, nullptr, qh, kt, vt, 3 * E_, E_);
    wtile_kernel<<<dim3(16, 16, L_), tb>>>(Wo, woT, E_, E_, 7, EE, EE);              // 5
    wtile_kernel<<<dim3(64, 16, L_), tb>>>(W1, w1T, E_, F_, 8, EF, EF);              // 6
    wtile_kernel<<<dim3(16, 64, L_), tb>>>(W2, w2T, F_, E_, 7, EF, EF);              // 7
    wtile_kernel<<<dim3(500, 16, 1), tb>>>(Wout, wouT, E_, V_, 8, 0, 0);             // 8

    for (int l = 0; l < L_; l++) {
        if (l > 0) {
            ln_kernel<<<M_ / 8, 256>>>(h, ln1g + l * E_, ln1b + l * E_, xn);
            btgemm_kernel<3><<<dim3(M_ / 128, 12), 256, BT_SMEM>>>(
                xn, qkvT + l * 3 * EE, bqkv + l * 3 * E_, nullptr, qh, kt, vt, 3 * E_, E_);
        }
        fattn_kernel<<<B_ * H_ * (T_ / 64), 128>>>(qh, kt, vt, o);
        tgemm_res_kernel<<<dim3(M_ / 128, 8), 256, ST_SMEM>>>(
            o, woT + l * EE, bo + l * E_, h, h, E_, E_);
        ln_kernel<<<M_ / 8, 256>>>(h, ln2g + l * E_, ln2b + l * E_, xn);
        btgemm_kernel<1><<<dim3(M_ / 128, F_ / 256), 256, BT_SMEM>>>(
            xn, w1T + l * EF, b1 + l * F_, nullptr, mlp, nullptr, nullptr, F_, E_);
        tgemm_res_kernel<<<dim3(M_ / 128, 8), 256, ST_SMEM>>>(
            mlp, w2T + l * EF, b2 + l * E_, h, h, E_, F_);
    }

    ln_kernel<<<M_ / 8, 256>>>(h, lnfg, lnfb, xn);
    btgemm_kernel<0><<<dim3(M_ / 128, V_ / 256), 256, BT_SMEM>>>(
        xn, wouT, bout, out, nullptr, nullptr, nullptr, V_, E_);
}